// round 1
// baseline (speedup 1.0000x reference)
#include <cuda_runtime.h>
#include <math.h>

#define T_  128
#define B_  64
#define F_  75
#define H_  512
#define G4  2048   // 4*H
#define H2  1024   // 2*H

// ---------------- static scratch (no runtime allocation allowed) ----------------
__device__ float g_xw  [2ll * T_ * B_ * G4];    // gate preactivations (input part), both dirs
__device__ float g_y   [(long long)T_ * B_ * H2]; // layer output (concat fwd|bwd)
__device__ float g_hbuf[2 * 2 * B_ * H_];       // ping-pong h state [buf][dir][B][H]
__device__ float g_cbuf[2 * B_ * H_];           // c state [dir][B][H]
__device__ float g_t1  [2 * B_ * H_];
__device__ float g_e   [2 * B_ * F_];
__device__ float g_ab  [B_ * F_];
__device__ float g_xwx [T_ * B_ * F_];

// ---------------- generic tiled GEMM: C = A(MxK) * W(NxK)^T + b1 + b2 ----------------
// ACT: 0 none, 1 tanh, 2 exp. Batched over grid.z with strides.
template<int ACT>
__global__ void gemm_bias(const float* __restrict__ A, int lda, long long sA,
                          const float* __restrict__ W, int ldw, long long sW,
                          const float* __restrict__ b1, long long sB1,
                          const float* __restrict__ b2, long long sB2,
                          float* __restrict__ C, int ldc, long long sC,
                          int M, int N, int K)
{
    const int BM = 128, BN = 128, BK = 16;
    int bz = blockIdx.z;
    A += (long long)bz * sA;
    W += (long long)bz * sW;
    C += (long long)bz * sC;
    if (b1) b1 += (long long)bz * sB1;
    if (b2) b2 += (long long)bz * sB2;

    __shared__ float As[BK][BM + 4];
    __shared__ float Ws[BK][BN + 4];

    int m0 = blockIdx.y * BM;
    int n0 = blockIdx.x * BN;
    int tid = threadIdx.x;            // 256 threads
    int trow = tid >> 4, tcol = tid & 15;
    int tm = trow * 8, tn = tcol * 8;

    float acc[8][8];
    #pragma unroll
    for (int i = 0; i < 8; i++)
        #pragma unroll
        for (int j = 0; j < 8; j++) acc[i][j] = 0.f;

    for (int kk = 0; kk < K; kk += BK) {
        #pragma unroll
        for (int i = 0; i < 8; i++) {
            int idx = i * 256 + tid;
            int m = idx / BK, k = idx % BK;
            int gm = m0 + m, gk = kk + k;
            As[k][m] = (gm < M && gk < K) ? A[(long long)gm * lda + gk] : 0.f;
        }
        #pragma unroll
        for (int i = 0; i < 8; i++) {
            int idx = i * 256 + tid;
            int n = idx / BK, k = idx % BK;
            int gn = n0 + n, gk = kk + k;
            Ws[k][n] = (gn < N && gk < K) ? W[(long long)gn * ldw + gk] : 0.f;
        }
        __syncthreads();
        #pragma unroll
        for (int k = 0; k < BK; k++) {
            float a[8], w[8];
            #pragma unroll
            for (int i = 0; i < 8; i++) a[i] = As[k][tm + i];
            #pragma unroll
            for (int j = 0; j < 8; j++) w[j] = Ws[k][tn + j];
            #pragma unroll
            for (int i = 0; i < 8; i++)
                #pragma unroll
                for (int j = 0; j < 8; j++)
                    acc[i][j] += a[i] * w[j];
        }
        __syncthreads();
    }

    #pragma unroll
    for (int i = 0; i < 8; i++) {
        int gm = m0 + tm + i;
        if (gm >= M) continue;
        #pragma unroll
        for (int j = 0; j < 8; j++) {
            int gn = n0 + tn + j;
            if (gn >= N) continue;
            float v = acc[i][j];
            if (b1) v += b1[gn];
            if (b2) v += b2[gn];
            if (ACT == 1) v = tanhf(v);
            else if (ACT == 2) v = expf(v);
            C[(long long)gm * ldc + gn] = v;
        }
    }
}

// ---------------- fused bidirectional LSTM step ----------------
// grid: 128 blocks = 2 dirs * 64 h-slices (HS=8). Block computes all 4 gates
// for its slice (64 batch x 32 gate-cols), then the pointwise c/h update.
// h is double-buffered (hsrc -> hdst); c is block-private in-place.
__global__ void lstm_step(const float* __restrict__ xw,   // [2][T][B][G4]
                          const float* __restrict__ Whh,  // [2][G4][H]
                          const float* __restrict__ hsrc, // [2][B][H]
                          float* __restrict__ hdst,       // [2][B][H]
                          float* __restrict__ c,          // [2][B][H]
                          float* __restrict__ y,          // [T][B][2H] or null
                          int t)
{
    const int HS = 8;
    int d  = blockIdx.x >> 6;
    int j0 = (blockIdx.x & 63) * HS;
    int td = d ? (T_ - 1 - t) : t;

    __shared__ float hs[32][66];
    __shared__ float ws[32][36];
    __shared__ float gs[64][33];

    int tid = threadIdx.x;            // 256
    int b0 = (tid >> 3) * 2;          // 2 batch rows per thread
    int c0 = (tid & 7) * 4;           // 4 gate-cols per thread (within one gate)

    const float* hp = hsrc + d * B_ * H_;
    const float* wp = Whh + (long long)d * G4 * H_;
    const float* xp = xw + ((long long)(d * T_ + td) * B_) * G4;

    float acc[2][4];
    #pragma unroll
    for (int i = 0; i < 2; i++)
        #pragma unroll
        for (int j = 0; j < 4; j++) {
            int col = c0 + j;
            int gate = col >> 3, jj = col & 7;
            acc[i][j] = xp[(b0 + i) * G4 + gate * H_ + j0 + jj];
        }

    for (int kk = 0; kk < H_; kk += 32) {
        #pragma unroll
        for (int i = 0; i < 8; i++) {
            int idx = i * 256 + tid;
            int b = idx >> 5, k = idx & 31;
            hs[k][b] = hp[b * H_ + kk + k];
        }
        #pragma unroll
        for (int i = 0; i < 4; i++) {
            int idx = i * 256 + tid;
            int r = idx >> 5, k = idx & 31;
            int gate = r >> 3, jj = r & 7;
            ws[k][r] = wp[(gate * H_ + j0 + jj) * H_ + kk + k];
        }
        __syncthreads();
        #pragma unroll
        for (int k = 0; k < 32; k++) {
            float h0v = hs[k][b0];
            float h1v = hs[k][b0 + 1];
            float w0 = ws[k][c0], w1 = ws[k][c0 + 1], w2 = ws[k][c0 + 2], w3 = ws[k][c0 + 3];
            acc[0][0] += h0v * w0; acc[0][1] += h0v * w1; acc[0][2] += h0v * w2; acc[0][3] += h0v * w3;
            acc[1][0] += h1v * w0; acc[1][1] += h1v * w1; acc[1][2] += h1v * w2; acc[1][3] += h1v * w3;
        }
        __syncthreads();
    }

    #pragma unroll
    for (int i = 0; i < 2; i++)
        #pragma unroll
        for (int j = 0; j < 4; j++)
            gs[b0 + i][c0 + j] = acc[i][j];
    __syncthreads();

    // pointwise: 64 b x 8 jj = 512 outputs, 2 per thread
    #pragma unroll
    for (int it = 0; it < 2; it++) {
        int idx = it * 256 + tid;
        int b = idx >> 3, jj = idx & 7;
        float gi = gs[b][jj];
        float gf = gs[b][8 + jj];
        float gg = gs[b][16 + jj];
        float go = gs[b][24 + jj];
        int hidx = d * B_ * H_ + b * H_ + j0 + jj;
        float cv = c[hidx];
        float si = 1.f / (1.f + expf(-gi));
        float sf = 1.f / (1.f + expf(-gf));
        float so = 1.f / (1.f + expf(-go));
        float cn = sf * cv + si * tanhf(gg);
        float hn = so * tanhf(cn);
        c[hidx] = cn;
        hdst[hidx] = hn;
        if (y) y[((long long)td * B_ + b) * H2 + d * H_ + j0 + jj] = hn;
    }
}

// ---------------- small kernels ----------------
__global__ void copy2(float* __restrict__ dh, float* __restrict__ dc,
                      const float* __restrict__ h0, const float* __restrict__ c0, int n)
{
    int i = blockIdx.x * blockDim.x + threadIdx.x;
    if (i < n) { dh[i] = h0[i]; dc[i] = c0[i]; }
}

__global__ void attn_alpha(const float* __restrict__ e, float* __restrict__ alphab)
{
    int b = blockIdx.x;               // 64 blocks
    __shared__ float a[2 * F_];
    __shared__ float red[128];
    __shared__ float redc[128];
    int tid = threadIdx.x;            // 128

    for (int i = tid; i < 2 * F_; i += 128) {
        int d = i / F_, j = i % F_;
        a[i] = e[(d * B_ + b) * F_ + j];
    }
    __syncthreads();

    float s = 0.f;
    for (int i = tid; i < 2 * F_; i += 128) s += a[i];
    red[tid] = s; __syncthreads();
    for (int off = 64; off; off >>= 1) { if (tid < off) red[tid] += red[tid + off]; __syncthreads(); }
    float denom = red[0];
    __syncthreads();

    for (int i = tid; i < 2 * F_; i += 128) a[i] /= denom;
    __syncthreads();

    float cnt = 0.f, sel = 0.f;
    for (int i = tid; i < 2 * F_; i += 128) {
        float v = a[i];
        if (v >= 0.1f) { cnt += 1.f; sel += v; }
    }
    red[tid] = sel; redc[tid] = cnt; __syncthreads();
    for (int off = 64; off; off >>= 1) {
        if (tid < off) { red[tid] += red[tid + off]; redc[tid] += redc[tid + off]; }
        __syncthreads();
    }
    float selmean = red[0] / fmaxf(redc[0], 1.f);
    __syncthreads();

    for (int i = tid; i < 2 * F_; i += 128)
        if (a[i] >= 0.1f) a[i] = selmean;
    __syncthreads();

    for (int j = tid; j < F_; j += 128)
        alphab[b * F_ + j] = 0.5f * (a[j] + a[F_ + j]);
}

__global__ void scale_x(const float* __restrict__ x, const float* __restrict__ ab,
                        float* __restrict__ xo, int n)
{
    int i = blockIdx.x * blockDim.x + threadIdx.x;
    if (i < n) {
        int f = i % F_;
        int b = (i / F_) % B_;
        xo[i] = x[i] * ab[b * F_ + f];
    }
}

// ---------------- host driver ----------------
extern "C" void kernel_launch(void* const* d_in, const int* in_sizes, int n_in,
                              void* d_out, int out_size)
{
    const float* x     = (const float*)d_in[0];
    const float* h0    = (const float*)d_in[1];
    const float* c0    = (const float*)d_in[2];
    const float* saWih = (const float*)d_in[3];
    const float* saWhh = (const float*)d_in[4];
    const float* sabih = (const float*)d_in[5];
    const float* sabhh = (const float*)d_in[6];
    const float* m0Wih = (const float*)d_in[7];
    const float* m0Whh = (const float*)d_in[8];
    const float* m0bih = (const float*)d_in[9];
    const float* m0bhh = (const float*)d_in[10];
    const float* mLWih = (const float*)d_in[11];
    const float* mLWhh = (const float*)d_in[12];
    const float* mLbih = (const float*)d_in[13];
    const float* mLbhh = (const float*)d_in[14];
    const float* sf1W  = (const float*)d_in[15];
    const float* sf1b  = (const float*)d_in[16];
    const float* sf2W  = (const float*)d_in[17];
    const float* sf2b  = (const float*)d_in[18];
    const float* fc1W  = (const float*)d_in[19];
    const float* fc1b  = (const float*)d_in[20];
    float* out = (float*)d_out;

    float *xw, *y, *hbuf, *cbuf, *t1, *e, *ab, *xwx;
    cudaGetSymbolAddress((void**)&xw,   g_xw);
    cudaGetSymbolAddress((void**)&y,    g_y);
    cudaGetSymbolAddress((void**)&hbuf, g_hbuf);
    cudaGetSymbolAddress((void**)&cbuf, g_cbuf);
    cudaGetSymbolAddress((void**)&t1,   g_t1);
    cudaGetSymbolAddress((void**)&e,    g_e);
    cudaGetSymbolAddress((void**)&ab,   g_ab);
    cudaGetSymbolAddress((void**)&xwx,  g_xwx);

    auto run_stage = [&](const float* Ain, int K,
                         const float* Wih, const float* Whh,
                         const float* bih, const float* bhh,
                         const float* h0s, const float* c0s,
                         float* yout)
    {
        dim3 gp(G4 / 128, (T_ * B_) / 128, 2);
        gemm_bias<0><<<gp, 256>>>(Ain, K, 0ll,
                                  Wih, K, (long long)G4 * K,
                                  bih, G4, bhh, G4,
                                  xw, G4, (long long)T_ * B_ * G4,
                                  T_ * B_, G4, K);
        copy2<<<(2 * B_ * H_ + 255) / 256, 256>>>(hbuf, cbuf, h0s, c0s, 2 * B_ * H_);
        for (int t = 0; t < T_; t++) {
            float* hs = hbuf + (t & 1) * 2 * B_ * H_;
            float* hd = hbuf + ((t + 1) & 1) * 2 * B_ * H_;
            lstm_step<<<128, 256>>>(xw, Whh, hs, hd, cbuf, yout, t);
        }
    };

    // 1) spatial-attention biLSTM (only final hidden states needed)
    run_stage(x, F_, saWih, saWhh, sabih, sabhh, h0, c0, nullptr);

    // 2) attention weights (final h lands in hbuf buffer 0 since T is even)
    gemm_bias<1><<<dim3(H_ / 128, 1, 1), 256>>>(hbuf, H_, 0ll, sf1W, H_, 0ll,
                                                sf1b, 0ll, nullptr, 0ll,
                                                t1, H_, 0ll, 2 * B_, H_, H_);
    gemm_bias<2><<<dim3(1, 1, 1), 256>>>(t1, H_, 0ll, sf2W, H_, 0ll,
                                         sf2b, 0ll, nullptr, 0ll,
                                         e, F_, 0ll, 2 * B_, F_, H_);
    attn_alpha<<<B_, 128>>>(e, ab);
    scale_x<<<(T_ * B_ * F_ + 255) / 256, 256>>>(x, ab, xwx, T_ * B_ * F_);

    // 3) main biLSTM layer 0 (input F)
    run_stage(xwx, F_, m0Wih, m0Whh, m0bih, m0bhh, h0, c0, y);

    // 4) main biLSTM layers 1,2 (input 2H)
    run_stage(y, H2, mLWih, mLWhh, mLbih, mLbhh,
              h0 + 2 * B_ * H_, c0 + 2 * B_ * H_, y);
    run_stage(y, H2, mLWih + 2ll * G4 * H2, mLWhh + 2ll * G4 * H_,
              mLbih + 2 * G4, mLbhh + 2 * G4,
              h0 + 4 * B_ * H_, c0 + 4 * B_ * H_, y);

    // 5) final FC: out = y @ fc1_W^T + fc1_b
    gemm_bias<0><<<dim3(H_ / 128, (T_ * B_) / 128, 1), 256>>>(
        y, H2, 0ll, fc1W, H2, 0ll, fc1b, 0ll, nullptr, 0ll,
        out, H_, 0ll, T_ * B_, H_, H2);
}

// round 2
// speedup vs baseline: 1.4084x; 1.4084x over previous
#include <cuda_runtime.h>
#include <math.h>
#include <stdint.h>

#define T_  128
#define B_  64
#define F_  75
#define H_  512
#define G4  2048   // 4*H
#define H2  1024   // 2*H

// ---------------- static scratch ----------------
__device__ float g_xw   [2ll * T_ * B_ * G4];     // gate preactivations, both dirs
__device__ float g_y    [(long long)T_ * B_ * H2];
__device__ float g_h    [2 * 2 * H_ * B_];        // ping-pong h: [buf][d][k][b]
__device__ float g_hlast[2 * B_ * H_];            // final h, [d][b][k]
__device__ float g_t1   [2 * B_ * H_];
__device__ float g_e    [2 * B_ * F_];
__device__ float g_ab   [B_ * F_];
__device__ float g_xwx  [T_ * B_ * F_];
__device__ unsigned g_bar[2];

// ---------------- f32x2 helpers ----------------
__device__ __forceinline__ unsigned long long pack2(float lo, float hi) {
    unsigned long long r;
    asm("mov.b64 %0, {%1, %2};" : "=l"(r) : "f"(lo), "f"(hi));
    return r;
}
__device__ __forceinline__ void unpack2(unsigned long long v, float& lo, float& hi) {
    asm("mov.b64 {%0, %1}, %2;" : "=f"(lo), "=f"(hi) : "l"(v));
}
__device__ __forceinline__ void ffma2(unsigned long long& d,
                                      unsigned long long a, unsigned long long b) {
    asm("fma.rn.f32x2 %0, %1, %2, %3;" : "=l"(d) : "l"(a), "l"(b), "l"(d));
}
__device__ __forceinline__ void cp16(uint32_t dst, const float* src) {
    asm volatile("cp.async.cg.shared.global [%0], [%1], 16;" :: "r"(dst), "l"(src));
}

// ---------------- generic tiled GEMM: C = A(MxK) * W(NxK)^T + b1 + b2 ----------------
template<int ACT>
__global__ void gemm_bias(const float* __restrict__ A, int lda, long long sA,
                          const float* __restrict__ W, int ldw, long long sW,
                          const float* __restrict__ b1, long long sB1,
                          const float* __restrict__ b2, long long sB2,
                          float* __restrict__ C, int ldc, long long sC,
                          int M, int N, int K)
{
    const int BM = 128, BN = 128, BK = 16;
    int bz = blockIdx.z;
    A += (long long)bz * sA;
    W += (long long)bz * sW;
    C += (long long)bz * sC;
    if (b1) b1 += (long long)bz * sB1;
    if (b2) b2 += (long long)bz * sB2;

    __shared__ float As[BK][BM + 4];
    __shared__ float Ws[BK][BN + 4];

    int m0 = blockIdx.y * BM;
    int n0 = blockIdx.x * BN;
    int tid = threadIdx.x;
    int trow = tid >> 4, tcol = tid & 15;
    int tm = trow * 8, tn = tcol * 8;

    float acc[8][8];
    #pragma unroll
    for (int i = 0; i < 8; i++)
        #pragma unroll
        for (int j = 0; j < 8; j++) acc[i][j] = 0.f;

    for (int kk = 0; kk < K; kk += BK) {
        #pragma unroll
        for (int i = 0; i < 8; i++) {
            int idx = i * 256 + tid;
            int m = idx / BK, k = idx % BK;
            int gm = m0 + m, gk = kk + k;
            As[k][m] = (gm < M && gk < K) ? A[(long long)gm * lda + gk] : 0.f;
        }
        #pragma unroll
        for (int i = 0; i < 8; i++) {
            int idx = i * 256 + tid;
            int n = idx / BK, k = idx % BK;
            int gn = n0 + n, gk = kk + k;
            Ws[k][n] = (gn < N && gk < K) ? W[(long long)gn * ldw + gk] : 0.f;
        }
        __syncthreads();
        #pragma unroll
        for (int k = 0; k < BK; k++) {
            float a[8], w[8];
            #pragma unroll
            for (int i = 0; i < 8; i++) a[i] = As[k][tm + i];
            #pragma unroll
            for (int j = 0; j < 8; j++) w[j] = Ws[k][tn + j];
            #pragma unroll
            for (int i = 0; i < 8; i++)
                #pragma unroll
                for (int j = 0; j < 8; j++)
                    acc[i][j] += a[i] * w[j];
        }
        __syncthreads();
    }

    #pragma unroll
    for (int i = 0; i < 8; i++) {
        int gm = m0 + tm + i;
        if (gm >= M) continue;
        #pragma unroll
        for (int j = 0; j < 8; j++) {
            int gn = n0 + tn + j;
            if (gn >= N) continue;
            float v = acc[i][j];
            if (b1) v += b1[gn];
            if (b2) v += b2[gn];
            if (ACT == 1) v = tanhf(v);
            else if (ACT == 2) v = expf(v);
            C[(long long)gm * ldc + gn] = v;
        }
    }
}

// ---------------- persistent bidirectional LSTM recurrence ----------------
// 128 blocks = 2 dirs * 64 h-slices of 8. Each block caches its Whh slice
// (512 x 32 gate cols) in SMEM once, loops over all T steps internally with a
// per-direction release/acquire barrier. h in global, k-major [d][k][b],
// double-buffered; staged into SMEM via cp.async double buffering. c in SMEM.
// Inner product uses fma.rn.f32x2 (2 MACs per issue).
__global__ void __launch_bounds__(256, 1)
lstm_persist(const float* __restrict__ xw,   // [2][T][B][G4]
             const float* __restrict__ Whh,  // [2][G4][H]
             const float* __restrict__ c0s,  // [2][B][H]
             float* __restrict__ hbuf,       // [2][2][H][B]
             float* __restrict__ hlast,      // [2][B][H]
             float* __restrict__ y,          // [T][B][2H] or null
             unsigned* __restrict__ bar)
{
    extern __shared__ float sm[];
    float* ws  = sm;                 // [512][33]  padded weights (67.6KB)
    float* hsA = ws + 512 * 33;      // [128][64]  h chunk buf A (32KB)
    float* hsB = hsA + 128 * 64;     // buf B (32KB)
    float* cs  = hsB + 128 * 64;     // [512] cell state (2KB)
    float* gs  = hsA;                // alias: gate exchange [2][64][33] (fits in hsA)

    const int tid = threadIdx.x;
    const int d   = blockIdx.x >> 6;
    const int j0  = (blockIdx.x & 63) * 8;

    const int kh  = tid >> 7;        // k-half: 0 or 1
    const int lx  = tid & 127;
    const int b0  = (lx >> 4) * 8;   // 8 batch rows
    const int c0  = (lx & 15) * 2;   // 2 gate cols (never cross a gate boundary)
    const int g0  = c0 >> 3;
    const int jj0 = c0 & 7;

    const float* wp = Whh + (size_t)d * G4 * H_;

    // load Whh slice: ws[k][cl] = Whh[d][gate*H + j0 + jj][k]
    for (int i = tid; i < 512 * 32; i += 256) {
        int cl = i >> 9;
        int k  = i & 511;
        int gate = cl >> 3, jj = cl & 7;
        ws[k * 33 + cl] = wp[(size_t)(gate * H_ + j0 + jj) * H_ + k];
    }
    // load cell state slice
    for (int i = tid; i < 512; i += 256) {
        int b = i >> 3, jj = i & 7;
        cs[i] = c0s[(size_t)d * B_ * H_ + b * H_ + j0 + jj];
    }
    __syncthreads();

    const uint32_t hsAaddr = (uint32_t)__cvta_generic_to_shared(hsA);
    const uint32_t hsBaddr = (uint32_t)__cvta_generic_to_shared(hsB);

    for (int t = 0; t < T_; t++) {
        const int td = d ? (T_ - 1 - t) : t;
        const float* hsrc = hbuf + ((t & 1) ? 2 * H_ * B_ : 0) + d * H_ * B_;
        float*       hdst = hbuf + ((t & 1) ? 0 : 2 * H_ * B_) + d * H_ * B_;
        const float* xp   = xw + ((size_t)(d * T_ + td) * B_) * G4;

        // preload input-projection gate values (consumed at the end)
        float xv[4][2][2];
        if (kh == 0) {
            #pragma unroll
            for (int p = 0; p < 4; p++)
                #pragma unroll
                for (int dd = 0; dd < 2; dd++)
                    #pragma unroll
                    for (int c = 0; c < 2; c++)
                        xv[p][dd][c] =
                            xp[(size_t)(b0 + 2 * p + dd) * G4 + g0 * H_ + j0 + jj0 + c];
        }

        unsigned long long acc[4][2];
        #pragma unroll
        for (int p = 0; p < 4; p++)
            #pragma unroll
            for (int c = 0; c < 2; c++) acc[p][c] = 0ull;

        // stage chunk 0
        {
            const float* src = hsrc;
            #pragma unroll
            for (int i = 0; i < 8; i++) {
                int idx = i * 256 + tid;
                cp16(hsAaddr + idx * 16, src + idx * 4);
            }
            asm volatile("cp.async.commit_group;");
        }

        #pragma unroll
        for (int ch = 0; ch < 4; ch++) {
            const float* cur = (ch & 1) ? hsB : hsA;
            if (ch < 3) {
                const float* src = hsrc + (ch + 1) * 128 * 64;
                uint32_t dsta = (ch & 1) ? hsAaddr : hsBaddr;
                #pragma unroll
                for (int i = 0; i < 8; i++) {
                    int idx = i * 256 + tid;
                    cp16(dsta + idx * 16, src + idx * 4);
                }
                asm volatile("cp.async.commit_group;");
                asm volatile("cp.async.wait_group 1;");
            } else {
                asm volatile("cp.async.wait_group 0;");
            }
            __syncthreads();

            const float* hrow = cur + kh * 64 * 64 + b0;
            const float* wrow = ws + (size_t)(ch * 128 + kh * 64) * 33;
            #pragma unroll 4
            for (int k = 0; k < 64; k++) {
                unsigned long long h0v = *(const unsigned long long*)(hrow + k * 64 + 0);
                unsigned long long h1v = *(const unsigned long long*)(hrow + k * 64 + 2);
                unsigned long long h2v = *(const unsigned long long*)(hrow + k * 64 + 4);
                unsigned long long h3v = *(const unsigned long long*)(hrow + k * 64 + 6);
                float w0 = wrow[k * 33 + c0];
                float w1 = wrow[k * 33 + c0 + 1];
                unsigned long long wd0 = pack2(w0, w0);
                unsigned long long wd1 = pack2(w1, w1);
                ffma2(acc[0][0], h0v, wd0); ffma2(acc[0][1], h0v, wd1);
                ffma2(acc[1][0], h1v, wd0); ffma2(acc[1][1], h1v, wd1);
                ffma2(acc[2][0], h2v, wd0); ffma2(acc[2][1], h2v, wd1);
                ffma2(acc[3][0], h3v, wd0); ffma2(acc[3][1], h3v, wd1);
            }
            __syncthreads();
        }

        // gate exchange (kh=0 folds in the xw contribution)
        #pragma unroll
        for (int p = 0; p < 4; p++)
            #pragma unroll
            for (int c = 0; c < 2; c++) {
                float lo, hi;
                unpack2(acc[p][c], lo, hi);
                if (kh == 0) { lo += xv[p][0][c]; hi += xv[p][1][c]; }
                gs[kh * 2112 + (b0 + 2 * p) * 33 + c0 + c]     = lo;
                gs[kh * 2112 + (b0 + 2 * p + 1) * 33 + c0 + c] = hi;
            }
        __syncthreads();

        // pointwise c/h update (512 outputs, 2 per thread)
        #pragma unroll
        for (int it = 0; it < 2; it++) {
            int o = it * 256 + tid;
            int b = o >> 3, jj = o & 7;
            float gi = gs[b * 33 + jj]      + gs[2112 + b * 33 + jj];
            float gf = gs[b * 33 + 8 + jj]  + gs[2112 + b * 33 + 8 + jj];
            float gg = gs[b * 33 + 16 + jj] + gs[2112 + b * 33 + 16 + jj];
            float go = gs[b * 33 + 24 + jj] + gs[2112 + b * 33 + 24 + jj];
            float cv = cs[o];
            float si = 1.f / (1.f + expf(-gi));
            float sf = 1.f / (1.f + expf(-gf));
            float so = 1.f / (1.f + expf(-go));
            float cn = sf * cv + si * tanhf(gg);
            float hn = so * tanhf(cn);
            cs[o] = cn;
            hdst[(j0 + jj) * B_ + b] = hn;
            if (y) y[(size_t)(td * B_ + b) * H2 + d * H_ + j0 + jj] = hn;
            if (t == T_ - 1) hlast[(size_t)d * B_ * H_ + b * H_ + j0 + jj] = hn;
        }

        // per-direction inter-block barrier (release/acquire)
        __threadfence();
        __syncthreads();
        if (t < T_ - 1) {
            if (tid == 0) {
                atomicAdd(&bar[d], 1u);
                unsigned tgt = 64u * (unsigned)(t + 1);
                unsigned v;
                do {
                    asm volatile("ld.acquire.gpu.u32 %0, [%1];" : "=r"(v) : "l"(bar + d));
                } while (v < tgt);
            }
            __syncthreads();
        }
    }
}

// ---------------- small kernels ----------------
__global__ void init_state(const float* __restrict__ h0s, float* __restrict__ hbuf,
                           unsigned* __restrict__ bar)
{
    int i = blockIdx.x * blockDim.x + threadIdx.x;
    if (i < 2) bar[i] = 0;
    if (i < 2 * H_ * B_) {
        int b = i & (B_ - 1);
        int k = (i >> 6) & (H_ - 1);
        int d = i >> 15;
        hbuf[i] = h0s[((size_t)d * B_ + b) * H_ + k];   // transpose to [d][k][b]
    }
}

__global__ void attn_alpha(const float* __restrict__ e, float* __restrict__ alphab)
{
    int b = blockIdx.x;
    __shared__ float a[2 * F_];
    __shared__ float red[128];
    __shared__ float redc[128];
    int tid = threadIdx.x;

    for (int i = tid; i < 2 * F_; i += 128) {
        int d = i / F_, j = i % F_;
        a[i] = e[(d * B_ + b) * F_ + j];
    }
    __syncthreads();

    float s = 0.f;
    for (int i = tid; i < 2 * F_; i += 128) s += a[i];
    red[tid] = s; __syncthreads();
    for (int off = 64; off; off >>= 1) { if (tid < off) red[tid] += red[tid + off]; __syncthreads(); }
    float denom = red[0];
    __syncthreads();

    for (int i = tid; i < 2 * F_; i += 128) a[i] /= denom;
    __syncthreads();

    float cnt = 0.f, sel = 0.f;
    for (int i = tid; i < 2 * F_; i += 128) {
        float v = a[i];
        if (v >= 0.1f) { cnt += 1.f; sel += v; }
    }
    red[tid] = sel; redc[tid] = cnt; __syncthreads();
    for (int off = 64; off; off >>= 1) {
        if (tid < off) { red[tid] += red[tid + off]; redc[tid] += redc[tid + off]; }
        __syncthreads();
    }
    float selmean = red[0] / fmaxf(redc[0], 1.f);
    __syncthreads();

    for (int i = tid; i < 2 * F_; i += 128)
        if (a[i] >= 0.1f) a[i] = selmean;
    __syncthreads();

    for (int j = tid; j < F_; j += 128)
        alphab[b * F_ + j] = 0.5f * (a[j] + a[F_ + j]);
}

__global__ void scale_x(const float* __restrict__ x, const float* __restrict__ ab,
                        float* __restrict__ xo, int n)
{
    int i = blockIdx.x * blockDim.x + threadIdx.x;
    if (i < n) {
        int f = i % F_;
        int b = (i / F_) % B_;
        xo[i] = x[i] * ab[b * F_ + f];
    }
}

// ---------------- host driver ----------------
extern "C" void kernel_launch(void* const* d_in, const int* in_sizes, int n_in,
                              void* d_out, int out_size)
{
    const float* x     = (const float*)d_in[0];
    const float* h0    = (const float*)d_in[1];
    const float* c0    = (const float*)d_in[2];
    const float* saWih = (const float*)d_in[3];
    const float* saWhh = (const float*)d_in[4];
    const float* sabih = (const float*)d_in[5];
    const float* sabhh = (const float*)d_in[6];
    const float* m0Wih = (const float*)d_in[7];
    const float* m0Whh = (const float*)d_in[8];
    const float* m0bih = (const float*)d_in[9];
    const float* m0bhh = (const float*)d_in[10];
    const float* mLWih = (const float*)d_in[11];
    const float* mLWhh = (const float*)d_in[12];
    const float* mLbih = (const float*)d_in[13];
    const float* mLbhh = (const float*)d_in[14];
    const float* sf1W  = (const float*)d_in[15];
    const float* sf1b  = (const float*)d_in[16];
    const float* sf2W  = (const float*)d_in[17];
    const float* sf2b  = (const float*)d_in[18];
    const float* fc1W  = (const float*)d_in[19];
    const float* fc1b  = (const float*)d_in[20];
    float* out = (float*)d_out;

    float *xw, *y, *hbuf, *hlast, *t1, *e, *ab, *xwx;
    unsigned* bar;
    cudaGetSymbolAddress((void**)&xw,    g_xw);
    cudaGetSymbolAddress((void**)&y,     g_y);
    cudaGetSymbolAddress((void**)&hbuf,  g_h);
    cudaGetSymbolAddress((void**)&hlast, g_hlast);
    cudaGetSymbolAddress((void**)&t1,    g_t1);
    cudaGetSymbolAddress((void**)&e,     g_e);
    cudaGetSymbolAddress((void**)&ab,    g_ab);
    cudaGetSymbolAddress((void**)&xwx,   g_xwx);
    cudaGetSymbolAddress((void**)&bar,   g_bar);

    const int SMEMSZ = (512 * 33 + 2 * 128 * 64 + 512) * 4;   // 135168 B
    cudaFuncSetAttribute(lstm_persist, cudaFuncAttributeMaxDynamicSharedMemorySize, SMEMSZ);

    auto run_stage = [&](const float* Ain, int K,
                         const float* Wih, const float* Whh,
                         const float* bih, const float* bhh,
                         const float* h0s, const float* c0s,
                         float* yout)
    {
        dim3 gp(G4 / 128, (T_ * B_) / 128, 2);
        gemm_bias<0><<<gp, 256>>>(Ain, K, 0ll,
                                  Wih, K, (long long)G4 * K,
                                  bih, G4, bhh, G4,
                                  xw, G4, (long long)T_ * B_ * G4,
                                  T_ * B_, G4, K);
        init_state<<<(2 * H_ * B_ + 255) / 256, 256>>>(h0s, hbuf, bar);
        lstm_persist<<<128, 256, SMEMSZ>>>(xw, Whh, c0s, hbuf, hlast, yout, bar);
    };

    // 1) spatial-attention biLSTM (only final hidden states needed)
    run_stage(x, F_, saWih, saWhh, sabih, sabhh, h0, c0, nullptr);

    // 2) attention weights from final hidden states
    gemm_bias<1><<<dim3(H_ / 128, 1, 1), 256>>>(hlast, H_, 0ll, sf1W, H_, 0ll,
                                                sf1b, 0ll, nullptr, 0ll,
                                                t1, H_, 0ll, 2 * B_, H_, H_);
    gemm_bias<2><<<dim3(1, 1, 1), 256>>>(t1, H_, 0ll, sf2W, H_, 0ll,
                                         sf2b, 0ll, nullptr, 0ll,
                                         e, F_, 0ll, 2 * B_, F_, H_);
    attn_alpha<<<B_, 128>>>(e, ab);
    scale_x<<<(T_ * B_ * F_ + 255) / 256, 256>>>(x, ab, xwx, T_ * B_ * F_);

    // 3) main biLSTM layer 0 (input F)
    run_stage(xwx, F_, m0Wih, m0Whh, m0bih, m0bhh, h0, c0, y);

    // 4) main biLSTM layers 1,2 (input 2H)
    run_stage(y, H2, mLWih, mLWhh, mLbih, mLbhh,
              h0 + 2 * B_ * H_, c0 + 2 * B_ * H_, y);
    run_stage(y, H2, mLWih + 2ll * G4 * H2, mLWhh + 2ll * G4 * H_,
              mLbih + 2 * G4, mLbhh + 2 * G4,
              h0 + 4 * B_ * H_, c0 + 4 * B_ * H_, y);

    // 5) final FC
    gemm_bias<0><<<dim3(H_ / 128, (T_ * B_) / 128, 1), 256>>>(
        y, H2, 0ll, fc1W, H2, 0ll, fc1b, 0ll, nullptr, 0ll,
        out, H_, 0ll, T_ * B_, H_, H2);
}

// round 3
// speedup vs baseline: 1.4807x; 1.0513x over previous
#include <cuda_runtime.h>
#include <math.h>
#include <stdint.h>

#define T_  128
#define B_  64
#define F_  75
#define H_  512
#define G4  2048   // 4*H
#define H2  1024   // 2*H

typedef unsigned long long ull;

// ---------------- static scratch ----------------
__device__ float g_xw   [2ll * T_ * B_ * G4];
__device__ float g_y    [(long long)T_ * B_ * H2];
__device__ float g_h    [2 * 2 * H_ * B_];        // ping-pong h: [buf][d][k][b]
__device__ float g_hlast[2 * B_ * H_];
__device__ float g_t1   [2 * B_ * H_];
__device__ float g_e    [2 * B_ * F_];
__device__ float g_ab   [B_ * F_];
__device__ float g_xwx  [T_ * B_ * F_];
__device__ unsigned g_bar[2];

// ---------------- f32x2 helpers ----------------
__device__ __forceinline__ ull pack2(float lo, float hi) {
    ull r;
    asm("mov.b64 %0, {%1, %2};" : "=l"(r) : "f"(lo), "f"(hi));
    return r;
}
__device__ __forceinline__ void unpack2(ull v, float& lo, float& hi) {
    asm("mov.b64 {%0, %1}, %2;" : "=f"(lo), "=f"(hi) : "l"(v));
}
__device__ __forceinline__ void ffma2(ull& d, ull a, ull b) {
    asm("fma.rn.f32x2 %0, %1, %2, %3;" : "=l"(d) : "l"(a), "l"(b), "l"(d));
}
__device__ __forceinline__ void cp16(uint32_t dst, const float* src) {
    asm volatile("cp.async.cg.shared.global [%0], [%1], 16;" :: "r"(dst), "l"(src));
}

// ================= big GEMM, f32x2 packed: C = A(MxK) @ W(NxK)^T + b1 + b2 =========
// 128x128x16 tiles, 256 threads, microtile 8(m, as 4 pairs) x 8(n, stride-16 interleave).
// Register-prefetch double buffering, one __syncthreads per k-chunk.
// Requires M % 128 == 0, N % 128 == 0 (true for all call sites).
__global__ void __launch_bounds__(256, 2)
gemm_f2(const float* __restrict__ A, int lda, long long sA,
        const float* __restrict__ W, int ldw, long long sW,
        const float* __restrict__ b1, long long sB1,
        const float* __restrict__ b2, long long sB2,
        float* __restrict__ C, int ldc, long long sC,
        int M, int N, int K)
{
    const int BK = 16;
    int bz = blockIdx.z;
    A += (long long)bz * sA;
    W += (long long)bz * sW;
    C += (long long)bz * sC;
    if (b1) b1 += (long long)bz * sB1;
    if (b2) b2 += (long long)bz * sB2;

    __shared__ float As[2][BK][130];   // [k][m], pad->conflict-free, 8B-aligned pairs
    __shared__ float Ws[2][BK][130];   // [k][n]

    const int m0 = blockIdx.y * 128;
    const int n0 = blockIdx.x * 128;
    const int tid = threadIdx.x;
    const int trow = tid >> 4, tcol = tid & 15;
    const int tm = trow * 8;           // 8 m-rows as 4 pairs

    ull acc[4][8];
    #pragma unroll
    for (int p = 0; p < 4; p++)
        #pragma unroll
        for (int j = 0; j < 8; j++) acc[p][j] = 0ull;

    float ra[8], rw[8];
    const int nk = (K + BK - 1) / BK;

    auto ldg = [&](int kk) {
        #pragma unroll
        for (int i = 0; i < 8; i++) {
            int idx = i * 256 + tid;
            int r = idx >> 4, k = idx & 15;
            int gk = kk + k;
            ra[i] = (gk < K) ? A[(long long)(m0 + r) * lda + gk] : 0.f;
            rw[i] = (gk < K) ? W[(long long)(n0 + r) * ldw + gk] : 0.f;
        }
    };
    auto sts = [&](int buf) {
        #pragma unroll
        for (int i = 0; i < 8; i++) {
            int idx = i * 256 + tid;
            int r = idx >> 4, k = idx & 15;
            As[buf][k][r] = ra[i];
            Ws[buf][k][r] = rw[i];
        }
    };

    ldg(0);
    sts(0);
    __syncthreads();

    for (int ch = 0; ch < nk; ch++) {
        if (ch + 1 < nk) ldg((ch + 1) * BK);

        const float* as = &As[ch & 1][0][0];
        const float* ws = &Ws[ch & 1][0][0];
        #pragma unroll
        for (int k = 0; k < BK; k++) {
            ull a[4];
            #pragma unroll
            for (int p = 0; p < 4; p++)
                a[p] = *(const ull*)(as + k * 130 + tm + 2 * p);
            ull wd[8];
            #pragma unroll
            for (int j = 0; j < 8; j++) {
                float w = ws[k * 130 + tcol + 16 * j];
                wd[j] = pack2(w, w);
            }
            #pragma unroll
            for (int p = 0; p < 4; p++)
                #pragma unroll
                for (int j = 0; j < 8; j++)
                    ffma2(acc[p][j], a[p], wd[j]);
        }

        if (ch + 1 < nk) {
            sts((ch + 1) & 1);
            __syncthreads();
        }
    }

    #pragma unroll
    for (int j = 0; j < 8; j++) {
        int gn = n0 + tcol + 16 * j;
        float bb = 0.f;
        if (b1) bb += b1[gn];
        if (b2) bb += b2[gn];
        #pragma unroll
        for (int p = 0; p < 4; p++) {
            float lo, hi;
            unpack2(acc[p][j], lo, hi);
            long long gm = m0 + tm + 2 * p;
            C[gm * ldc + gn]       = lo + bb;
            C[(gm + 1) * ldc + gn] = hi + bb;
        }
    }
}

// ================= small generic GEMM (attention FCs) ==============================
template<int ACT, int BM, int BN, int TM, int TN>
__global__ void gemm_small(const float* __restrict__ A, int lda,
                           const float* __restrict__ W, int ldw,
                           const float* __restrict__ b1,
                           float* __restrict__ C, int ldc,
                           int M, int N, int K)
{
    const int BK = 16;
    __shared__ float As[BK][BM + 2];
    __shared__ float Ws[BK][BN + 2];

    int m0 = blockIdx.y * BM;
    int n0 = blockIdx.x * BN;
    int tid = threadIdx.x;
    int tcol = tid % (BN / TN);
    int trow = tid / (BN / TN);
    int tm = trow * TM, tn = tcol * TN;

    float acc[TM][TN];
    #pragma unroll
    for (int i = 0; i < TM; i++)
        #pragma unroll
        for (int j = 0; j < TN; j++) acc[i][j] = 0.f;

    for (int kk = 0; kk < K; kk += BK) {
        for (int idx = tid; idx < BM * BK; idx += 256) {
            int m = idx / BK, k = idx % BK;
            int gm = m0 + m, gk = kk + k;
            As[k][m] = (gm < M && gk < K) ? A[(long long)gm * lda + gk] : 0.f;
        }
        for (int idx = tid; idx < BN * BK; idx += 256) {
            int n = idx / BK, k = idx % BK;
            int gn = n0 + n, gk = kk + k;
            Ws[k][n] = (gn < N && gk < K) ? W[(long long)gn * ldw + gk] : 0.f;
        }
        __syncthreads();
        #pragma unroll
        for (int k = 0; k < BK; k++) {
            float a[TM], w[TN];
            #pragma unroll
            for (int i = 0; i < TM; i++) a[i] = As[k][tm + i];
            #pragma unroll
            for (int j = 0; j < TN; j++) w[j] = Ws[k][tn + j];
            #pragma unroll
            for (int i = 0; i < TM; i++)
                #pragma unroll
                for (int j = 0; j < TN; j++)
                    acc[i][j] += a[i] * w[j];
        }
        __syncthreads();
    }

    #pragma unroll
    for (int i = 0; i < TM; i++) {
        int gm = m0 + tm + i;
        if (gm >= M) continue;
        #pragma unroll
        for (int j = 0; j < TN; j++) {
            int gn = n0 + tn + j;
            if (gn >= N) continue;
            float v = acc[i][j] + b1[gn];
            if (ACT == 1) v = tanhf(v);
            else if (ACT == 2) v = expf(v);
            C[(long long)gm * ldc + gn] = v;
        }
    }
}

// ---------------- persistent bidirectional LSTM recurrence ----------------
__global__ void __launch_bounds__(256, 1)
lstm_persist(const float* __restrict__ xw,   // [2][T][B][G4]
             const float* __restrict__ Whh,  // [2][G4][H]
             const float* __restrict__ c0s,  // [2][B][H]
             float* __restrict__ hbuf,       // [2][2][H][B]
             float* __restrict__ hlast,      // [2][B][H]
             float* __restrict__ y,          // [T][B][2H] or null
             unsigned* __restrict__ bar)
{
    extern __shared__ float sm[];
    float* ws  = sm;                 // [512][33]
    float* hsA = ws + 512 * 33;      // [128][64]
    float* hsB = hsA + 128 * 64;
    float* cs  = hsB + 128 * 64;     // [512]
    float* gs  = hsA;                // alias for gate exchange

    const int tid = threadIdx.x;
    const int d   = blockIdx.x >> 6;
    const int j0  = (blockIdx.x & 63) * 8;

    const int kh  = tid >> 7;
    const int lx  = tid & 127;
    const int b0  = (lx >> 4) * 8;
    const int c0  = (lx & 15) * 2;
    const int g0  = c0 >> 3;
    const int jj0 = c0 & 7;

    const float* wp = Whh + (size_t)d * G4 * H_;

    for (int i = tid; i < 512 * 32; i += 256) {
        int cl = i >> 9;
        int k  = i & 511;
        int gate = cl >> 3, jj = cl & 7;
        ws[k * 33 + cl] = wp[(size_t)(gate * H_ + j0 + jj) * H_ + k];
    }
    for (int i = tid; i < 512; i += 256) {
        int b = i >> 3, jj = i & 7;
        cs[i] = c0s[(size_t)d * B_ * H_ + b * H_ + j0 + jj];
    }
    __syncthreads();

    const uint32_t hsAaddr = (uint32_t)__cvta_generic_to_shared(hsA);
    const uint32_t hsBaddr = (uint32_t)__cvta_generic_to_shared(hsB);

    for (int t = 0; t < T_; t++) {
        const int td = d ? (T_ - 1 - t) : t;
        const float* hsrc = hbuf + ((t & 1) ? 2 * H_ * B_ : 0) + d * H_ * B_;
        float*       hdst = hbuf + ((t & 1) ? 0 : 2 * H_ * B_) + d * H_ * B_;
        const float* xp   = xw + ((size_t)(d * T_ + td) * B_) * G4;

        float xv[4][2][2];
        if (kh == 0) {
            #pragma unroll
            for (int p = 0; p < 4; p++)
                #pragma unroll
                for (int dd = 0; dd < 2; dd++)
                    #pragma unroll
                    for (int c = 0; c < 2; c++)
                        xv[p][dd][c] =
                            xp[(size_t)(b0 + 2 * p + dd) * G4 + g0 * H_ + j0 + jj0 + c];
        }

        ull acc[4][2];
        #pragma unroll
        for (int p = 0; p < 4; p++)
            #pragma unroll
            for (int c = 0; c < 2; c++) acc[p][c] = 0ull;

        {
            const float* src = hsrc;
            #pragma unroll
            for (int i = 0; i < 8; i++) {
                int idx = i * 256 + tid;
                cp16(hsAaddr + idx * 16, src + idx * 4);
            }
            asm volatile("cp.async.commit_group;");
        }

        #pragma unroll
        for (int ch = 0; ch < 4; ch++) {
            const float* cur = (ch & 1) ? hsB : hsA;
            if (ch < 3) {
                const float* src = hsrc + (ch + 1) * 128 * 64;
                uint32_t dsta = (ch & 1) ? hsAaddr : hsBaddr;
                #pragma unroll
                for (int i = 0; i < 8; i++) {
                    int idx = i * 256 + tid;
                    cp16(dsta + idx * 16, src + idx * 4);
                }
                asm volatile("cp.async.commit_group;");
                asm volatile("cp.async.wait_group 1;");
            } else {
                asm volatile("cp.async.wait_group 0;");
            }
            __syncthreads();

            const float* hrow = cur + kh * 64 * 64 + b0;
            const float* wrow = ws + (size_t)(ch * 128 + kh * 64) * 33;
            #pragma unroll 4
            for (int k = 0; k < 64; k++) {
                ull h0v = *(const ull*)(hrow + k * 64 + 0);
                ull h1v = *(const ull*)(hrow + k * 64 + 2);
                ull h2v = *(const ull*)(hrow + k * 64 + 4);
                ull h3v = *(const ull*)(hrow + k * 64 + 6);
                float w0 = wrow[k * 33 + c0];
                float w1 = wrow[k * 33 + c0 + 1];
                ull wd0 = pack2(w0, w0);
                ull wd1 = pack2(w1, w1);
                ffma2(acc[0][0], h0v, wd0); ffma2(acc[0][1], h0v, wd1);
                ffma2(acc[1][0], h1v, wd0); ffma2(acc[1][1], h1v, wd1);
                ffma2(acc[2][0], h2v, wd0); ffma2(acc[2][1], h2v, wd1);
                ffma2(acc[3][0], h3v, wd0); ffma2(acc[3][1], h3v, wd1);
            }
            __syncthreads();
        }

        #pragma unroll
        for (int p = 0; p < 4; p++)
            #pragma unroll
            for (int c = 0; c < 2; c++) {
                float lo, hi;
                unpack2(acc[p][c], lo, hi);
                if (kh == 0) { lo += xv[p][0][c]; hi += xv[p][1][c]; }
                gs[kh * 2112 + (b0 + 2 * p) * 33 + c0 + c]     = lo;
                gs[kh * 2112 + (b0 + 2 * p + 1) * 33 + c0 + c] = hi;
            }
        __syncthreads();

        #pragma unroll
        for (int it = 0; it < 2; it++) {
            int o = it * 256 + tid;
            int b = o >> 3, jj = o & 7;
            float gi = gs[b * 33 + jj]      + gs[2112 + b * 33 + jj];
            float gf = gs[b * 33 + 8 + jj]  + gs[2112 + b * 33 + 8 + jj];
            float gg = gs[b * 33 + 16 + jj] + gs[2112 + b * 33 + 16 + jj];
            float go = gs[b * 33 + 24 + jj] + gs[2112 + b * 33 + 24 + jj];
            float cv = cs[o];
            float si = 1.f / (1.f + expf(-gi));
            float sf = 1.f / (1.f + expf(-gf));
            float so = 1.f / (1.f + expf(-go));
            float cn = sf * cv + si * tanhf(gg);
            float hn = so * tanhf(cn);
            cs[o] = cn;
            hdst[(j0 + jj) * B_ + b] = hn;
            if (y) y[(size_t)(td * B_ + b) * H2 + d * H_ + j0 + jj] = hn;
            if (t == T_ - 1) hlast[(size_t)d * B_ * H_ + b * H_ + j0 + jj] = hn;
        }

        __threadfence();
        __syncthreads();
        if (t < T_ - 1) {
            if (tid == 0) {
                atomicAdd(&bar[d], 1u);
                unsigned tgt = 64u * (unsigned)(t + 1);
                unsigned v;
                do {
                    asm volatile("ld.acquire.gpu.u32 %0, [%1];" : "=r"(v) : "l"(bar + d));
                } while (v < tgt);
            }
            __syncthreads();
        }
    }
}

// ---------------- small kernels ----------------
__global__ void init_state(const float* __restrict__ h0s, float* __restrict__ hbuf,
                           unsigned* __restrict__ bar)
{
    int i = blockIdx.x * blockDim.x + threadIdx.x;
    if (i < 2) bar[i] = 0;
    if (i < 2 * H_ * B_) {
        int b = i & (B_ - 1);
        int k = (i >> 6) & (H_ - 1);
        int d = i >> 15;
        hbuf[i] = h0s[((size_t)d * B_ + b) * H_ + k];
    }
}

__global__ void attn_alpha(const float* __restrict__ e, float* __restrict__ alphab)
{
    int b = blockIdx.x;
    __shared__ float a[2 * F_];
    __shared__ float red[128];
    __shared__ float redc[128];
    int tid = threadIdx.x;

    for (int i = tid; i < 2 * F_; i += 128) {
        int d = i / F_, j = i % F_;
        a[i] = e[(d * B_ + b) * F_ + j];
    }
    __syncthreads();

    float s = 0.f;
    for (int i = tid; i < 2 * F_; i += 128) s += a[i];
    red[tid] = s; __syncthreads();
    for (int off = 64; off; off >>= 1) { if (tid < off) red[tid] += red[tid + off]; __syncthreads(); }
    float denom = red[0];
    __syncthreads();

    for (int i = tid; i < 2 * F_; i += 128) a[i] /= denom;
    __syncthreads();

    float cnt = 0.f, sel = 0.f;
    for (int i = tid; i < 2 * F_; i += 128) {
        float v = a[i];
        if (v >= 0.1f) { cnt += 1.f; sel += v; }
    }
    red[tid] = sel; redc[tid] = cnt; __syncthreads();
    for (int off = 64; off; off >>= 1) {
        if (tid < off) { red[tid] += red[tid + off]; redc[tid] += redc[tid + off]; }
        __syncthreads();
    }
    float selmean = red[0] / fmaxf(redc[0], 1.f);
    __syncthreads();

    for (int i = tid; i < 2 * F_; i += 128)
        if (a[i] >= 0.1f) a[i] = selmean;
    __syncthreads();

    for (int j = tid; j < F_; j += 128)
        alphab[b * F_ + j] = 0.5f * (a[j] + a[F_ + j]);
}

__global__ void scale_x(const float* __restrict__ x, const float* __restrict__ ab,
                        float* __restrict__ xo, int n)
{
    int i = blockIdx.x * blockDim.x + threadIdx.x;
    if (i < n) {
        int f = i % F_;
        int b = (i / F_) % B_;
        xo[i] = x[i] * ab[b * F_ + f];
    }
}

// ---------------- host driver ----------------
extern "C" void kernel_launch(void* const* d_in, const int* in_sizes, int n_in,
                              void* d_out, int out_size)
{
    const float* x     = (const float*)d_in[0];
    const float* h0    = (const float*)d_in[1];
    const float* c0    = (const float*)d_in[2];
    const float* saWih = (const float*)d_in[3];
    const float* saWhh = (const float*)d_in[4];
    const float* sabih = (const float*)d_in[5];
    const float* sabhh = (const float*)d_in[6];
    const float* m0Wih = (const float*)d_in[7];
    const float* m0Whh = (const float*)d_in[8];
    const float* m0bih = (const float*)d_in[9];
    const float* m0bhh = (const float*)d_in[10];
    const float* mLWih = (const float*)d_in[11];
    const float* mLWhh = (const float*)d_in[12];
    const float* mLbih = (const float*)d_in[13];
    const float* mLbhh = (const float*)d_in[14];
    const float* sf1W  = (const float*)d_in[15];
    const float* sf1b  = (const float*)d_in[16];
    const float* sf2W  = (const float*)d_in[17];
    const float* sf2b  = (const float*)d_in[18];
    const float* fc1W  = (const float*)d_in[19];
    const float* fc1b  = (const float*)d_in[20];
    float* out = (float*)d_out;

    float *xw, *y, *hbuf, *hlast, *t1, *e, *ab, *xwx;
    unsigned* bar;
    cudaGetSymbolAddress((void**)&xw,    g_xw);
    cudaGetSymbolAddress((void**)&y,     g_y);
    cudaGetSymbolAddress((void**)&hbuf,  g_h);
    cudaGetSymbolAddress((void**)&hlast, g_hlast);
    cudaGetSymbolAddress((void**)&t1,    g_t1);
    cudaGetSymbolAddress((void**)&e,     g_e);
    cudaGetSymbolAddress((void**)&ab,    g_ab);
    cudaGetSymbolAddress((void**)&xwx,   g_xwx);
    cudaGetSymbolAddress((void**)&bar,   g_bar);

    const int SMEMSZ = (512 * 33 + 2 * 128 * 64 + 512) * 4;
    cudaFuncSetAttribute(lstm_persist, cudaFuncAttributeMaxDynamicSharedMemorySize, SMEMSZ);

    auto run_stage = [&](const float* Ain, int K,
                         const float* Wih, const float* Whh,
                         const float* bih, const float* bhh,
                         const float* h0s, const float* c0s,
                         float* yout)
    {
        dim3 gp(G4 / 128, (T_ * B_) / 128, 2);
        gemm_f2<<<gp, 256>>>(Ain, K, 0ll,
                             Wih, K, (long long)G4 * K,
                             bih, G4, bhh, G4,
                             xw, G4, (long long)T_ * B_ * G4,
                             T_ * B_, G4, K);
        init_state<<<(2 * H_ * B_ + 255) / 256, 256>>>(h0s, hbuf, bar);
        lstm_persist<<<128, 256, SMEMSZ>>>(xw, Whh, c0s, hbuf, hlast, yout, bar);
    };

    // 1) spatial-attention biLSTM (only final hidden states needed)
    run_stage(x, F_, saWih, saWhh, sabih, sabhh, h0, c0, nullptr);

    // 2) attention weights from final hidden states (small-tile GEMMs)
    gemm_small<1, 32, 64, 2, 4><<<dim3(H_ / 64, (2 * B_ + 31) / 32), 256>>>(
        hlast, H_, sf1W, H_, sf1b, t1, H_, 2 * B_, H_, H_);
    gemm_small<2, 32, 64, 2, 4><<<dim3((F_ + 63) / 64, (2 * B_ + 31) / 32), 256>>>(
        t1, H_, sf2W, H_, sf2b, e, F_, 2 * B_, F_, H_);
    attn_alpha<<<B_, 128>>>(e, ab);
    scale_x<<<(T_ * B_ * F_ + 255) / 256, 256>>>(x, ab, xwx, T_ * B_ * F_);

    // 3) main biLSTM layer 0 (input F)
    run_stage(xwx, F_, m0Wih, m0Whh, m0bih, m0bhh, h0, c0, y);

    // 4) main biLSTM layers 1,2 (input 2H)
    run_stage(y, H2, mLWih, mLWhh, mLbih, mLbhh,
              h0 + 2 * B_ * H_, c0 + 2 * B_ * H_, y);
    run_stage(y, H2, mLWih + 2ll * G4 * H2, mLWhh + 2ll * G4 * H_,
              mLbih + 2 * G4, mLbhh + 2 * G4,
              h0 + 4 * B_ * H_, c0 + 4 * B_ * H_, y);

    // 5) final FC
    gemm_f2<<<dim3(H_ / 128, (T_ * B_) / 128, 1), 256>>>(
        y, H2, 0ll, fc1W, H2, 0ll, fc1b, 0ll, nullptr, 0ll,
        out, H_, 0ll, T_ * B_, H_, H2);
}

// round 5
// speedup vs baseline: 1.7774x; 1.2004x over previous
#include <cuda_runtime.h>
#include <cuda_bf16.h>
#include <math.h>
#include <stdint.h>

#define T_  128
#define B_  64
#define F_  75
#define H_  512
#define G4  2048   // 4*H
#define H2  1024   // 2*H

typedef unsigned long long ull;

// ---------------- static scratch ----------------
__device__ __align__(256) float g_xw   [2ll * T_ * B_ * G4];
__device__ __align__(256) float g_y    [(long long)T_ * B_ * H2];
__device__ __align__(256) float g_h    [2 * 2 * H_ * B_];    // ping-pong h: [buf][d][k][b]
__device__ float g_hlast[2 * B_ * H_];
__device__ float g_t1   [2 * B_ * H_];
__device__ float g_e    [2 * B_ * F_];
__device__ float g_ab   [B_ * F_];
__device__ float g_xwx  [T_ * B_ * F_];
__device__ unsigned g_bar[2];

// bf16 split buffers (hi / lo)
#define WSZ 10485760ll
__device__ __align__(256) __nv_bfloat16 g_wh[WSZ];
__device__ __align__(256) __nv_bfloat16 g_wl[WSZ];
__device__ __align__(256) __nv_bfloat16 g_ah[8388608ll];
__device__ __align__(256) __nv_bfloat16 g_al[8388608ll];

#define OFF_SAW 0ll
#define OFF_M0W 524288ll
#define OFF_MLW 1048576ll
#define OFF_FCW 9437184ll

// ---------------- helpers ----------------
__device__ __forceinline__ ull pack2(float lo, float hi) {
    ull r; asm("mov.b64 %0, {%1, %2};" : "=l"(r) : "f"(lo), "f"(hi)); return r;
}
__device__ __forceinline__ void unpack2(ull v, float& lo, float& hi) {
    asm("mov.b64 {%0, %1}, %2;" : "=f"(lo), "=f"(hi) : "l"(v));
}
__device__ __forceinline__ void ffma2(ull& d, ull a, ull b) {
    asm("fma.rn.f32x2 %0, %1, %2, %3;" : "=l"(d) : "l"(a), "l"(b), "l"(d));
}
__device__ __forceinline__ void cp16(uint32_t dst, const void* src) {
    asm volatile("cp.async.cg.shared.global [%0], [%1], 16;" :: "r"(dst), "l"(src));
}
__device__ __forceinline__ uint32_t smem_u32(const void* p) {
    return (uint32_t)__cvta_generic_to_shared(p);
}
__device__ __forceinline__ void mma_bf16(float* d, const uint32_t* a, const uint32_t* b) {
    asm volatile(
        "mma.sync.aligned.m16n8k16.row.col.f32.bf16.bf16.f32 "
        "{%0,%1,%2,%3}, {%4,%5,%6,%7}, {%8,%9}, {%0,%1,%2,%3};"
        : "+f"(d[0]), "+f"(d[1]), "+f"(d[2]), "+f"(d[3])
        : "r"(a[0]), "r"(a[1]), "r"(a[2]), "r"(a[3]), "r"(b[0]), "r"(b[1]));
}

// ---------------- fp32 -> bf16 hi/lo split conversion ----------------
__global__ void conv_split(const float* __restrict__ src, int rows, int K, int Kpad,
                           __nv_bfloat16* __restrict__ hi, __nv_bfloat16* __restrict__ lo)
{
    long long n = (long long)rows * Kpad;
    for (long long i = blockIdx.x * (long long)blockDim.x + threadIdx.x; i < n;
         i += (long long)gridDim.x * blockDim.x) {
        int kc = (int)(i % Kpad);
        long long r = i / Kpad;
        float v = (kc < K) ? src[r * K + kc] : 0.f;
        __nv_bfloat16 h = __float2bfloat16(v);
        hi[i] = h;
        lo[i] = __float2bfloat16(v - __bfloat162float(h));
    }
}

// ================= bf16 split tensor-core GEMM (mma.sync / HMMA) ==================
// C(z)[m][n] = sum_k A[m][k]*W(z)[n][k] + b1(z)[n] + b2(z)[n], fp32 out.
// A,W as bf16 hi/lo pairs, row stride Kpad (mult of 32). M,N multiples of 128.
// CTA 128x128x32 tile, 8 warps (2x4), warp tile 64x32, double-buffered cp.async.
#define PITCH 40            // bf16 elems per smem row (80 B): 16B-aligned + conflict-free
#define TILEB 10240         // 128 * 80
#define BUFB  40960         // 4 tiles per buffer

__global__ void __launch_bounds__(256, 1)
gemm_mma(const __nv_bfloat16* __restrict__ Ah, const __nv_bfloat16* __restrict__ Al,
         const __nv_bfloat16* __restrict__ Wh, const __nv_bfloat16* __restrict__ Wl,
         long long sW,
         const float* __restrict__ b1, long long sB1,
         const float* __restrict__ b2, long long sB2,
         float* __restrict__ C, long long sC,
         int Kpad, int N)
{
    extern __shared__ char smem[];
    const uint32_t sb = smem_u32(smem);

    const int z = blockIdx.z;
    Wh += (long long)z * sW;
    Wl += (long long)z * sW;
    C  += (long long)z * sC;
    if (b1) b1 += (long long)z * sB1;
    if (b2) b2 += (long long)z * sB2;

    const int tid  = threadIdx.x;
    const int lane = tid & 31;
    const int warp = tid >> 5;
    const int wm   = warp >> 2;          // 0..1
    const int wn   = warp & 3;           // 0..3
    const int m0   = blockIdx.y * 128;
    const int n0   = blockIdx.x * 128;
    const int q2   = (lane & 3) * 2;     // k sub-offset within fragment
    const int lr   = lane >> 2;          // row/col sub-offset

    float acc[4][4][4];
    #pragma unroll
    for (int mf = 0; mf < 4; mf++)
        #pragma unroll
        for (int nf = 0; nf < 4; nf++)
            #pragma unroll
            for (int r = 0; r < 4; r++) acc[mf][nf][r] = 0.f;

    // staging: 512 16B chunks per tile, 2 per thread per tile
    const int sr = tid >> 1;                   // 0..127 (row)
    const int skc = (tid & 1) * 2;             // chunk col pair base (0 or 2)

    auto stage = [&](int buf, int ch) {
        long long col = (long long)ch * 32;
        #pragma unroll
        for (int i = 0; i < 2; i++) {
            int kc = skc + i;                  // 0..3, 8 bf16 each
            uint32_t so = (uint32_t)(buf * BUFB + sr * 80 + kc * 16);
            long long gc = col + kc * 8;
            cp16(sb + so,             Ah + (long long)(m0 + sr) * Kpad + gc);
            cp16(sb + so + TILEB,     Al + (long long)(m0 + sr) * Kpad + gc);
            cp16(sb + so + 2 * TILEB, Wh + (long long)(n0 + sr) * Kpad + gc);
            cp16(sb + so + 3 * TILEB, Wl + (long long)(n0 + sr) * Kpad + gc);
        }
        asm volatile("cp.async.commit_group;");
    };

    const int nch = Kpad >> 5;
    stage(0, 0);

    for (int ch = 0; ch < nch; ch++) {
        if (ch + 1 < nch) {
            stage((ch + 1) & 1, ch + 1);
            asm volatile("cp.async.wait_group 1;");
        } else {
            asm volatile("cp.async.wait_group 0;");
        }
        __syncthreads();

        const char* base = smem + (ch & 1) * BUFB;
        #pragma unroll
        for (int ks = 0; ks < 2; ks++) {
            const int k0 = ks * 16;
            uint32_t ah[4][4], al[4][4], bh[4][2], bl[4][2];
            #pragma unroll
            for (int mf = 0; mf < 4; mf++) {
                int row = wm * 64 + mf * 16 + lr;
                const char* p0 = base + row * 80 + (k0 + q2) * 2;
                const char* p1 = base + (row + 8) * 80 + (k0 + q2) * 2;
                ah[mf][0] = *(const uint32_t*)(p0);
                ah[mf][1] = *(const uint32_t*)(p1);
                ah[mf][2] = *(const uint32_t*)(p0 + 16);
                ah[mf][3] = *(const uint32_t*)(p1 + 16);
                al[mf][0] = *(const uint32_t*)(p0 + TILEB);
                al[mf][1] = *(const uint32_t*)(p1 + TILEB);
                al[mf][2] = *(const uint32_t*)(p0 + 16 + TILEB);
                al[mf][3] = *(const uint32_t*)(p1 + 16 + TILEB);
            }
            #pragma unroll
            for (int nf = 0; nf < 4; nf++) {
                int col = wn * 32 + nf * 8 + lr;
                const char* p = base + 2 * TILEB + col * 80 + (k0 + q2) * 2;
                bh[nf][0] = *(const uint32_t*)(p);
                bh[nf][1] = *(const uint32_t*)(p + 16);
                bl[nf][0] = *(const uint32_t*)(p + TILEB);
                bl[nf][1] = *(const uint32_t*)(p + 16 + TILEB);
            }
            #pragma unroll
            for (int mf = 0; mf < 4; mf++)
                #pragma unroll
                for (int nf = 0; nf < 4; nf++)
                    mma_bf16(acc[mf][nf], ah[mf], bh[nf]);
            #pragma unroll
            for (int mf = 0; mf < 4; mf++)
                #pragma unroll
                for (int nf = 0; nf < 4; nf++)
                    mma_bf16(acc[mf][nf], ah[mf], bl[nf]);
            #pragma unroll
            for (int mf = 0; mf < 4; mf++)
                #pragma unroll
                for (int nf = 0; nf < 4; nf++)
                    mma_bf16(acc[mf][nf], al[mf], bh[nf]);
        }
        __syncthreads();
    }

    // epilogue
    #pragma unroll
    for (int nf = 0; nf < 4; nf++) {
        int gn = n0 + wn * 32 + nf * 8 + q2;
        float bb0 = 0.f, bb1 = 0.f;
        if (b1) { bb0 += b1[gn]; bb1 += b1[gn + 1]; }
        if (b2) { bb0 += b2[gn]; bb1 += b2[gn + 1]; }
        #pragma unroll
        for (int mf = 0; mf < 4; mf++) {
            long long gm = m0 + wm * 64 + mf * 16 + lr;
            float2 v0 = make_float2(acc[mf][nf][0] + bb0, acc[mf][nf][1] + bb1);
            float2 v1 = make_float2(acc[mf][nf][2] + bb0, acc[mf][nf][3] + bb1);
            *(float2*)(C + gm * N + gn)       = v0;
            *(float2*)(C + (gm + 8) * N + gn) = v1;
        }
    }
}

// ================= small generic GEMM (attention FCs) ==============================
template<int ACT, int BM, int BN, int TM, int TN>
__global__ void gemm_small(const float* __restrict__ A, int lda,
                           const float* __restrict__ W, int ldw,
                           const float* __restrict__ b1,
                           float* __restrict__ C, int ldc,
                           int M, int N, int K)
{
    const int BK = 16;
    __shared__ float As[BK][BM + 2];
    __shared__ float Ws[BK][BN + 2];

    int m0 = blockIdx.y * BM;
    int n0 = blockIdx.x * BN;
    int tid = threadIdx.x;
    int tcol = tid % (BN / TN);
    int trow = tid / (BN / TN);
    int tm = trow * TM, tn = tcol * TN;

    float acc[TM][TN];
    #pragma unroll
    for (int i = 0; i < TM; i++)
        #pragma unroll
        for (int j = 0; j < TN; j++) acc[i][j] = 0.f;

    for (int kk = 0; kk < K; kk += BK) {
        for (int idx = tid; idx < BM * BK; idx += 256) {
            int m = idx / BK, k = idx % BK;
            int gm = m0 + m, gk = kk + k;
            As[k][m] = (gm < M && gk < K) ? A[(long long)gm * lda + gk] : 0.f;
        }
        for (int idx = tid; idx < BN * BK; idx += 256) {
            int n = idx / BK, k = idx % BK;
            int gn = n0 + n, gk = kk + k;
            Ws[k][n] = (gn < N && gk < K) ? W[(long long)gn * ldw + gk] : 0.f;
        }
        __syncthreads();
        #pragma unroll
        for (int k = 0; k < BK; k++) {
            float a[TM], w[TN];
            #pragma unroll
            for (int i = 0; i < TM; i++) a[i] = As[k][tm + i];
            #pragma unroll
            for (int j = 0; j < TN; j++) w[j] = Ws[k][tn + j];
            #pragma unroll
            for (int i = 0; i < TM; i++)
                #pragma unroll
                for (int j = 0; j < TN; j++)
                    acc[i][j] += a[i] * w[j];
        }
        __syncthreads();
    }

    #pragma unroll
    for (int i = 0; i < TM; i++) {
        int gm = m0 + tm + i;
        if (gm >= M) continue;
        #pragma unroll
        for (int j = 0; j < TN; j++) {
            int gn = n0 + tn + j;
            if (gn >= N) continue;
            float v = acc[i][j] + b1[gn];
            if (ACT == 1) v = tanhf(v);
            else if (ACT == 2) v = expf(v);
            C[(long long)gm * ldc + gn] = v;
        }
    }
}

// ---------------- persistent bidirectional LSTM recurrence ----------------
__global__ void __launch_bounds__(256, 1)
lstm_persist(const float* __restrict__ xw,   // [2][T][B][G4]
             const float* __restrict__ Whh,  // [2][G4][H]
             const float* __restrict__ c0s,  // [2][B][H]
             float* __restrict__ hbuf,       // [2][2][H][B]
             float* __restrict__ hlast,      // [2][B][H]
             float* __restrict__ y,          // [T][B][2H] or null
             unsigned* __restrict__ bar)
{
    extern __shared__ float sm[];
    float* ws  = sm;                 // [512][33]
    float* hsA = ws + 512 * 33;      // [128][64]
    float* hsB = hsA + 128 * 64;
    float* cs  = hsB + 128 * 64;     // [512]
    float* xt  = cs + 512;           // [64][32] xw tile for this step
    float* gs  = hsA;                // alias for gate exchange

    const int tid = threadIdx.x;
    const int d   = blockIdx.x >> 6;
    const int j0  = (blockIdx.x & 63) * 8;

    const int kh  = tid >> 7;
    const int lx  = tid & 127;
    const int b0  = (lx >> 4) * 8;
    const int c0  = (lx & 15) * 2;

    const float* wp = Whh + (size_t)d * G4 * H_;

    for (int i = tid; i < 512 * 32; i += 256) {
        int cl = i >> 9;
        int k  = i & 511;
        int gate = cl >> 3, jj = cl & 7;
        ws[k * 33 + cl] = wp[(size_t)(gate * H_ + j0 + jj) * H_ + k];
    }
    for (int i = tid; i < 512; i += 256) {
        int b = i >> 3, jj = i & 7;
        cs[i] = c0s[(size_t)d * B_ * H_ + b * H_ + j0 + jj];
    }
    __syncthreads();

    const uint32_t hsAaddr = smem_u32(hsA);
    const uint32_t hsBaddr = smem_u32(hsB);
    const uint32_t xtaddr  = smem_u32(xt);

    for (int t = 0; t < T_; t++) {
        const int td = d ? (T_ - 1 - t) : t;
        const float* hsrc = hbuf + ((t & 1) ? 2 * H_ * B_ : 0) + d * H_ * B_;
        float*       hdst = hbuf + ((t & 1) ? 0 : 2 * H_ * B_) + d * H_ * B_;
        const float* xp   = xw + ((size_t)(d * T_ + td) * B_) * G4;

        // stage xw tile: 64 b x 4 gates x 8 floats -> xt[b][gate*8+jj]
        #pragma unroll
        for (int i = 0; i < 2; i++) {
            int idx = i * 256 + tid;          // 0..511
            int half = idx & 1, seg = idx >> 1;
            int b = seg >> 2, gate = seg & 3;
            cp16(xtaddr + idx * 16, xp + (size_t)b * G4 + gate * H_ + j0 + half * 4);
        }
        asm volatile("cp.async.commit_group;");

        ull acc[4][2];
        #pragma unroll
        for (int p = 0; p < 4; p++)
            #pragma unroll
            for (int c = 0; c < 2; c++) acc[p][c] = 0ull;

        // stage h chunk 0
        #pragma unroll
        for (int i = 0; i < 8; i++) {
            int idx = i * 256 + tid;
            cp16(hsAaddr + idx * 16, hsrc + idx * 4);
        }
        asm volatile("cp.async.commit_group;");

        #pragma unroll
        for (int ch = 0; ch < 4; ch++) {
            const float* cur = (ch & 1) ? hsB : hsA;
            if (ch < 3) {
                const float* src = hsrc + (ch + 1) * 128 * 64;
                uint32_t dsta = (ch & 1) ? hsAaddr : hsBaddr;
                #pragma unroll
                for (int i = 0; i < 8; i++) {
                    int idx = i * 256 + tid;
                    cp16(dsta + idx * 16, src + idx * 4);
                }
                asm volatile("cp.async.commit_group;");
                asm volatile("cp.async.wait_group 1;");
            } else {
                asm volatile("cp.async.wait_group 0;");
            }
            __syncthreads();

            const float* hrow = cur + kh * 64 * 64 + b0;
            const float* wrow = ws + (size_t)(ch * 128 + kh * 64) * 33;
            #pragma unroll 4
            for (int k = 0; k < 64; k++) {
                ull h0v = *(const ull*)(hrow + k * 64 + 0);
                ull h1v = *(const ull*)(hrow + k * 64 + 2);
                ull h2v = *(const ull*)(hrow + k * 64 + 4);
                ull h3v = *(const ull*)(hrow + k * 64 + 6);
                float w0 = wrow[k * 33 + c0];
                float w1 = wrow[k * 33 + c0 + 1];
                ull wd0 = pack2(w0, w0);
                ull wd1 = pack2(w1, w1);
                ffma2(acc[0][0], h0v, wd0); ffma2(acc[0][1], h0v, wd1);
                ffma2(acc[1][0], h1v, wd0); ffma2(acc[1][1], h1v, wd1);
                ffma2(acc[2][0], h2v, wd0); ffma2(acc[2][1], h2v, wd1);
                ffma2(acc[3][0], h3v, wd0); ffma2(acc[3][1], h3v, wd1);
            }
            __syncthreads();
        }

        #pragma unroll
        for (int p = 0; p < 4; p++)
            #pragma unroll
            for (int c = 0; c < 2; c++) {
                float lo, hi;
                unpack2(acc[p][c], lo, hi);
                gs[kh * 2112 + (b0 + 2 * p) * 33 + c0 + c]     = lo;
                gs[kh * 2112 + (b0 + 2 * p + 1) * 33 + c0 + c] = hi;
            }
        __syncthreads();

        #pragma unroll
        for (int it = 0; it < 2; it++) {
            int o = it * 256 + tid;
            int b = o >> 3, jj = o & 7;
            float gi = gs[b * 33 + jj]      + gs[2112 + b * 33 + jj]      + xt[b * 32 + jj];
            float gf = gs[b * 33 + 8 + jj]  + gs[2112 + b * 33 + 8 + jj]  + xt[b * 32 + 8 + jj];
            float gg = gs[b * 33 + 16 + jj] + gs[2112 + b * 33 + 16 + jj] + xt[b * 32 + 16 + jj];
            float go = gs[b * 33 + 24 + jj] + gs[2112 + b * 33 + 24 + jj] + xt[b * 32 + 24 + jj];
            float cv = cs[o];
            float si = 1.f / (1.f + expf(-gi));
            float sf = 1.f / (1.f + expf(-gf));
            float so = 1.f / (1.f + expf(-go));
            float cn = sf * cv + si * tanhf(gg);
            float hn = so * tanhf(cn);
            cs[o] = cn;
            hdst[(j0 + jj) * B_ + b] = hn;
            if (y) y[(size_t)(td * B_ + b) * H2 + d * H_ + j0 + jj] = hn;
            if (t == T_ - 1) hlast[(size_t)d * B_ * H_ + b * H_ + j0 + jj] = hn;
        }

        __threadfence();
        __syncthreads();
        if (t < T_ - 1) {
            if (tid == 0) {
                atomicAdd(&bar[d], 1u);
                unsigned tgt = 64u * (unsigned)(t + 1);
                unsigned v;
                do {
                    asm volatile("ld.acquire.gpu.u32 %0, [%1];" : "=r"(v) : "l"(bar + d));
                } while (v < tgt);
            }
            __syncthreads();
        }
    }
}

// ---------------- small kernels ----------------
__global__ void init_state(const float* __restrict__ h0s, float* __restrict__ hbuf,
                           unsigned* __restrict__ bar)
{
    int i = blockIdx.x * blockDim.x + threadIdx.x;
    if (i < 2) bar[i] = 0;
    if (i < 2 * H_ * B_) {
        int b = i & (B_ - 1);
        int k = (i >> 6) & (H_ - 1);
        int d = i >> 15;
        hbuf[i] = h0s[((size_t)d * B_ + b) * H_ + k];
    }
}

__global__ void attn_alpha(const float* __restrict__ e, float* __restrict__ alphab)
{
    int b = blockIdx.x;
    __shared__ float a[2 * F_];
    __shared__ float red[128];
    __shared__ float redc[128];
    int tid = threadIdx.x;

    for (int i = tid; i < 2 * F_; i += 128) {
        int d = i / F_, j = i % F_;
        a[i] = e[(d * B_ + b) * F_ + j];
    }
    __syncthreads();

    float s = 0.f;
    for (int i = tid; i < 2 * F_; i += 128) s += a[i];
    red[tid] = s; __syncthreads();
    for (int off = 64; off; off >>= 1) { if (tid < off) red[tid] += red[tid + off]; __syncthreads(); }
    float denom = red[0];
    __syncthreads();

    for (int i = tid; i < 2 * F_; i += 128) a[i] /= denom;
    __syncthreads();

    float cnt = 0.f, sel = 0.f;
    for (int i = tid; i < 2 * F_; i += 128) {
        float v = a[i];
        if (v >= 0.1f) { cnt += 1.f; sel += v; }
    }
    red[tid] = sel; redc[tid] = cnt; __syncthreads();
    for (int off = 64; off; off >>= 1) {
        if (tid < off) { red[tid] += red[tid + off]; redc[tid] += redc[tid + off]; }
        __syncthreads();
    }
    float selmean = red[0] / fmaxf(redc[0], 1.f);
    __syncthreads();

    for (int i = tid; i < 2 * F_; i += 128)
        if (a[i] >= 0.1f) a[i] = selmean;
    __syncthreads();

    for (int j = tid; j < F_; j += 128)
        alphab[b * F_ + j] = 0.5f * (a[j] + a[F_ + j]);
}

__global__ void scale_x(const float* __restrict__ x, const float* __restrict__ ab,
                        float* __restrict__ xo, int n)
{
    int i = blockIdx.x * blockDim.x + threadIdx.x;
    if (i < n) {
        int f = i % F_;
        int b = (i / F_) % B_;
        xo[i] = x[i] * ab[b * F_ + f];
    }
}

// ---------------- host driver ----------------
extern "C" void kernel_launch(void* const* d_in, const int* in_sizes, int n_in,
                              void* d_out, int out_size)
{
    const float* x     = (const float*)d_in[0];
    const float* h0    = (const float*)d_in[1];
    const float* c0    = (const float*)d_in[2];
    const float* saWih = (const float*)d_in[3];
    const float* saWhh = (const float*)d_in[4];
    const float* sabih = (const float*)d_in[5];
    const float* sabhh = (const float*)d_in[6];
    const float* m0Wih = (const float*)d_in[7];
    const float* m0Whh = (const float*)d_in[8];
    const float* m0bih = (const float*)d_in[9];
    const float* m0bhh = (const float*)d_in[10];
    const float* mLWih = (const float*)d_in[11];
    const float* mLWhh = (const float*)d_in[12];
    const float* mLbih = (const float*)d_in[13];
    const float* mLbhh = (const float*)d_in[14];
    const float* sf1W  = (const float*)d_in[15];
    const float* sf1b  = (const float*)d_in[16];
    const float* sf2W  = (const float*)d_in[17];
    const float* sf2b  = (const float*)d_in[18];
    const float* fc1W  = (const float*)d_in[19];
    const float* fc1b  = (const float*)d_in[20];
    float* out = (float*)d_out;

    float *xw, *y, *hbuf, *hlast, *t1, *e, *ab, *xwx;
    unsigned* bar;
    __nv_bfloat16 *wh, *wl, *ah, *al;
    cudaGetSymbolAddress((void**)&xw,    g_xw);
    cudaGetSymbolAddress((void**)&y,     g_y);
    cudaGetSymbolAddress((void**)&hbuf,  g_h);
    cudaGetSymbolAddress((void**)&hlast, g_hlast);
    cudaGetSymbolAddress((void**)&t1,    g_t1);
    cudaGetSymbolAddress((void**)&e,     g_e);
    cudaGetSymbolAddress((void**)&ab,    g_ab);
    cudaGetSymbolAddress((void**)&xwx,   g_xwx);
    cudaGetSymbolAddress((void**)&bar,   g_bar);
    cudaGetSymbolAddress((void**)&wh,    g_wh);
    cudaGetSymbolAddress((void**)&wl,    g_wl);
    cudaGetSymbolAddress((void**)&ah,    g_ah);
    cudaGetSymbolAddress((void**)&al,    g_al);

    const int SMEM_LSTM = (512 * 33 + 2 * 128 * 64 + 512 + 2048) * 4;   // 143360
    cudaFuncSetAttribute(lstm_persist, cudaFuncAttributeMaxDynamicSharedMemorySize, SMEM_LSTM);
    const int SMEM_MMA = 2 * BUFB;   // 81920
    cudaFuncSetAttribute(gemm_mma, cudaFuncAttributeMaxDynamicSharedMemorySize, SMEM_MMA);

    const int M = T_ * B_;   // 8192

    auto proj = [&](long long woff, const float* bih, const float* bhh, int Kpad) {
        gemm_mma<<<dim3(G4 / 128, M / 128, 2), 256, SMEM_MMA>>>(
            ah, al, wh + woff, wl + woff, (long long)G4 * Kpad,
            bih, G4, bhh, G4, xw, (long long)M * G4, Kpad, G4);
    };
    auto recur = [&](const float* Whh, const float* h0s, const float* c0s, float* yout) {
        init_state<<<(2 * H_ * B_ + 255) / 256, 256>>>(h0s, hbuf, bar);
        lstm_persist<<<128, 256, SMEM_LSTM>>>(xw, Whh, c0s, hbuf, hlast, yout, bar);
    };

    // ---- stage 1: spatial-attention biLSTM ----
    conv_split<<<1024, 256>>>(saWih, 2 * G4, F_, 128, wh + OFF_SAW, wl + OFF_SAW);
    conv_split<<<1024, 256>>>(x, M, F_, 128, ah, al);
    proj(OFF_SAW, sabih, sabhh, 128);
    conv_split<<<1024, 256>>>(m0Wih, 2 * G4, F_, 128, wh + OFF_M0W, wl + OFF_M0W);
    init_state<<<(2 * H_ * B_ + 255) / 256, 256>>>(h0, hbuf, bar);
    lstm_persist<<<128, 256, SMEM_LSTM>>>(xw, saWhh, c0, hbuf, hlast, nullptr, bar);

    // ---- attention ----
    gemm_small<1, 32, 64, 2, 4><<<dim3(H_ / 64, (2 * B_ + 31) / 32), 256>>>(
        hlast, H_, sf1W, H_, sf1b, t1, H_, 2 * B_, H_, H_);
    gemm_small<2, 32, 64, 2, 4><<<dim3((F_ + 63) / 64, (2 * B_ + 31) / 32), 256>>>(
        t1, H_, sf2W, H_, sf2b, e, F_, 2 * B_, F_, H_);
    attn_alpha<<<B_, 128>>>(e, ab);
    scale_x<<<(T_ * B_ * F_ + 255) / 256, 256>>>(x, ab, xwx, T_ * B_ * F_);

    // ---- main layer 0 ----
    conv_split<<<1024, 256>>>(xwx, M, F_, 128, ah, al);
    proj(OFF_M0W, m0bih, m0bhh, 128);
    recur(m0Whh, h0, c0, y);

    // ---- main layers 1,2 ----
    conv_split<<<2048, 256>>>(mLWih, 2 * 2 * G4, H2, H2, wh + OFF_MLW, wl + OFF_MLW);
    conv_split<<<2048, 256>>>(y, M, H2, H2, ah, al);
    proj(OFF_MLW, mLbih, mLbhh, H2);
    recur(mLWhh, h0 + 2 * B_ * H_, c0 + 2 * B_ * H_, y);

    conv_split<<<2048, 256>>>(y, M, H2, H2, ah, al);
    gemm_mma<<<dim3(G4 / 128, M / 128, 2), 256, SMEM_MMA>>>(
        ah, al, wh + OFF_MLW + 2ll * G4 * H2, wl + OFF_MLW + 2ll * G4 * H2,
        (long long)G4 * H2,
        mLbih + 2 * G4, G4, mLbhh + 2 * G4, G4, xw, (long long)M * G4, H2, G4);
    recur(mLWhh + 2ll * G4 * H_, h0 + 4 * B_ * H_, c0 + 4 * B_ * H_, y);

    // ---- final FC ----
    conv_split<<<2048, 256>>>(fc1W, H_, H2, H2, wh + OFF_FCW, wl + OFF_FCW);
    conv_split<<<2048, 256>>>(y, M, H2, H2, ah, al);
    gemm_mma<<<dim3(H_ / 128, M / 128, 1), 256, SMEM_MMA>>>(
        ah, al, wh + OFF_FCW, wl + OFF_FCW, 0ll,
        fc1b, 0ll, nullptr, 0ll, out, 0ll, H2, H_);
}

// round 6
// speedup vs baseline: 2.3095x; 1.2994x over previous
#include <cuda_runtime.h>
#include <cuda_bf16.h>
#include <math.h>
#include <stdint.h>

#define T_  128
#define B_  64
#define F_  75
#define H_  512
#define G4  2048   // 4*H
#define H2  1024   // 2*H

typedef unsigned long long ull;

// ---------------- static scratch ----------------
__device__ __align__(256) float g_xw   [2ll * T_ * B_ * G4];
__device__ __align__(256) float g_y    [(long long)T_ * B_ * H2];
__device__ __align__(256) __nv_bfloat16 g_hbf[2 * 2 * 2 * B_ * H_];  // [buf][d][hi/lo][b][k]
__device__ float g_hlast[2 * B_ * H_];
__device__ float g_t1   [2 * B_ * H_];
__device__ float g_e    [2 * B_ * F_];
__device__ float g_ab   [B_ * F_];
__device__ float g_xwx  [T_ * B_ * F_];
__device__ unsigned g_bar[2];

// bf16 split buffers (hi / lo)
#define WSZ 10485760ll
__device__ __align__(256) __nv_bfloat16 g_wh[WSZ];
__device__ __align__(256) __nv_bfloat16 g_wl[WSZ];
__device__ __align__(256) __nv_bfloat16 g_ah[8388608ll];
__device__ __align__(256) __nv_bfloat16 g_al[8388608ll];

#define OFF_SAW 0ll
#define OFF_M0W 524288ll
#define OFF_MLW 1048576ll
#define OFF_FCW 9437184ll

// ---------------- helpers ----------------
__device__ __forceinline__ void cp16(uint32_t dst, const void* src) {
    asm volatile("cp.async.cg.shared.global [%0], [%1], 16;" :: "r"(dst), "l"(src));
}
__device__ __forceinline__ uint32_t smem_u32(const void* p) {
    return (uint32_t)__cvta_generic_to_shared(p);
}
__device__ __forceinline__ void mma_bf16(float* d, const uint32_t* a, const uint32_t* b) {
    asm volatile(
        "mma.sync.aligned.m16n8k16.row.col.f32.bf16.bf16.f32 "
        "{%0,%1,%2,%3}, {%4,%5,%6,%7}, {%8,%9}, {%0,%1,%2,%3};"
        : "+f"(d[0]), "+f"(d[1]), "+f"(d[2]), "+f"(d[3])
        : "r"(a[0]), "r"(a[1]), "r"(a[2]), "r"(a[3]), "r"(b[0]), "r"(b[1]));
}
__device__ __forceinline__ uint32_t pkbf2(float a, float b) {
    __nv_bfloat16 ha = __float2bfloat16(a), hb = __float2bfloat16(b);
    uint16_t ua = *(uint16_t*)&ha, ub = *(uint16_t*)&hb;
    return (uint32_t)ua | ((uint32_t)ub << 16);
}

// ---------------- fp32 -> bf16 hi/lo split conversion ----------------
__global__ void conv_split(const float* __restrict__ src, int rows, int K, int Kpad,
                           __nv_bfloat16* __restrict__ hi, __nv_bfloat16* __restrict__ lo)
{
    long long n = (long long)rows * Kpad;
    for (long long i = blockIdx.x * (long long)blockDim.x + threadIdx.x; i < n;
         i += (long long)gridDim.x * blockDim.x) {
        int kc = (int)(i % Kpad);
        long long r = i / Kpad;
        float v = (kc < K) ? src[r * K + kc] : 0.f;
        __nv_bfloat16 h = __float2bfloat16(v);
        hi[i] = h;
        lo[i] = __float2bfloat16(v - __bfloat162float(h));
    }
}

// ================= bf16 split tensor-core GEMM (mma.sync / HMMA) ==================
#define PITCH 40
#define TILEB 10240
#define BUFB  40960

__global__ void __launch_bounds__(256, 1)
gemm_mma(const __nv_bfloat16* __restrict__ Ah, const __nv_bfloat16* __restrict__ Al,
         const __nv_bfloat16* __restrict__ Wh, const __nv_bfloat16* __restrict__ Wl,
         long long sW,
         const float* __restrict__ b1, long long sB1,
         const float* __restrict__ b2, long long sB2,
         float* __restrict__ C, long long sC,
         int Kpad, int N)
{
    extern __shared__ char smem[];
    const uint32_t sb = smem_u32(smem);

    const int z = blockIdx.z;
    Wh += (long long)z * sW;
    Wl += (long long)z * sW;
    C  += (long long)z * sC;
    if (b1) b1 += (long long)z * sB1;
    if (b2) b2 += (long long)z * sB2;

    const int tid  = threadIdx.x;
    const int lane = tid & 31;
    const int warp = tid >> 5;
    const int wm   = warp >> 2;
    const int wn   = warp & 3;
    const int m0   = blockIdx.y * 128;
    const int n0   = blockIdx.x * 128;
    const int q2   = (lane & 3) * 2;
    const int lr   = lane >> 2;

    float acc[4][4][4];
    #pragma unroll
    for (int mf = 0; mf < 4; mf++)
        #pragma unroll
        for (int nf = 0; nf < 4; nf++)
            #pragma unroll
            for (int r = 0; r < 4; r++) acc[mf][nf][r] = 0.f;

    const int sr = tid >> 1;
    const int skc = (tid & 1) * 2;

    auto stage = [&](int buf, int ch) {
        long long col = (long long)ch * 32;
        #pragma unroll
        for (int i = 0; i < 2; i++) {
            int kc = skc + i;
            uint32_t so = (uint32_t)(buf * BUFB + sr * 80 + kc * 16);
            long long gc = col + kc * 8;
            cp16(sb + so,             Ah + (long long)(m0 + sr) * Kpad + gc);
            cp16(sb + so + TILEB,     Al + (long long)(m0 + sr) * Kpad + gc);
            cp16(sb + so + 2 * TILEB, Wh + (long long)(n0 + sr) * Kpad + gc);
            cp16(sb + so + 3 * TILEB, Wl + (long long)(n0 + sr) * Kpad + gc);
        }
        asm volatile("cp.async.commit_group;");
    };

    const int nch = Kpad >> 5;
    stage(0, 0);

    for (int ch = 0; ch < nch; ch++) {
        if (ch + 1 < nch) {
            stage((ch + 1) & 1, ch + 1);
            asm volatile("cp.async.wait_group 1;");
        } else {
            asm volatile("cp.async.wait_group 0;");
        }
        __syncthreads();

        const char* base = smem + (ch & 1) * BUFB;
        #pragma unroll
        for (int ks = 0; ks < 2; ks++) {
            const int k0 = ks * 16;
            uint32_t ah[4][4], al[4][4], bh[4][2], bl[4][2];
            #pragma unroll
            for (int mf = 0; mf < 4; mf++) {
                int row = wm * 64 + mf * 16 + lr;
                const char* p0 = base + row * 80 + (k0 + q2) * 2;
                const char* p1 = base + (row + 8) * 80 + (k0 + q2) * 2;
                ah[mf][0] = *(const uint32_t*)(p0);
                ah[mf][1] = *(const uint32_t*)(p1);
                ah[mf][2] = *(const uint32_t*)(p0 + 16);
                ah[mf][3] = *(const uint32_t*)(p1 + 16);
                al[mf][0] = *(const uint32_t*)(p0 + TILEB);
                al[mf][1] = *(const uint32_t*)(p1 + TILEB);
                al[mf][2] = *(const uint32_t*)(p0 + 16 + TILEB);
                al[mf][3] = *(const uint32_t*)(p1 + 16 + TILEB);
            }
            #pragma unroll
            for (int nf = 0; nf < 4; nf++) {
                int col = wn * 32 + nf * 8 + lr;
                const char* p = base + 2 * TILEB + col * 80 + (k0 + q2) * 2;
                bh[nf][0] = *(const uint32_t*)(p);
                bh[nf][1] = *(const uint32_t*)(p + 16);
                bl[nf][0] = *(const uint32_t*)(p + TILEB);
                bl[nf][1] = *(const uint32_t*)(p + 16 + TILEB);
            }
            #pragma unroll
            for (int mf = 0; mf < 4; mf++)
                #pragma unroll
                for (int nf = 0; nf < 4; nf++)
                    mma_bf16(acc[mf][nf], ah[mf], bh[nf]);
            #pragma unroll
            for (int mf = 0; mf < 4; mf++)
                #pragma unroll
                for (int nf = 0; nf < 4; nf++)
                    mma_bf16(acc[mf][nf], ah[mf], bl[nf]);
            #pragma unroll
            for (int mf = 0; mf < 4; mf++)
                #pragma unroll
                for (int nf = 0; nf < 4; nf++)
                    mma_bf16(acc[mf][nf], al[mf], bh[nf]);
        }
        __syncthreads();
    }

    #pragma unroll
    for (int nf = 0; nf < 4; nf++) {
        int gn = n0 + wn * 32 + nf * 8 + q2;
        float bb0 = 0.f, bb1 = 0.f;
        if (b1) { bb0 += b1[gn]; bb1 += b1[gn + 1]; }
        if (b2) { bb0 += b2[gn]; bb1 += b2[gn + 1]; }
        #pragma unroll
        for (int mf = 0; mf < 4; mf++) {
            long long gm = m0 + wm * 64 + mf * 16 + lr;
            float2 v0 = make_float2(acc[mf][nf][0] + bb0, acc[mf][nf][1] + bb1);
            float2 v1 = make_float2(acc[mf][nf][2] + bb0, acc[mf][nf][3] + bb1);
            *(float2*)(C + gm * N + gn)       = v0;
            *(float2*)(C + (gm + 8) * N + gn) = v1;
        }
    }
}

// ================= small generic GEMM (attention FCs) ==============================
template<int ACT, int BM, int BN, int TM, int TN>
__global__ void gemm_small(const float* __restrict__ A, int lda,
                           const float* __restrict__ W, int ldw,
                           const float* __restrict__ b1,
                           float* __restrict__ C, int ldc,
                           int M, int N, int K)
{
    const int BK = 16;
    __shared__ float As[BK][BM + 2];
    __shared__ float Ws[BK][BN + 2];

    int m0 = blockIdx.y * BM;
    int n0 = blockIdx.x * BN;
    int tid = threadIdx.x;
    int tcol = tid % (BN / TN);
    int trow = tid / (BN / TN);
    int tm = trow * TM, tn = tcol * TN;

    float acc[TM][TN];
    #pragma unroll
    for (int i = 0; i < TM; i++)
        #pragma unroll
        for (int j = 0; j < TN; j++) acc[i][j] = 0.f;

    for (int kk = 0; kk < K; kk += BK) {
        for (int idx = tid; idx < BM * BK; idx += 256) {
            int m = idx / BK, k = idx % BK;
            int gm = m0 + m, gk = kk + k;
            As[k][m] = (gm < M && gk < K) ? A[(long long)gm * lda + gk] : 0.f;
        }
        for (int idx = tid; idx < BN * BK; idx += 256) {
            int n = idx / BK, k = idx % BK;
            int gn = n0 + n, gk = kk + k;
            Ws[k][n] = (gn < N && gk < K) ? W[(long long)gn * ldw + gk] : 0.f;
        }
        __syncthreads();
        #pragma unroll
        for (int k = 0; k < BK; k++) {
            float a[TM], w[TN];
            #pragma unroll
            for (int i = 0; i < TM; i++) a[i] = As[k][tm + i];
            #pragma unroll
            for (int j = 0; j < TN; j++) w[j] = Ws[k][tn + j];
            #pragma unroll
            for (int i = 0; i < TM; i++)
                #pragma unroll
                for (int j = 0; j < TN; j++)
                    acc[i][j] += a[i] * w[j];
        }
        __syncthreads();
    }

    #pragma unroll
    for (int i = 0; i < TM; i++) {
        int gm = m0 + tm + i;
        if (gm >= M) continue;
        #pragma unroll
        for (int j = 0; j < TN; j++) {
            int gn = n0 + tn + j;
            if (gn >= N) continue;
            float v = acc[i][j] + b1[gn];
            if (ACT == 1) v = tanhf(v);
            else if (ACT == 2) v = expf(v);
            C[(long long)gm * ldc + gn] = v;
        }
    }
}

// ---------------- persistent bidirectional LSTM recurrence (tensor-core) ----------
// 128 blocks = 2 dirs * 64 slices of 8 h-cols (= 32 gate cols). Per block:
// Whh slice pre-split bf16 hi/lo in SMEM (once). Each step: h (bf16 hi/lo,
// [b][k] in global, double-buffered) staged per-warp via cp.async into XOR-
// swizzled SMEM; gates = h @ W^T via mma.sync bf16 with hi/lo 3-term split.
// Warps: wm = m-half (32 batches), kq = k-quarter (128 k). N=32 full per warp.
// k-partials reduced via SMEM atomicAdd into gs; pointwise fp32.
__global__ void __launch_bounds__(256, 1)
lstm_persist(const float* __restrict__ xw,    // [2][T][B][G4]
             const float* __restrict__ Whh,   // [2][G4][H]
             const float* __restrict__ c0s,   // [2][B][H]
             __nv_bfloat16* __restrict__ hbf, // [2][2][2][B][H]
             float* __restrict__ hlast,       // [2][B][H]
             float* __restrict__ y,           // [T][B][2H] or null
             unsigned* __restrict__ bar)
{
    extern __shared__ char smem[];
    char*  wsh = smem;                         // 32 x 1024B  (W hi, swizzled)
    char*  wsl = smem + 32768;                 // W lo
    char*  hh  = smem + 65536;                 // 64 x 1024B  (h hi, swizzled)
    char*  hl  = smem + 131072;                // h lo
    float* xt  = (float*)(smem + 196608);      // [64][32]
    float* gs  = (float*)(smem + 204800);      // [64][33]
    float* cs  = (float*)(smem + 213248);      // [512]

    const int tid  = threadIdx.x;
    const int lane = tid & 31, w = tid >> 5;
    const int wm   = w & 1;                    // m-half
    const int kq   = w >> 1;                   // k-quarter
    const int r    = lane >> 2, q = lane & 3;
    const int d    = blockIdx.x >> 6;
    const int j0   = (blockIdx.x & 63) * 8;

    // ---- prologue: split Whh slice into SMEM (once per stage) ----
    const float* wp = Whh + (size_t)d * G4 * H_;
    for (int i = tid; i < 32 * 64; i += 256) {
        int cl = i >> 6, u = i & 63;
        int gate = cl >> 3, jj = cl & 7;
        const float* src = wp + (size_t)(gate * H_ + j0 + jj) * H_ + u * 8;
        uint32_t hi4[4], lo4[4];
        #pragma unroll
        for (int p = 0; p < 4; p++) {
            float a = src[2 * p], b = src[2 * p + 1];
            __nv_bfloat16 ha = __float2bfloat16(a), hb = __float2bfloat16(b);
            hi4[p] = pkbf2(a, b);
            lo4[p] = pkbf2(a - __bfloat162float(ha), b - __bfloat162float(hb));
        }
        int off = cl * 1024 + ((u ^ (cl & 7)) << 4);
        *(uint4*)(wsh + off) = make_uint4(hi4[0], hi4[1], hi4[2], hi4[3]);
        *(uint4*)(wsl + off) = make_uint4(lo4[0], lo4[1], lo4[2], lo4[3]);
    }
    for (int i = tid; i < 512; i += 256) {
        int b = i >> 3, jj = i & 7;
        cs[i] = c0s[(size_t)d * B_ * H_ + b * H_ + j0 + jj];
    }
    for (int i = tid; i < 64 * 33; i += 256) gs[i] = 0.f;
    __syncthreads();

    const uint32_t hhA = smem_u32(hh);
    const uint32_t hlA = smem_u32(hl);
    const uint32_t xtA = smem_u32(xt);

    float acc[2][4][4];
    #pragma unroll
    for (int mf = 0; mf < 2; mf++)
        #pragma unroll
        for (int nf = 0; nf < 4; nf++)
            #pragma unroll
            for (int x = 0; x < 4; x++) acc[mf][nf][x] = 0.f;

    for (int t = 0; t < T_; t++) {
        const int td = d ? (T_ - 1 - t) : t;
        const float* xp = xw + ((size_t)(d * T_ + td) * B_) * G4;

        // group 1: xw tile
        #pragma unroll
        for (int i = 0; i < 2; i++) {
            int idx = i * 256 + tid;
            int half = idx & 1, seg = idx >> 1;
            int b = seg >> 2, gate = seg & 3;
            cp16(xtA + idx * 16, xp + (size_t)b * G4 + gate * H_ + j0 + half * 4);
        }
        asm volatile("cp.async.commit_group;");

        // per-warp h staging of own k-quarter (hi+lo), two halves
        const __nv_bfloat16* hbr = hbf + (size_t)(t & 1) * 131072 + d * 65536;
        #pragma unroll 4
        for (int i = lane; i < 512; i += 32) {       // group 2: uu 0..7
            int b = i >> 3, uu = i & 7;
            int U = kq * 16 + uu;
            uint32_t dsto = (uint32_t)(b << 10) + (uint32_t)((U ^ (b & 7)) << 4);
            const __nv_bfloat16* s = hbr + b * 512 + U * 8;
            cp16(hhA + dsto, s);
            cp16(hlA + dsto, s + 32768);
        }
        asm volatile("cp.async.commit_group;");
        #pragma unroll 4
        for (int i = lane; i < 512; i += 32) {       // group 3: uu 8..15
            int b = i >> 3, uu = 8 + (i & 7);
            int U = kq * 16 + uu;
            uint32_t dsto = (uint32_t)(b << 10) + (uint32_t)((U ^ (b & 7)) << 4);
            const __nv_bfloat16* s = hbr + b * 512 + U * 8;
            cp16(hhA + dsto, s);
            cp16(hlA + dsto, s + 32768);
        }
        asm volatile("cp.async.commit_group;");

        // compute: two halves of 4 k-steps each
        #pragma unroll
        for (int hf = 0; hf < 2; hf++) {
            if (hf == 0) asm volatile("cp.async.wait_group 1;");
            else         asm volatile("cp.async.wait_group 0;");
            #pragma unroll
            for (int ks2 = 0; ks2 < 4; ks2++) {
                const int u0 = (kq << 4) + ((hf * 4 + ks2) << 1);
                const int usw0 = ((u0 ^ r) << 4) + q * 4;
                const int usw1 = (((u0 + 1) ^ r) << 4) + q * 4;

                uint32_t ah[2][4], al2[2][4], bh[4][2], bl2[4][2];
                #pragma unroll
                for (int mf = 0; mf < 2; mf++) {
                    int m0r = wm * 32 + mf * 16 + r;
                    const char* p0 = hh + (m0r << 10);
                    const char* p1 = hh + ((m0r + 8) << 10);
                    ah[mf][0] = *(const uint32_t*)(p0 + usw0);
                    ah[mf][1] = *(const uint32_t*)(p1 + usw0);
                    ah[mf][2] = *(const uint32_t*)(p0 + usw1);
                    ah[mf][3] = *(const uint32_t*)(p1 + usw1);
                    const char* q0 = hl + (m0r << 10);
                    const char* q1 = hl + ((m0r + 8) << 10);
                    al2[mf][0] = *(const uint32_t*)(q0 + usw0);
                    al2[mf][1] = *(const uint32_t*)(q1 + usw0);
                    al2[mf][2] = *(const uint32_t*)(q0 + usw1);
                    al2[mf][3] = *(const uint32_t*)(q1 + usw1);
                }
                #pragma unroll
                for (int nf = 0; nf < 4; nf++) {
                    int nr = nf * 8 + r;
                    const char* pb = wsh + (nr << 10);
                    const char* qb = wsl + (nr << 10);
                    bh[nf][0]  = *(const uint32_t*)(pb + usw0);
                    bh[nf][1]  = *(const uint32_t*)(pb + usw1);
                    bl2[nf][0] = *(const uint32_t*)(qb + usw0);
                    bl2[nf][1] = *(const uint32_t*)(qb + usw1);
                }
                #pragma unroll
                for (int mf = 0; mf < 2; mf++)
                    #pragma unroll
                    for (int nf = 0; nf < 4; nf++) {
                        mma_bf16(acc[mf][nf], ah[mf],  bh[nf]);
                        mma_bf16(acc[mf][nf], ah[mf],  bl2[nf]);
                        mma_bf16(acc[mf][nf], al2[mf], bh[nf]);
                    }
            }
        }

        // reduce k-partials into gs
        #pragma unroll
        for (int mf = 0; mf < 2; mf++) {
            int b = wm * 32 + mf * 16 + r;
            #pragma unroll
            for (int nf = 0; nf < 4; nf++) {
                int cl = nf * 8 + q * 2;
                atomicAdd(&gs[b * 33 + cl],           acc[mf][nf][0]);
                atomicAdd(&gs[b * 33 + cl + 1],       acc[mf][nf][1]);
                atomicAdd(&gs[(b + 8) * 33 + cl],     acc[mf][nf][2]);
                atomicAdd(&gs[(b + 8) * 33 + cl + 1], acc[mf][nf][3]);
                acc[mf][nf][0] = acc[mf][nf][1] = acc[mf][nf][2] = acc[mf][nf][3] = 0.f;
            }
        }
        __syncthreads();

        // pointwise c/h update; write split bf16 h to the other buffer
        __nv_bfloat16* hbw = hbf + (size_t)((t + 1) & 1) * 131072 + d * 65536;
        #pragma unroll
        for (int it = 0; it < 2; it++) {
            int o = it * 256 + tid;
            int b = o >> 3, jj = o & 7;
            float gi = gs[b * 33 + jj]      + xt[b * 32 + jj];
            float gf = gs[b * 33 + 8 + jj]  + xt[b * 32 + 8 + jj];
            float gg = gs[b * 33 + 16 + jj] + xt[b * 32 + 16 + jj];
            float go = gs[b * 33 + 24 + jj] + xt[b * 32 + 24 + jj];
            gs[b * 33 + jj] = 0.f;
            gs[b * 33 + 8 + jj] = 0.f;
            gs[b * 33 + 16 + jj] = 0.f;
            gs[b * 33 + 24 + jj] = 0.f;
            float cv = cs[o];
            float si = 1.f / (1.f + expf(-gi));
            float sf = 1.f / (1.f + expf(-gf));
            float so = 1.f / (1.f + expf(-go));
            float cn = sf * cv + si * tanhf(gg);
            float hn = so * tanhf(cn);
            cs[o] = cn;
            __nv_bfloat16 hhi = __float2bfloat16(hn);
            __nv_bfloat16 hlo = __float2bfloat16(hn - __bfloat162float(hhi));
            hbw[b * 512 + j0 + jj] = hhi;
            hbw[32768 + b * 512 + j0 + jj] = hlo;
            if (y) y[(size_t)(td * B_ + b) * H2 + d * H_ + j0 + jj] = hn;
            if (t == T_ - 1) hlast[(size_t)d * B_ * H_ + b * H_ + j0 + jj] = hn;
        }

        __threadfence();
        __syncthreads();
        if (t < T_ - 1) {
            if (tid == 0) {
                atomicAdd(&bar[d], 1u);
                unsigned tgt = 64u * (unsigned)(t + 1);
                unsigned v;
                do {
                    asm volatile("ld.acquire.gpu.u32 %0, [%1];" : "=r"(v) : "l"(bar + d));
                } while (v < tgt);
            }
            __syncthreads();
        }
    }
}

// ---------------- small kernels ----------------
__global__ void init_state(const float* __restrict__ h0s, __nv_bfloat16* __restrict__ hbf,
                           unsigned* __restrict__ bar)
{
    int i = blockIdx.x * blockDim.x + threadIdx.x;
    if (i < 2) bar[i] = 0;
    if (i < 2 * B_ * H_) {
        int dd = i >> 15, rem = i & 32767, b = rem >> 9, k = rem & 511;
        float v = h0s[((size_t)dd * B_ + b) * H_ + k];
        __nv_bfloat16 h = __float2bfloat16(v);
        __nv_bfloat16 l = __float2bfloat16(v - __bfloat162float(h));
        hbf[dd * 65536 + b * 512 + k] = h;
        hbf[dd * 65536 + 32768 + b * 512 + k] = l;
    }
}

__global__ void attn_alpha(const float* __restrict__ e, float* __restrict__ alphab)
{
    int b = blockIdx.x;
    __shared__ float a[2 * F_];
    __shared__ float red[128];
    __shared__ float redc[128];
    int tid = threadIdx.x;

    for (int i = tid; i < 2 * F_; i += 128) {
        int d = i / F_, j = i % F_;
        a[i] = e[(d * B_ + b) * F_ + j];
    }
    __syncthreads();

    float s = 0.f;
    for (int i = tid; i < 2 * F_; i += 128) s += a[i];
    red[tid] = s; __syncthreads();
    for (int off = 64; off; off >>= 1) { if (tid < off) red[tid] += red[tid + off]; __syncthreads(); }
    float denom = red[0];
    __syncthreads();

    for (int i = tid; i < 2 * F_; i += 128) a[i] /= denom;
    __syncthreads();

    float cnt = 0.f, sel = 0.f;
    for (int i = tid; i < 2 * F_; i += 128) {
        float v = a[i];
        if (v >= 0.1f) { cnt += 1.f; sel += v; }
    }
    red[tid] = sel; redc[tid] = cnt; __syncthreads();
    for (int off = 64; off; off >>= 1) {
        if (tid < off) { red[tid] += red[tid + off]; redc[tid] += redc[tid + off]; }
        __syncthreads();
    }
    float selmean = red[0] / fmaxf(redc[0], 1.f);
    __syncthreads();

    for (int i = tid; i < 2 * F_; i += 128)
        if (a[i] >= 0.1f) a[i] = selmean;
    __syncthreads();

    for (int j = tid; j < F_; j += 128)
        alphab[b * F_ + j] = 0.5f * (a[j] + a[F_ + j]);
}

__global__ void scale_x(const float* __restrict__ x, const float* __restrict__ ab,
                        float* __restrict__ xo, int n)
{
    int i = blockIdx.x * blockDim.x + threadIdx.x;
    if (i < n) {
        int f = i % F_;
        int b = (i / F_) % B_;
        xo[i] = x[i] * ab[b * F_ + f];
    }
}

// ---------------- host driver ----------------
extern "C" void kernel_launch(void* const* d_in, const int* in_sizes, int n_in,
                              void* d_out, int out_size)
{
    const float* x     = (const float*)d_in[0];
    const float* h0    = (const float*)d_in[1];
    const float* c0    = (const float*)d_in[2];
    const float* saWih = (const float*)d_in[3];
    const float* saWhh = (const float*)d_in[4];
    const float* sabih = (const float*)d_in[5];
    const float* sabhh = (const float*)d_in[6];
    const float* m0Wih = (const float*)d_in[7];
    const float* m0Whh = (const float*)d_in[8];
    const float* m0bih = (const float*)d_in[9];
    const float* m0bhh = (const float*)d_in[10];
    const float* mLWih = (const float*)d_in[11];
    const float* mLWhh = (const float*)d_in[12];
    const float* mLbih = (const float*)d_in[13];
    const float* mLbhh = (const float*)d_in[14];
    const float* sf1W  = (const float*)d_in[15];
    const float* sf1b  = (const float*)d_in[16];
    const float* sf2W  = (const float*)d_in[17];
    const float* sf2b  = (const float*)d_in[18];
    const float* fc1W  = (const float*)d_in[19];
    const float* fc1b  = (const float*)d_in[20];
    float* out = (float*)d_out;

    float *xw, *y, *hlast, *t1, *e, *ab, *xwx;
    unsigned* bar;
    __nv_bfloat16 *wh, *wl, *ah, *al, *hbf;
    cudaGetSymbolAddress((void**)&xw,    g_xw);
    cudaGetSymbolAddress((void**)&y,     g_y);
    cudaGetSymbolAddress((void**)&hbf,   g_hbf);
    cudaGetSymbolAddress((void**)&hlast, g_hlast);
    cudaGetSymbolAddress((void**)&t1,    g_t1);
    cudaGetSymbolAddress((void**)&e,     g_e);
    cudaGetSymbolAddress((void**)&ab,    g_ab);
    cudaGetSymbolAddress((void**)&xwx,   g_xwx);
    cudaGetSymbolAddress((void**)&bar,   g_bar);
    cudaGetSymbolAddress((void**)&wh,    g_wh);
    cudaGetSymbolAddress((void**)&wl,    g_wl);
    cudaGetSymbolAddress((void**)&ah,    g_ah);
    cudaGetSymbolAddress((void**)&al,    g_al);

    const int SMEM_LSTM = 215296;
    cudaFuncSetAttribute(lstm_persist, cudaFuncAttributeMaxDynamicSharedMemorySize, SMEM_LSTM);
    const int SMEM_MMA = 2 * BUFB;
    cudaFuncSetAttribute(gemm_mma, cudaFuncAttributeMaxDynamicSharedMemorySize, SMEM_MMA);

    const int M = T_ * B_;   // 8192

    auto proj = [&](long long woff, const float* bih, const float* bhh, int Kpad) {
        gemm_mma<<<dim3(G4 / 128, M / 128, 2), 256, SMEM_MMA>>>(
            ah, al, wh + woff, wl + woff, (long long)G4 * Kpad,
            bih, G4, bhh, G4, xw, (long long)M * G4, Kpad, G4);
    };
    auto recur = [&](const float* Whh, const float* h0s, const float* c0s, float* yout) {
        init_state<<<(2 * B_ * H_ + 255) / 256, 256>>>(h0s, hbf, bar);
        lstm_persist<<<128, 256, SMEM_LSTM>>>(xw, Whh, c0s, hbf, hlast, yout, bar);
    };

    // ---- stage 1: spatial-attention biLSTM ----
    conv_split<<<1024, 256>>>(saWih, 2 * G4, F_, 128, wh + OFF_SAW, wl + OFF_SAW);
    conv_split<<<1024, 256>>>(x, M, F_, 128, ah, al);
    proj(OFF_SAW, sabih, sabhh, 128);
    conv_split<<<1024, 256>>>(m0Wih, 2 * G4, F_, 128, wh + OFF_M0W, wl + OFF_M0W);
    recur(saWhh, h0, c0, nullptr);

    // ---- attention ----
    gemm_small<1, 32, 64, 2, 4><<<dim3(H_ / 64, (2 * B_ + 31) / 32), 256>>>(
        hlast, H_, sf1W, H_, sf1b, t1, H_, 2 * B_, H_, H_);
    gemm_small<2, 32, 64, 2, 4><<<dim3((F_ + 63) / 64, (2 * B_ + 31) / 32), 256>>>(
        t1, H_, sf2W, H_, sf2b, e, F_, 2 * B_, F_, H_);
    attn_alpha<<<B_, 128>>>(e, ab);
    scale_x<<<(T_ * B_ * F_ + 255) / 256, 256>>>(x, ab, xwx, T_ * B_ * F_);

    // ---- main layer 0 ----
    conv_split<<<1024, 256>>>(xwx, M, F_, 128, ah, al);
    proj(OFF_M0W, m0bih, m0bhh, 128);
    recur(m0Whh, h0, c0, y);

    // ---- main layers 1,2 ----
    conv_split<<<2048, 256>>>(mLWih, 2 * 2 * G4, H2, H2, wh + OFF_MLW, wl + OFF_MLW);
    conv_split<<<2048, 256>>>(y, M, H2, H2, ah, al);
    proj(OFF_MLW, mLbih, mLbhh, H2);
    recur(mLWhh, h0 + 2 * B_ * H_, c0 + 2 * B_ * H_, y);

    conv_split<<<2048, 256>>>(y, M, H2, H2, ah, al);
    gemm_mma<<<dim3(G4 / 128, M / 128, 2), 256, SMEM_MMA>>>(
        ah, al, wh + OFF_MLW + 2ll * G4 * H2, wl + OFF_MLW + 2ll * G4 * H2,
        (long long)G4 * H2,
        mLbih + 2 * G4, G4, mLbhh + 2 * G4, G4, xw, (long long)M * G4, H2, G4);
    recur(mLWhh + 2ll * G4 * H_, h0 + 4 * B_ * H_, c0 + 4 * B_ * H_, y);

    // ---- final FC ----
    conv_split<<<2048, 256>>>(fc1W, H_, H2, H2, wh + OFF_FCW, wl + OFF_FCW);
    conv_split<<<2048, 256>>>(y, M, H2, H2, ah, al);
    gemm_mma<<<dim3(H_ / 128, M / 128, 1), 256, SMEM_MMA>>>(
        ah, al, wh + OFF_FCW, wl + OFF_FCW, 0ll,
        fc1b, 0ll, nullptr, 0ll, out, 0ll, H2, H_);
}

// round 7
// speedup vs baseline: 2.7019x; 1.1699x over previous
#include <cuda_runtime.h>
#include <cuda_bf16.h>
#include <math.h>
#include <stdint.h>

#define T_  128
#define B_  64
#define F_  75
#define H_  512
#define G4  2048   // 4*H
#define H2  1024   // 2*H

// ---------------- static scratch ----------------
__device__ __align__(256) float g_xw   [2ll * T_ * B_ * G4];
__device__ __align__(256) __nv_bfloat16 g_hbf[2 * 2 * 2 * B_ * H_];  // [buf][d][hi/lo][b][k]
__device__ float g_hlast[2 * B_ * H_];
__device__ float g_t1   [2 * B_ * H_];
__device__ float g_e    [2 * B_ * F_];
__device__ float g_ab   [B_ * F_];
__device__ unsigned g_bar[8];

// bf16 split buffers (hi / lo)
#define WSZ 10485760ll
__device__ __align__(256) __nv_bfloat16 g_wh[WSZ];
__device__ __align__(256) __nv_bfloat16 g_wl[WSZ];
__device__ __align__(256) __nv_bfloat16 g_ah[8388608ll];
__device__ __align__(256) __nv_bfloat16 g_al[8388608ll];

#define OFF_SAW 0ll
#define OFF_M0W 524288ll
#define OFF_MLW 1048576ll
#define OFF_FCW 9437184ll

// ---------------- helpers ----------------
__device__ __forceinline__ void cp16(uint32_t dst, const void* src) {
    asm volatile("cp.async.cg.shared.global [%0], [%1], 16;" :: "r"(dst), "l"(src));
}
__device__ __forceinline__ uint32_t smem_u32(const void* p) {
    return (uint32_t)__cvta_generic_to_shared(p);
}
__device__ __forceinline__ void mma_bf16(float* d, const uint32_t* a, const uint32_t* b) {
    asm volatile(
        "mma.sync.aligned.m16n8k16.row.col.f32.bf16.bf16.f32 "
        "{%0,%1,%2,%3}, {%4,%5,%6,%7}, {%8,%9}, {%0,%1,%2,%3};"
        : "+f"(d[0]), "+f"(d[1]), "+f"(d[2]), "+f"(d[3])
        : "r"(a[0]), "r"(a[1]), "r"(a[2]), "r"(a[3]), "r"(b[0]), "r"(b[1]));
}
__device__ __forceinline__ uint32_t pkbf2(float a, float b) {
    __nv_bfloat16 ha = __float2bfloat16(a), hb = __float2bfloat16(b);
    uint16_t ua = *(uint16_t*)&ha, ub = *(uint16_t*)&hb;
    return (uint32_t)ua | ((uint32_t)ub << 16);
}

// ---------------- fp32 -> bf16 hi/lo split conversion ----------------
__global__ void conv_split(const float* __restrict__ src, int rows, int K, int Kpad,
                           __nv_bfloat16* __restrict__ hi, __nv_bfloat16* __restrict__ lo)
{
    long long n = (long long)rows * Kpad;
    for (long long i = blockIdx.x * (long long)blockDim.x + threadIdx.x; i < n;
         i += (long long)gridDim.x * blockDim.x) {
        int kc = (int)(i % Kpad);
        long long r = i / Kpad;
        float v = (kc < K) ? src[r * K + kc] : 0.f;
        __nv_bfloat16 h = __float2bfloat16(v);
        hi[i] = h;
        lo[i] = __float2bfloat16(v - __bfloat162float(h));
    }
}

// ================= bf16 split tensor-core GEMM (mma.sync / HMMA) ==================
#define TILEB 10240
#define BUFB  40960

__global__ void __launch_bounds__(256, 1)
gemm_mma(const __nv_bfloat16* __restrict__ Ah, const __nv_bfloat16* __restrict__ Al,
         const __nv_bfloat16* __restrict__ Wh, const __nv_bfloat16* __restrict__ Wl,
         long long sW,
         const float* __restrict__ b1, long long sB1,
         const float* __restrict__ b2, long long sB2,
         float* __restrict__ C, long long sC,
         int Kpad, int N)
{
    extern __shared__ char smem[];
    const uint32_t sb = smem_u32(smem);

    const int z = blockIdx.z;
    Wh += (long long)z * sW;
    Wl += (long long)z * sW;
    C  += (long long)z * sC;
    if (b1) b1 += (long long)z * sB1;
    if (b2) b2 += (long long)z * sB2;

    const int tid  = threadIdx.x;
    const int lane = tid & 31;
    const int warp = tid >> 5;
    const int wm   = warp >> 2;
    const int wn   = warp & 3;
    const int m0   = blockIdx.y * 128;
    const int n0   = blockIdx.x * 128;
    const int q2   = (lane & 3) * 2;
    const int lr   = lane >> 2;

    float acc[4][4][4];
    #pragma unroll
    for (int mf = 0; mf < 4; mf++)
        #pragma unroll
        for (int nf = 0; nf < 4; nf++)
            #pragma unroll
            for (int r = 0; r < 4; r++) acc[mf][nf][r] = 0.f;

    const int sr = tid >> 1;
    const int skc = (tid & 1) * 2;

    auto stage = [&](int buf, int ch) {
        long long col = (long long)ch * 32;
        #pragma unroll
        for (int i = 0; i < 2; i++) {
            int kc = skc + i;
            uint32_t so = (uint32_t)(buf * BUFB + sr * 80 + kc * 16);
            long long gc = col + kc * 8;
            cp16(sb + so,             Ah + (long long)(m0 + sr) * Kpad + gc);
            cp16(sb + so + TILEB,     Al + (long long)(m0 + sr) * Kpad + gc);
            cp16(sb + so + 2 * TILEB, Wh + (long long)(n0 + sr) * Kpad + gc);
            cp16(sb + so + 3 * TILEB, Wl + (long long)(n0 + sr) * Kpad + gc);
        }
        asm volatile("cp.async.commit_group;");
    };

    const int nch = Kpad >> 5;
    stage(0, 0);

    for (int ch = 0; ch < nch; ch++) {
        if (ch + 1 < nch) {
            stage((ch + 1) & 1, ch + 1);
            asm volatile("cp.async.wait_group 1;");
        } else {
            asm volatile("cp.async.wait_group 0;");
        }
        __syncthreads();

        const char* base = smem + (ch & 1) * BUFB;
        #pragma unroll
        for (int ks = 0; ks < 2; ks++) {
            const int k0 = ks * 16;
            uint32_t ah[4][4], al[4][4], bh[4][2], bl[4][2];
            #pragma unroll
            for (int mf = 0; mf < 4; mf++) {
                int row = wm * 64 + mf * 16 + lr;
                const char* p0 = base + row * 80 + (k0 + q2) * 2;
                const char* p1 = base + (row + 8) * 80 + (k0 + q2) * 2;
                ah[mf][0] = *(const uint32_t*)(p0);
                ah[mf][1] = *(const uint32_t*)(p1);
                ah[mf][2] = *(const uint32_t*)(p0 + 16);
                ah[mf][3] = *(const uint32_t*)(p1 + 16);
                al[mf][0] = *(const uint32_t*)(p0 + TILEB);
                al[mf][1] = *(const uint32_t*)(p1 + TILEB);
                al[mf][2] = *(const uint32_t*)(p0 + 16 + TILEB);
                al[mf][3] = *(const uint32_t*)(p1 + 16 + TILEB);
            }
            #pragma unroll
            for (int nf = 0; nf < 4; nf++) {
                int col = wn * 32 + nf * 8 + lr;
                const char* p = base + 2 * TILEB + col * 80 + (k0 + q2) * 2;
                bh[nf][0] = *(const uint32_t*)(p);
                bh[nf][1] = *(const uint32_t*)(p + 16);
                bl[nf][0] = *(const uint32_t*)(p + TILEB);
                bl[nf][1] = *(const uint32_t*)(p + 16 + TILEB);
            }
            #pragma unroll
            for (int mf = 0; mf < 4; mf++)
                #pragma unroll
                for (int nf = 0; nf < 4; nf++)
                    mma_bf16(acc[mf][nf], ah[mf], bh[nf]);
            #pragma unroll
            for (int mf = 0; mf < 4; mf++)
                #pragma unroll
                for (int nf = 0; nf < 4; nf++)
                    mma_bf16(acc[mf][nf], ah[mf], bl[nf]);
            #pragma unroll
            for (int mf = 0; mf < 4; mf++)
                #pragma unroll
                for (int nf = 0; nf < 4; nf++)
                    mma_bf16(acc[mf][nf], al[mf], bh[nf]);
        }
        __syncthreads();
    }

    #pragma unroll
    for (int nf = 0; nf < 4; nf++) {
        int gn = n0 + wn * 32 + nf * 8 + q2;
        float bb0 = 0.f, bb1 = 0.f;
        if (b1) { bb0 += b1[gn]; bb1 += b1[gn + 1]; }
        if (b2) { bb0 += b2[gn]; bb1 += b2[gn + 1]; }
        #pragma unroll
        for (int mf = 0; mf < 4; mf++) {
            long long gm = m0 + wm * 64 + mf * 16 + lr;
            float2 v0 = make_float2(acc[mf][nf][0] + bb0, acc[mf][nf][1] + bb1);
            float2 v1 = make_float2(acc[mf][nf][2] + bb0, acc[mf][nf][3] + bb1);
            *(float2*)(C + gm * N + gn)       = v0;
            *(float2*)(C + (gm + 8) * N + gn) = v1;
        }
    }
}

// ================= small generic GEMM (attention FCs) ==============================
template<int ACT, int BM, int BN, int TM, int TN>
__global__ void gemm_small(const float* __restrict__ A, int lda,
                           const float* __restrict__ W, int ldw,
                           const float* __restrict__ b1,
                           float* __restrict__ C, int ldc,
                           int M, int N, int K)
{
    const int BK = 16;
    __shared__ float As[BK][BM + 2];
    __shared__ float Ws[BK][BN + 2];

    int m0 = blockIdx.y * BM;
    int n0 = blockIdx.x * BN;
    int tid = threadIdx.x;
    int tcol = tid % (BN / TN);
    int trow = tid / (BN / TN);
    int tm = trow * TM, tn = tcol * TN;

    float acc[TM][TN];
    #pragma unroll
    for (int i = 0; i < TM; i++)
        #pragma unroll
        for (int j = 0; j < TN; j++) acc[i][j] = 0.f;

    for (int kk = 0; kk < K; kk += BK) {
        for (int idx = tid; idx < BM * BK; idx += 256) {
            int m = idx / BK, k = idx % BK;
            int gm = m0 + m, gk = kk + k;
            As[k][m] = (gm < M && gk < K) ? A[(long long)gm * lda + gk] : 0.f;
        }
        for (int idx = tid; idx < BN * BK; idx += 256) {
            int n = idx / BK, k = idx % BK;
            int gn = n0 + n, gk = kk + k;
            Ws[k][n] = (gn < N && gk < K) ? W[(long long)gn * ldw + gk] : 0.f;
        }
        __syncthreads();
        #pragma unroll
        for (int k = 0; k < BK; k++) {
            float a[TM], wv[TN];
            #pragma unroll
            for (int i = 0; i < TM; i++) a[i] = As[k][tm + i];
            #pragma unroll
            for (int j = 0; j < TN; j++) wv[j] = Ws[k][tn + j];
            #pragma unroll
            for (int i = 0; i < TM; i++)
                #pragma unroll
                for (int j = 0; j < TN; j++)
                    acc[i][j] += a[i] * wv[j];
        }
        __syncthreads();
    }

    #pragma unroll
    for (int i = 0; i < TM; i++) {
        int gm = m0 + tm + i;
        if (gm >= M) continue;
        #pragma unroll
        for (int j = 0; j < TN; j++) {
            int gn = n0 + tn + j;
            if (gn >= N) continue;
            float v = acc[i][j] + b1[gn];
            if (ACT == 1) v = tanhf(v);
            else if (ACT == 2) v = expf(v);
            C[(long long)gm * ldc + gn] = v;
        }
    }
}

// ---------------- persistent bidirectional LSTM recurrence (tensor-core v2) -------
// 128 blocks = 2 dirs * 64 slices of 8 h-cols. Unique per-warp h staging
// (no duplication), pair-wise named barriers, atomic-free k-partial reduction,
// xw gate values + c state in registers, release/acquire global step barrier.
__global__ void __launch_bounds__(256, 1)
lstm_persist(const float* __restrict__ xw,    // [2][T][B][G4]
             const float* __restrict__ Whh,   // [2][G4][H]
             const float* __restrict__ h0s,   // [2][B][H]
             const float* __restrict__ c0s,   // [2][B][H]
             __nv_bfloat16* __restrict__ hbf, // [2][2][2][B][H]
             float* __restrict__ hlast,       // [2][B][H]
             __nv_bfloat16* __restrict__ yh,  // [T*B][2H] split hi or null
             __nv_bfloat16* __restrict__ yl,  // split lo or null
             unsigned* __restrict__ bar)      // 2 counters (per dir)
{
    extern __shared__ char smem[];
    char*  wsh = smem;                         // 32KB W hi (swizzled)
    char*  wsl = smem + 32768;                 // 32KB W lo
    char*  hh  = smem + 65536;                 // 64KB h hi
    char*  hl  = smem + 131072;                // 64KB h lo
    float* gs  = (float*)(smem + 196608);      // [4][64][33] partials

    const int tid  = threadIdx.x;
    const int lane = tid & 31, w = tid >> 5;
    const int wm   = w & 1;                    // m-half
    const int kq   = w >> 1;                   // k-quarter
    const int r    = lane >> 2, q = lane & 3;
    const int d    = blockIdx.x >> 6;
    const int j0   = (blockIdx.x & 63) * 8;

    // ---- prologue: split Whh slice into SMEM; init h0/c0 ----
    const float* wp = Whh + (size_t)d * G4 * H_;
    for (int i = tid; i < 32 * 64; i += 256) {
        int cl = i >> 6, u = i & 63;
        int gate = cl >> 3, jj = cl & 7;
        const float* src = wp + (size_t)(gate * H_ + j0 + jj) * H_ + u * 8;
        uint32_t hi4[4], lo4[4];
        #pragma unroll
        for (int p = 0; p < 4; p++) {
            float a = src[2 * p], b = src[2 * p + 1];
            __nv_bfloat16 ha = __float2bfloat16(a), hb = __float2bfloat16(b);
            hi4[p] = pkbf2(a, b);
            lo4[p] = pkbf2(a - __bfloat162float(ha), b - __bfloat162float(hb));
        }
        int off = cl * 1024 + ((u ^ (cl & 7)) << 4);
        *(uint4*)(wsh + off) = make_uint4(hi4[0], hi4[1], hi4[2], hi4[3]);
        *(uint4*)(wsl + off) = make_uint4(lo4[0], lo4[1], lo4[2], lo4[3]);
    }
    __nv_bfloat16* hb0 = hbf + d * 65536;
    for (int i = tid; i < 512; i += 256) {
        int b = i >> 3, jj = i & 7;
        float v = h0s[(size_t)d * B_ * H_ + b * H_ + j0 + jj];
        __nv_bfloat16 hi = __float2bfloat16(v);
        hb0[b * 512 + j0 + jj]         = hi;
        hb0[32768 + b * 512 + j0 + jj] = __float2bfloat16(v - __bfloat162float(hi));
    }
    float creg[2];
    #pragma unroll
    for (int it = 0; it < 2; it++) {
        int o = it * 256 + tid, b = o >> 3, jj = o & 7;
        creg[it] = c0s[(size_t)d * B_ * H_ + b * H_ + j0 + jj];
    }
    __syncthreads();
    if (tid == 0) {
        asm volatile("red.release.gpu.global.add.u32 [%0], 1;" :: "l"(bar + d) : "memory");
        unsigned v;
        do { asm volatile("ld.acquire.gpu.u32 %0, [%1];" : "=r"(v) : "l"(bar + d)); }
        while (v < 64u);
    }
    __syncthreads();

    const uint32_t hhA = smem_u32(hh);
    const uint32_t hlA = smem_u32(hl);

    float acc[2][4][4];
    #pragma unroll
    for (int mf = 0; mf < 2; mf++)
        #pragma unroll
        for (int nf = 0; nf < 4; nf++)
            #pragma unroll
            for (int x = 0; x < 4; x++) acc[mf][nf][x] = 0.f;

    for (int t = 0; t < T_; t++) {
        const int td = d ? (T_ - 1 - t) : t;
        const float* xp = xw + ((size_t)(d * T_ + td) * B_) * G4;

        // xw gate values -> registers (latency hidden under staging + mma)
        float xv[2][4];
        #pragma unroll
        for (int it = 0; it < 2; it++) {
            int o = it * 256 + tid, b = o >> 3, jj = o & 7;
            #pragma unroll
            for (int g = 0; g < 4; g++)
                xv[it][g] = xp[(size_t)b * G4 + g * H_ + j0 + jj];
        }

        // unique per-warp h staging: warp stages 8 U chunks in 2 subs
        const __nv_bfloat16* hbr = hbf + (size_t)(t & 1) * 131072 + d * 65536;
        #pragma unroll
        for (int sub = 0; sub < 2; sub++) {
            #pragma unroll
            for (int i2 = 0; i2 < 8; i2++) {
                int i = i2 * 32 + lane;
                int b = i >> 2, uo = i & 3;
                int U = kq * 16 + sub * 8 + wm * 4 + uo;
                uint32_t dst = (uint32_t)(b << 10) + (uint32_t)((U ^ (b & 7)) << 4);
                const __nv_bfloat16* s = hbr + b * 512 + U * 8;
                cp16(hhA + dst, s);
                cp16(hlA + dst, s + 32768);
            }
            asm volatile("cp.async.commit_group;");
        }

        #pragma unroll
        for (int hf = 0; hf < 2; hf++) {
            if (hf == 0) asm volatile("cp.async.wait_group 1;");
            else         asm volatile("cp.async.wait_group 0;");
            asm volatile("bar.sync %0, 64;" :: "r"(1 + kq) : "memory");

            #pragma unroll
            for (int ks2 = 0; ks2 < 4; ks2++) {
                const int u0 = (kq << 4) + ((hf * 4 + ks2) << 1);
                const int usw0 = ((u0 ^ r) << 4) + q * 4;
                const int usw1 = (((u0 + 1) ^ r) << 4) + q * 4;

                uint32_t ah[2][4], al2[2][4], bh[4][2], bl2[4][2];
                #pragma unroll
                for (int mf = 0; mf < 2; mf++) {
                    int m0r = wm * 32 + mf * 16 + r;
                    const char* p0 = hh + (m0r << 10);
                    const char* p1 = hh + ((m0r + 8) << 10);
                    ah[mf][0] = *(const uint32_t*)(p0 + usw0);
                    ah[mf][1] = *(const uint32_t*)(p1 + usw0);
                    ah[mf][2] = *(const uint32_t*)(p0 + usw1);
                    ah[mf][3] = *(const uint32_t*)(p1 + usw1);
                    const char* q0 = hl + (m0r << 10);
                    const char* q1 = hl + ((m0r + 8) << 10);
                    al2[mf][0] = *(const uint32_t*)(q0 + usw0);
                    al2[mf][1] = *(const uint32_t*)(q1 + usw0);
                    al2[mf][2] = *(const uint32_t*)(q0 + usw1);
                    al2[mf][3] = *(const uint32_t*)(q1 + usw1);
                }
                #pragma unroll
                for (int nf = 0; nf < 4; nf++) {
                    int nr = nf * 8 + r;
                    const char* pb = wsh + (nr << 10);
                    const char* qb = wsl + (nr << 10);
                    bh[nf][0]  = *(const uint32_t*)(pb + usw0);
                    bh[nf][1]  = *(const uint32_t*)(pb + usw1);
                    bl2[nf][0] = *(const uint32_t*)(qb + usw0);
                    bl2[nf][1] = *(const uint32_t*)(qb + usw1);
                }
                #pragma unroll
                for (int mf = 0; mf < 2; mf++)
                    #pragma unroll
                    for (int nf = 0; nf < 4; nf++) {
                        mma_bf16(acc[mf][nf], ah[mf],  bh[nf]);
                        mma_bf16(acc[mf][nf], ah[mf],  bl2[nf]);
                        mma_bf16(acc[mf][nf], al2[mf], bh[nf]);
                    }
            }
        }

        // atomic-free partial store (each warp owns gs[kq] rows wm*32..+32)
        #pragma unroll
        for (int mf = 0; mf < 2; mf++) {
            int b = wm * 32 + mf * 16 + r;
            #pragma unroll
            for (int nf = 0; nf < 4; nf++) {
                int cl = nf * 8 + q * 2;
                float* gp0 = gs + ((kq * 64 + b) * 33) + cl;
                float* gp1 = gs + ((kq * 64 + b + 8) * 33) + cl;
                gp0[0] = acc[mf][nf][0]; gp0[1] = acc[mf][nf][1];
                gp1[0] = acc[mf][nf][2]; gp1[1] = acc[mf][nf][3];
                acc[mf][nf][0] = acc[mf][nf][1] = acc[mf][nf][2] = acc[mf][nf][3] = 0.f;
            }
        }
        __syncthreads();

        // pointwise c/h update; write split bf16 h (and y split) directly
        __nv_bfloat16* hbw = hbf + (size_t)((t + 1) & 1) * 131072 + d * 65536;
        #pragma unroll
        for (int it = 0; it < 2; it++) {
            int o = it * 256 + tid;
            int b = o >> 3, jj = o & 7;
            float gi = xv[it][0], gf = xv[it][1], gg = xv[it][2], go = xv[it][3];
            #pragma unroll
            for (int kk2 = 0; kk2 < 4; kk2++) {
                const float* gp = gs + (kk2 * 64 + b) * 33;
                gi += gp[jj]; gf += gp[8 + jj]; gg += gp[16 + jj]; go += gp[24 + jj];
            }
            float cv = creg[it];
            float si = 1.f / (1.f + expf(-gi));
            float sf = 1.f / (1.f + expf(-gf));
            float so = 1.f / (1.f + expf(-go));
            float cn = sf * cv + si * tanhf(gg);
            float hn = so * tanhf(cn);
            creg[it] = cn;
            __nv_bfloat16 hhi = __float2bfloat16(hn);
            __nv_bfloat16 hlo = __float2bfloat16(hn - __bfloat162float(hhi));
            hbw[b * 512 + j0 + jj]         = hhi;
            hbw[32768 + b * 512 + j0 + jj] = hlo;
            if (yh) {
                size_t yi = (size_t)(td * B_ + b) * H2 + d * H_ + j0 + jj;
                yh[yi] = hhi;
                yl[yi] = hlo;
            }
            if (t == T_ - 1)
                hlast[(size_t)d * B_ * H_ + b * H_ + j0 + jj] = hn;
        }

        __syncthreads();
        if (t < T_ - 1) {
            if (tid == 0) {
                asm volatile("red.release.gpu.global.add.u32 [%0], 1;" :: "l"(bar + d) : "memory");
                unsigned tgt = 64u * (unsigned)(t + 2), v;
                do { asm volatile("ld.acquire.gpu.u32 %0, [%1];" : "=r"(v) : "l"(bar + d)); }
                while (v < tgt);
            }
            __syncthreads();
        }
    }
}

// ---------------- small kernels ----------------
__global__ void reset_bar(unsigned* __restrict__ bar)
{
    if (threadIdx.x < 8) bar[threadIdx.x] = 0;
}

__global__ void attn_alpha(const float* __restrict__ e, float* __restrict__ alphab)
{
    int b = blockIdx.x;
    __shared__ float a[2 * F_];
    __shared__ float red[128];
    __shared__ float redc[128];
    int tid = threadIdx.x;

    for (int i = tid; i < 2 * F_; i += 128) {
        int d = i / F_, j = i % F_;
        a[i] = e[(d * B_ + b) * F_ + j];
    }
    __syncthreads();

    float s = 0.f;
    for (int i = tid; i < 2 * F_; i += 128) s += a[i];
    red[tid] = s; __syncthreads();
    for (int off = 64; off; off >>= 1) { if (tid < off) red[tid] += red[tid + off]; __syncthreads(); }
    float denom = red[0];
    __syncthreads();

    for (int i = tid; i < 2 * F_; i += 128) a[i] /= denom;
    __syncthreads();

    float cnt = 0.f, sel = 0.f;
    for (int i = tid; i < 2 * F_; i += 128) {
        float v = a[i];
        if (v >= 0.1f) { cnt += 1.f; sel += v; }
    }
    red[tid] = sel; redc[tid] = cnt; __syncthreads();
    for (int off = 64; off; off >>= 1) {
        if (tid < off) { red[tid] += red[tid + off]; redc[tid] += redc[tid + off]; }
        __syncthreads();
    }
    float selmean = red[0] / fmaxf(redc[0], 1.f);
    __syncthreads();

    for (int i = tid; i < 2 * F_; i += 128)
        if (a[i] >= 0.1f) a[i] = selmean;
    __syncthreads();

    for (int j = tid; j < F_; j += 128)
        alphab[b * F_ + j] = 0.5f * (a[j] + a[F_ + j]);
}

// fused: xw = x * alpha_b, padded to 128 cols, written as bf16 hi/lo split
__global__ void scale_split(const float* __restrict__ x, const float* __restrict__ ab,
                            __nv_bfloat16* __restrict__ hi, __nv_bfloat16* __restrict__ lo)
{
    int i = blockIdx.x * blockDim.x + threadIdx.x;   // over M*128
    if (i < T_ * B_ * 128) {
        int f = i & 127;
        int m = i >> 7;
        int b = m & (B_ - 1);
        float v = 0.f;
        if (f < F_) v = x[m * F_ + f] * ab[b * F_ + f];
        __nv_bfloat16 h = __float2bfloat16(v);
        hi[i] = h;
        lo[i] = __float2bfloat16(v - __bfloat162float(h));
    }
}

// ---------------- host driver ----------------
extern "C" void kernel_launch(void* const* d_in, const int* in_sizes, int n_in,
                              void* d_out, int out_size)
{
    const float* x     = (const float*)d_in[0];
    const float* h0    = (const float*)d_in[1];
    const float* c0    = (const float*)d_in[2];
    const float* saWih = (const float*)d_in[3];
    const float* saWhh = (const float*)d_in[4];
    const float* sabih = (const float*)d_in[5];
    const float* sabhh = (const float*)d_in[6];
    const float* m0Wih = (const float*)d_in[7];
    const float* m0Whh = (const float*)d_in[8];
    const float* m0bih = (const float*)d_in[9];
    const float* m0bhh = (const float*)d_in[10];
    const float* mLWih = (const float*)d_in[11];
    const float* mLWhh = (const float*)d_in[12];
    const float* mLbih = (const float*)d_in[13];
    const float* mLbhh = (const float*)d_in[14];
    const float* sf1W  = (const float*)d_in[15];
    const float* sf1b  = (const float*)d_in[16];
    const float* sf2W  = (const float*)d_in[17];
    const float* sf2b  = (const float*)d_in[18];
    const float* fc1W  = (const float*)d_in[19];
    const float* fc1b  = (const float*)d_in[20];
    float* out = (float*)d_out;

    float *xw, *hlast, *t1, *e, *ab;
    unsigned* bar;
    __nv_bfloat16 *wh, *wl, *ah, *al, *hbf;
    cudaGetSymbolAddress((void**)&xw,    g_xw);
    cudaGetSymbolAddress((void**)&hbf,   g_hbf);
    cudaGetSymbolAddress((void**)&hlast, g_hlast);
    cudaGetSymbolAddress((void**)&t1,    g_t1);
    cudaGetSymbolAddress((void**)&e,     g_e);
    cudaGetSymbolAddress((void**)&ab,    g_ab);
    cudaGetSymbolAddress((void**)&bar,   g_bar);
    cudaGetSymbolAddress((void**)&wh,    g_wh);
    cudaGetSymbolAddress((void**)&wl,    g_wl);
    cudaGetSymbolAddress((void**)&ah,    g_ah);
    cudaGetSymbolAddress((void**)&al,    g_al);

    const int SMEM_LSTM = 230400;
    cudaFuncSetAttribute(lstm_persist, cudaFuncAttributeMaxDynamicSharedMemorySize, SMEM_LSTM);
    const int SMEM_MMA = 2 * BUFB;
    cudaFuncSetAttribute(gemm_mma, cudaFuncAttributeMaxDynamicSharedMemorySize, SMEM_MMA);

    const int M = T_ * B_;   // 8192

    auto proj = [&](long long woff, const float* bih, const float* bhh, int Kpad) {
        gemm_mma<<<dim3(G4 / 128, M / 128, 2), 256, SMEM_MMA>>>(
            ah, al, wh + woff, wl + woff, (long long)G4 * Kpad,
            bih, G4, bhh, G4, xw, (long long)M * G4, Kpad, G4);
    };
    auto recur = [&](const float* Whh, const float* h0s, const float* c0s,
                     __nv_bfloat16* yh, __nv_bfloat16* yl, int stage) {
        lstm_persist<<<128, 256, SMEM_LSTM>>>(xw, Whh, h0s, c0s, hbf, hlast,
                                              yh, yl, bar + 2 * stage);
    };

    reset_bar<<<1, 32>>>(bar);

    // ---- stage 0: spatial-attention biLSTM ----
    conv_split<<<1024, 256>>>(saWih, 2 * G4, F_, 128, wh + OFF_SAW, wl + OFF_SAW);
    conv_split<<<1024, 256>>>(x, M, F_, 128, ah, al);
    proj(OFF_SAW, sabih, sabhh, 128);
    conv_split<<<1024, 256>>>(m0Wih, 2 * G4, F_, 128, wh + OFF_M0W, wl + OFF_M0W);
    recur(saWhh, h0, c0, nullptr, nullptr, 0);

    // ---- attention ----
    gemm_small<1, 32, 64, 2, 4><<<dim3(H_ / 64, (2 * B_ + 31) / 32), 256>>>(
        hlast, H_, sf1W, H_, sf1b, t1, H_, 2 * B_, H_, H_);
    gemm_small<2, 32, 64, 2, 4><<<dim3((F_ + 63) / 64, (2 * B_ + 31) / 32), 256>>>(
        t1, H_, sf2W, H_, sf2b, e, F_, 2 * B_, F_, H_);
    attn_alpha<<<B_, 128>>>(e, ab);
    scale_split<<<(M * 128 + 255) / 256, 256>>>(x, ab, ah, al);

    // ---- main layer 0 ----
    proj(OFF_M0W, m0bih, m0bhh, 128);
    conv_split<<<2048, 256>>>(mLWih, 2 * 2 * G4, H2, H2, wh + OFF_MLW, wl + OFF_MLW);
    recur(m0Whh, h0, c0, ah, al, 1);

    // ---- main layers 1,2 ----
    proj(OFF_MLW, mLbih, mLbhh, H2);
    recur(mLWhh, h0 + 2 * B_ * H_, c0 + 2 * B_ * H_, ah, al, 2);

    gemm_mma<<<dim3(G4 / 128, M / 128, 2), 256, SMEM_MMA>>>(
        ah, al, wh + OFF_MLW + 2ll * G4 * H2, wl + OFF_MLW + 2ll * G4 * H2,
        (long long)G4 * H2,
        mLbih + 2 * G4, G4, mLbhh + 2 * G4, G4, xw, (long long)M * G4, H2, G4);
    conv_split<<<1024, 256>>>(fc1W, H_, H2, H2, wh + OFF_FCW, wl + OFF_FCW);
    recur(mLWhh + 2ll * G4 * H_, h0 + 4 * B_ * H_, c0 + 4 * B_ * H_, ah, al, 3);

    // ---- final FC ----
    gemm_mma<<<dim3(H_ / 128, M / 128, 1), 256, SMEM_MMA>>>(
        ah, al, wh + OFF_FCW, wl + OFF_FCW, 0ll,
        fc1b, 0ll, nullptr, 0ll, out, 0ll, H2, H_);
}

// round 8
// speedup vs baseline: 2.7500x; 1.0178x over previous
#include <cuda_runtime.h>
#include <cuda_bf16.h>
#include <math.h>
#include <stdint.h>

#define T_  128
#define B_  64
#define F_  75
#define H_  512
#define G4  2048   // 4*H
#define H2  1024   // 2*H

// ---------------- static scratch ----------------
__device__ __align__(256) float g_xw   [2ll * T_ * B_ * G4];
// h carried between steps, stored in the XOR-swizzled SMEM layout:
// [buf][d][hi(32768 elems) | lo(32768 elems)], elem addr = (b<<9)+((U^(b&7))<<3)+(k&7)
__device__ __align__(256) __nv_bfloat16 g_hbf[2 * 2 * 2 * B_ * H_];
__device__ float g_hlast[2 * B_ * H_];
__device__ float g_t1   [2 * B_ * H_];
__device__ float g_e    [2 * B_ * F_];
__device__ float g_ab   [B_ * F_];
__device__ unsigned g_bar[8];

// bf16 split buffers (hi / lo)
#define WSZ 10485760ll
__device__ __align__(256) __nv_bfloat16 g_wh[WSZ];
__device__ __align__(256) __nv_bfloat16 g_wl[WSZ];
__device__ __align__(256) __nv_bfloat16 g_ah[8388608ll];
__device__ __align__(256) __nv_bfloat16 g_al[8388608ll];

#define OFF_SAW 0ll
#define OFF_M0W 524288ll
#define OFF_MLW 1048576ll
#define OFF_FCW 9437184ll

// ---------------- helpers ----------------
__device__ __forceinline__ void cp16(uint32_t dst, const void* src) {
    asm volatile("cp.async.cg.shared.global [%0], [%1], 16;" :: "r"(dst), "l"(src));
}
__device__ __forceinline__ uint32_t smem_u32(const void* p) {
    return (uint32_t)__cvta_generic_to_shared(p);
}
__device__ __forceinline__ void mma_bf16(float* d, const uint32_t* a, const uint32_t* b) {
    asm volatile(
        "mma.sync.aligned.m16n8k16.row.col.f32.bf16.bf16.f32 "
        "{%0,%1,%2,%3}, {%4,%5,%6,%7}, {%8,%9}, {%0,%1,%2,%3};"
        : "+f"(d[0]), "+f"(d[1]), "+f"(d[2]), "+f"(d[3])
        : "r"(a[0]), "r"(a[1]), "r"(a[2]), "r"(a[3]), "r"(b[0]), "r"(b[1]));
}
__device__ __forceinline__ uint32_t pkbf2(float a, float b) {
    __nv_bfloat16 ha = __float2bfloat16(a), hb = __float2bfloat16(b);
    uint16_t ua = *(uint16_t*)&ha, ub = *(uint16_t*)&hb;
    return (uint32_t)ua | ((uint32_t)ub << 16);
}

// ---------------- fp32 -> bf16 hi/lo split conversion ----------------
__global__ void conv_split(const float* __restrict__ src, int rows, int K, int Kpad,
                           __nv_bfloat16* __restrict__ hi, __nv_bfloat16* __restrict__ lo)
{
    long long n = (long long)rows * Kpad;
    for (long long i = blockIdx.x * (long long)blockDim.x + threadIdx.x; i < n;
         i += (long long)gridDim.x * blockDim.x) {
        int kc = (int)(i % Kpad);
        long long r = i / Kpad;
        float v = (kc < K) ? src[r * K + kc] : 0.f;
        __nv_bfloat16 h = __float2bfloat16(v);
        hi[i] = h;
        lo[i] = __float2bfloat16(v - __bfloat162float(h));
    }
}

// ================= bf16 split tensor-core GEMM (mma.sync / HMMA) ==================
#define TILEB 10240
#define BUFB  40960

__global__ void __launch_bounds__(256, 1)
gemm_mma(const __nv_bfloat16* __restrict__ Ah, const __nv_bfloat16* __restrict__ Al,
         const __nv_bfloat16* __restrict__ Wh, const __nv_bfloat16* __restrict__ Wl,
         long long sW,
         const float* __restrict__ b1, long long sB1,
         const float* __restrict__ b2, long long sB2,
         float* __restrict__ C, long long sC,
         int Kpad, int N)
{
    extern __shared__ char smem[];
    const uint32_t sb = smem_u32(smem);

    const int z = blockIdx.z;
    Wh += (long long)z * sW;
    Wl += (long long)z * sW;
    C  += (long long)z * sC;
    if (b1) b1 += (long long)z * sB1;
    if (b2) b2 += (long long)z * sB2;

    const int tid  = threadIdx.x;
    const int lane = tid & 31;
    const int warp = tid >> 5;
    const int wm   = warp >> 2;
    const int wn   = warp & 3;
    const int m0   = blockIdx.y * 128;
    const int n0   = blockIdx.x * 128;
    const int q2   = (lane & 3) * 2;
    const int lr   = lane >> 2;

    float acc[4][4][4];
    #pragma unroll
    for (int mf = 0; mf < 4; mf++)
        #pragma unroll
        for (int nf = 0; nf < 4; nf++)
            #pragma unroll
            for (int r = 0; r < 4; r++) acc[mf][nf][r] = 0.f;

    const int sr = tid >> 1;
    const int skc = (tid & 1) * 2;

    auto stage = [&](int buf, int ch) {
        long long col = (long long)ch * 32;
        #pragma unroll
        for (int i = 0; i < 2; i++) {
            int kc = skc + i;
            uint32_t so = (uint32_t)(buf * BUFB + sr * 80 + kc * 16);
            long long gc = col + kc * 8;
            cp16(sb + so,             Ah + (long long)(m0 + sr) * Kpad + gc);
            cp16(sb + so + TILEB,     Al + (long long)(m0 + sr) * Kpad + gc);
            cp16(sb + so + 2 * TILEB, Wh + (long long)(n0 + sr) * Kpad + gc);
            cp16(sb + so + 3 * TILEB, Wl + (long long)(n0 + sr) * Kpad + gc);
        }
        asm volatile("cp.async.commit_group;");
    };

    const int nch = Kpad >> 5;
    stage(0, 0);

    for (int ch = 0; ch < nch; ch++) {
        if (ch + 1 < nch) {
            stage((ch + 1) & 1, ch + 1);
            asm volatile("cp.async.wait_group 1;");
        } else {
            asm volatile("cp.async.wait_group 0;");
        }
        __syncthreads();

        const char* base = smem + (ch & 1) * BUFB;
        #pragma unroll
        for (int ks = 0; ks < 2; ks++) {
            const int k0 = ks * 16;
            uint32_t ah[4][4], al[4][4], bh[4][2], bl[4][2];
            #pragma unroll
            for (int mf = 0; mf < 4; mf++) {
                int row = wm * 64 + mf * 16 + lr;
                const char* p0 = base + row * 80 + (k0 + q2) * 2;
                const char* p1 = base + (row + 8) * 80 + (k0 + q2) * 2;
                ah[mf][0] = *(const uint32_t*)(p0);
                ah[mf][1] = *(const uint32_t*)(p1);
                ah[mf][2] = *(const uint32_t*)(p0 + 16);
                ah[mf][3] = *(const uint32_t*)(p1 + 16);
                al[mf][0] = *(const uint32_t*)(p0 + TILEB);
                al[mf][1] = *(const uint32_t*)(p1 + TILEB);
                al[mf][2] = *(const uint32_t*)(p0 + 16 + TILEB);
                al[mf][3] = *(const uint32_t*)(p1 + 16 + TILEB);
            }
            #pragma unroll
            for (int nf = 0; nf < 4; nf++) {
                int col = wn * 32 + nf * 8 + lr;
                const char* p = base + 2 * TILEB + col * 80 + (k0 + q2) * 2;
                bh[nf][0] = *(const uint32_t*)(p);
                bh[nf][1] = *(const uint32_t*)(p + 16);
                bl[nf][0] = *(const uint32_t*)(p + TILEB);
                bl[nf][1] = *(const uint32_t*)(p + 16 + TILEB);
            }
            #pragma unroll
            for (int mf = 0; mf < 4; mf++)
                #pragma unroll
                for (int nf = 0; nf < 4; nf++)
                    mma_bf16(acc[mf][nf], ah[mf], bh[nf]);
            #pragma unroll
            for (int mf = 0; mf < 4; mf++)
                #pragma unroll
                for (int nf = 0; nf < 4; nf++)
                    mma_bf16(acc[mf][nf], ah[mf], bl[nf]);
            #pragma unroll
            for (int mf = 0; mf < 4; mf++)
                #pragma unroll
                for (int nf = 0; nf < 4; nf++)
                    mma_bf16(acc[mf][nf], al[mf], bh[nf]);
        }
        __syncthreads();
    }

    #pragma unroll
    for (int nf = 0; nf < 4; nf++) {
        int gn = n0 + wn * 32 + nf * 8 + q2;
        float bb0 = 0.f, bb1 = 0.f;
        if (b1) { bb0 += b1[gn]; bb1 += b1[gn + 1]; }
        if (b2) { bb0 += b2[gn]; bb1 += b2[gn + 1]; }
        #pragma unroll
        for (int mf = 0; mf < 4; mf++) {
            long long gm = m0 + wm * 64 + mf * 16 + lr;
            float2 v0 = make_float2(acc[mf][nf][0] + bb0, acc[mf][nf][1] + bb1);
            float2 v1 = make_float2(acc[mf][nf][2] + bb0, acc[mf][nf][3] + bb1);
            *(float2*)(C + gm * N + gn)       = v0;
            *(float2*)(C + (gm + 8) * N + gn) = v1;
        }
    }
}

// ================= small generic GEMM (attention FCs) ==============================
template<int ACT, int BM, int BN, int TM, int TN>
__global__ void gemm_small(const float* __restrict__ A, int lda,
                           const float* __restrict__ W, int ldw,
                           const float* __restrict__ b1,
                           float* __restrict__ C, int ldc,
                           int M, int N, int K)
{
    const int BK = 16;
    __shared__ float As[BK][BM + 2];
    __shared__ float Ws[BK][BN + 2];

    int m0 = blockIdx.y * BM;
    int n0 = blockIdx.x * BN;
    int tid = threadIdx.x;
    int tcol = tid % (BN / TN);
    int trow = tid / (BN / TN);
    int tm = trow * TM, tn = tcol * TN;

    float acc[TM][TN];
    #pragma unroll
    for (int i = 0; i < TM; i++)
        #pragma unroll
        for (int j = 0; j < TN; j++) acc[i][j] = 0.f;

    for (int kk = 0; kk < K; kk += BK) {
        for (int idx = tid; idx < BM * BK; idx += 256) {
            int m = idx / BK, k = idx % BK;
            int gm = m0 + m, gk = kk + k;
            As[k][m] = (gm < M && gk < K) ? A[(long long)gm * lda + gk] : 0.f;
        }
        for (int idx = tid; idx < BN * BK; idx += 256) {
            int n = idx / BK, k = idx % BK;
            int gn = n0 + n, gk = kk + k;
            Ws[k][n] = (gn < N && gk < K) ? W[(long long)gn * ldw + gk] : 0.f;
        }
        __syncthreads();
        #pragma unroll
        for (int k = 0; k < BK; k++) {
            float a[TM], wv[TN];
            #pragma unroll
            for (int i = 0; i < TM; i++) a[i] = As[k][tm + i];
            #pragma unroll
            for (int j = 0; j < TN; j++) wv[j] = Ws[k][tn + j];
            #pragma unroll
            for (int i = 0; i < TM; i++)
                #pragma unroll
                for (int j = 0; j < TN; j++)
                    acc[i][j] += a[i] * wv[j];
        }
        __syncthreads();
    }

    #pragma unroll
    for (int i = 0; i < TM; i++) {
        int gm = m0 + tm + i;
        if (gm >= M) continue;
        #pragma unroll
        for (int j = 0; j < TN; j++) {
            int gn = n0 + tn + j;
            if (gn >= N) continue;
            float v = acc[i][j] + b1[gn];
            if (ACT == 1) v = tanhf(v);
            else if (ACT == 2) v = expf(v);
            C[(long long)gm * ldc + gn] = v;
        }
    }
}

// ---------------- persistent bidirectional LSTM recurrence (tensor-core v3) -------
// 128 blocks = 2 dirs * 64 slices of 8 h-cols. Per step, h (hi+lo bf16, already
// stored in the swizzled SMEM layout in global) arrives via ONE 128KB
// cp.async.bulk + mbarrier instead of 8192 cp.async.cg issues.
__global__ void __launch_bounds__(256, 1)
lstm_persist(const float* __restrict__ xw,    // [2][T][B][G4]
             const float* __restrict__ Whh,   // [2][G4][H]
             const float* __restrict__ h0s,   // [2][B][H]
             const float* __restrict__ c0s,   // [2][B][H]
             __nv_bfloat16* __restrict__ hbf, // [2][2][hi|lo swizzled]
             float* __restrict__ hlast,       // [2][B][H]
             __nv_bfloat16* __restrict__ yh,  // [T*B][2H] split hi or null
             __nv_bfloat16* __restrict__ yl,  // split lo or null
             unsigned* __restrict__ bar)      // 2 counters (per dir)
{
    extern __shared__ char smem[];
    char*  wsh = smem;                         // 32KB W hi (swizzled)
    char*  wsl = smem + 32768;                 // 32KB W lo
    char*  hh  = smem + 65536;                 // 64KB h hi  (bulk dst, contiguous
    char*  hl  = smem + 131072;                // 64KB h lo   with hh)
    float* gs  = (float*)(smem + 196608);      // [4][64][33] partials
    const uint32_t mbar = smem_u32(smem + 230400);

    const int tid  = threadIdx.x;
    const int lane = tid & 31, w = tid >> 5;
    const int wm   = w & 1;                    // m-half
    const int kq   = w >> 1;                   // k-quarter
    const int r    = lane >> 2, q = lane & 3;
    const int d    = blockIdx.x >> 6;
    const int s    = blockIdx.x & 63;          // h-chunk index (j0>>3)
    const int j0   = s * 8;

    // pointwise mapping: thread -> (batch pb, jj pair jp)
    const int pb = tid >> 2;
    const int jp = (tid & 3) << 1;

    // ---- prologue: split Whh slice into SMEM; init h0 (swizzled global) / c0 ----
    const float* wp = Whh + (size_t)d * G4 * H_;
    for (int i = tid; i < 32 * 64; i += 256) {
        int cl = i >> 6, u = i & 63;
        int gate = cl >> 3, jj = cl & 7;
        const float* src = wp + (size_t)(gate * H_ + j0 + jj) * H_ + u * 8;
        uint32_t hi4[4], lo4[4];
        #pragma unroll
        for (int p = 0; p < 4; p++) {
            float a = src[2 * p], b = src[2 * p + 1];
            __nv_bfloat16 ha = __float2bfloat16(a), hb = __float2bfloat16(b);
            hi4[p] = pkbf2(a, b);
            lo4[p] = pkbf2(a - __bfloat162float(ha), b - __bfloat162float(hb));
        }
        int off = cl * 1024 + ((u ^ (cl & 7)) << 4);
        *(uint4*)(wsh + off) = make_uint4(hi4[0], hi4[1], hi4[2], hi4[3]);
        *(uint4*)(wsl + off) = make_uint4(lo4[0], lo4[1], lo4[2], lo4[3]);
    }
    {
        __nv_bfloat16* hb0 = hbf + d * 65536;
        float2 v = *(const float2*)(h0s + (size_t)d * B_ * H_ + pb * H_ + j0 + jp);
        __nv_bfloat16 h0a = __float2bfloat16(v.x), h0b = __float2bfloat16(v.y);
        uint32_t hip = pkbf2(v.x, v.y);
        uint32_t lop = pkbf2(v.x - __bfloat162float(h0a), v.y - __bfloat162float(h0b));
        int el = (pb << 9) + ((s ^ (pb & 7)) << 3) + jp;
        *(uint32_t*)(hb0 + el)         = hip;
        *(uint32_t*)(hb0 + 32768 + el) = lop;
    }
    float2 creg = *(const float2*)(c0s + (size_t)d * B_ * H_ + pb * H_ + j0 + jp);

    if (tid == 0)
        asm volatile("mbarrier.init.shared.b64 [%0], 1;" :: "r"(mbar) : "memory");
    __syncthreads();
    if (tid == 0) {
        asm volatile("red.release.gpu.global.add.u32 [%0], 1;" :: "l"(bar + d) : "memory");
        unsigned v;
        do { asm volatile("ld.acquire.gpu.u32 %0, [%1];" : "=r"(v) : "l"(bar + d)); }
        while (v < 64u);
    }
    __syncthreads();

    const uint32_t hhA = smem_u32(hh);

    float acc[2][4][4];
    #pragma unroll
    for (int mf = 0; mf < 2; mf++)
        #pragma unroll
        for (int nf = 0; nf < 4; nf++)
            #pragma unroll
            for (int x = 0; x < 4; x++) acc[mf][nf][x] = 0.f;

    uint32_t phase = 0;

    for (int t = 0; t < T_; t++) {
        const int td = d ? (T_ - 1 - t) : t;

        // xw gate values -> registers (float2 pairs; latency hidden under bulk)
        const float* xp = xw + ((size_t)(d * T_ + td) * B_ + pb) * G4 + j0 + jp;
        float2 xg0 = *(const float2*)(xp);
        float2 xg1 = *(const float2*)(xp + H_);
        float2 xg2 = *(const float2*)(xp + 2 * H_);
        float2 xg3 = *(const float2*)(xp + 3 * H_);

        // one 128KB bulk copy: global (swizzled) -> SMEM hh|hl
        if (tid == 0) {
            asm volatile("fence.proxy.async;" ::: "memory");
            asm volatile("mbarrier.arrive.expect_tx.shared.b64 _, [%0], %1;"
                         :: "r"(mbar), "r"(131072u) : "memory");
            const __nv_bfloat16* src = hbf + (size_t)(t & 1) * 131072 + d * 65536;
            asm volatile(
                "cp.async.bulk.shared::cluster.global.mbarrier::complete_tx::bytes "
                "[%0], [%1], %2, [%3];"
                :: "r"(hhA), "l"(src), "r"(131072u), "r"(mbar) : "memory");
        }
        asm volatile(
            "{\n\t.reg .pred P;\n\t"
            "W%=:\n\t"
            "mbarrier.try_wait.parity.shared.b64 P, [%0], %1;\n\t"
            "@!P bra W%=;\n\t"
            "}" :: "r"(mbar), "r"(phase) : "memory");
        phase ^= 1;

        // MMA: this warp's k-quarter, 8 k16-steps
        #pragma unroll
        for (int ks2 = 0; ks2 < 8; ks2++) {
            const int u0 = (kq << 4) + (ks2 << 1);
            const int usw0 = ((u0 ^ r) << 4) + q * 4;
            const int usw1 = (((u0 + 1) ^ r) << 4) + q * 4;

            uint32_t ah[2][4], al2[2][4], bh[4][2], bl2[4][2];
            #pragma unroll
            for (int mf = 0; mf < 2; mf++) {
                int m0r = wm * 32 + mf * 16 + r;
                const char* p0 = hh + (m0r << 10);
                const char* p1 = hh + ((m0r + 8) << 10);
                ah[mf][0] = *(const uint32_t*)(p0 + usw0);
                ah[mf][1] = *(const uint32_t*)(p1 + usw0);
                ah[mf][2] = *(const uint32_t*)(p0 + usw1);
                ah[mf][3] = *(const uint32_t*)(p1 + usw1);
                const char* q0 = hl + (m0r << 10);
                const char* q1 = hl + ((m0r + 8) << 10);
                al2[mf][0] = *(const uint32_t*)(q0 + usw0);
                al2[mf][1] = *(const uint32_t*)(q1 + usw0);
                al2[mf][2] = *(const uint32_t*)(q0 + usw1);
                al2[mf][3] = *(const uint32_t*)(q1 + usw1);
            }
            #pragma unroll
            for (int nf = 0; nf < 4; nf++) {
                int nr = nf * 8 + r;
                const char* pb2 = wsh + (nr << 10);
                const char* qb2 = wsl + (nr << 10);
                bh[nf][0]  = *(const uint32_t*)(pb2 + usw0);
                bh[nf][1]  = *(const uint32_t*)(pb2 + usw1);
                bl2[nf][0] = *(const uint32_t*)(qb2 + usw0);
                bl2[nf][1] = *(const uint32_t*)(qb2 + usw1);
            }
            #pragma unroll
            for (int mf = 0; mf < 2; mf++)
                #pragma unroll
                for (int nf = 0; nf < 4; nf++) {
                    mma_bf16(acc[mf][nf], ah[mf],  bh[nf]);
                    mma_bf16(acc[mf][nf], ah[mf],  bl2[nf]);
                    mma_bf16(acc[mf][nf], al2[mf], bh[nf]);
                }
        }

        // atomic-free partial store (each warp owns gs[kq] rows wm*32..+32)
        #pragma unroll
        for (int mf = 0; mf < 2; mf++) {
            int b = wm * 32 + mf * 16 + r;
            #pragma unroll
            for (int nf = 0; nf < 4; nf++) {
                int cl = nf * 8 + q * 2;
                float* gp0 = gs + ((kq * 64 + b) * 33) + cl;
                float* gp1 = gs + ((kq * 64 + b + 8) * 33) + cl;
                gp0[0] = acc[mf][nf][0]; gp0[1] = acc[mf][nf][1];
                gp1[0] = acc[mf][nf][2]; gp1[1] = acc[mf][nf][3];
                acc[mf][nf][0] = acc[mf][nf][1] = acc[mf][nf][2] = acc[mf][nf][3] = 0.f;
            }
        }
        __syncthreads();

        // pointwise c/h update for the (pb, jp) pair
        float gi0 = xg0.x, gi1 = xg0.y;
        float gf0 = xg1.x, gf1 = xg1.y;
        float gg0 = xg2.x, gg1 = xg2.y;
        float go0 = xg3.x, go1 = xg3.y;
        #pragma unroll
        for (int kk2 = 0; kk2 < 4; kk2++) {
            const float* gp = gs + (kk2 * 64 + pb) * 33;
            gi0 += gp[jp];      gi1 += gp[jp + 1];
            gf0 += gp[8 + jp];  gf1 += gp[8 + jp + 1];
            gg0 += gp[16 + jp]; gg1 += gp[16 + jp + 1];
            go0 += gp[24 + jp]; go1 += gp[24 + jp + 1];
        }
        float si0 = 1.f / (1.f + expf(-gi0)), si1 = 1.f / (1.f + expf(-gi1));
        float sf0 = 1.f / (1.f + expf(-gf0)), sf1 = 1.f / (1.f + expf(-gf1));
        float so0 = 1.f / (1.f + expf(-go0)), so1 = 1.f / (1.f + expf(-go1));
        float cn0 = sf0 * creg.x + si0 * tanhf(gg0);
        float cn1 = sf1 * creg.y + si1 * tanhf(gg1);
        float hn0 = so0 * tanhf(cn0);
        float hn1 = so1 * tanhf(cn1);
        creg.x = cn0; creg.y = cn1;

        __nv_bfloat16 hb0 = __float2bfloat16(hn0), hb1 = __float2bfloat16(hn1);
        uint32_t hip = pkbf2(hn0, hn1);
        uint32_t lop = pkbf2(hn0 - __bfloat162float(hb0), hn1 - __bfloat162float(hb1));

        __nv_bfloat16* hbw = hbf + (size_t)((t + 1) & 1) * 131072 + d * 65536;
        int el = (pb << 9) + ((s ^ (pb & 7)) << 3) + jp;
        *(uint32_t*)(hbw + el)         = hip;
        *(uint32_t*)(hbw + 32768 + el) = lop;
        if (yh) {
            size_t yi = (size_t)(td * B_ + pb) * H2 + d * H_ + j0 + jp;
            *(uint32_t*)(yh + yi) = hip;
            *(uint32_t*)(yl + yi) = lop;
        }
        if (t == T_ - 1)
            *(float2*)(hlast + (size_t)d * B_ * H_ + pb * H_ + j0 + jp) =
                make_float2(hn0, hn1);

        __syncthreads();
        if (t < T_ - 1) {
            if (tid == 0) {
                asm volatile("red.release.gpu.global.add.u32 [%0], 1;" :: "l"(bar + d) : "memory");
                unsigned tgt = 64u * (unsigned)(t + 2), v;
                do { asm volatile("ld.acquire.gpu.u32 %0, [%1];" : "=r"(v) : "l"(bar + d)); }
                while (v < tgt);
            }
            __syncthreads();
        }
    }
}

// ---------------- small kernels ----------------
__global__ void reset_bar(unsigned* __restrict__ bar)
{
    if (threadIdx.x < 8) bar[threadIdx.x] = 0;
}

__global__ void attn_alpha(const float* __restrict__ e, float* __restrict__ alphab)
{
    int b = blockIdx.x;
    __shared__ float a[2 * F_];
    __shared__ float red[128];
    __shared__ float redc[128];
    int tid = threadIdx.x;

    for (int i = tid; i < 2 * F_; i += 128) {
        int d = i / F_, j = i % F_;
        a[i] = e[(d * B_ + b) * F_ + j];
    }
    __syncthreads();

    float s = 0.f;
    for (int i = tid; i < 2 * F_; i += 128) s += a[i];
    red[tid] = s; __syncthreads();
    for (int off = 64; off; off >>= 1) { if (tid < off) red[tid] += red[tid + off]; __syncthreads(); }
    float denom = red[0];
    __syncthreads();

    for (int i = tid; i < 2 * F_; i += 128) a[i] /= denom;
    __syncthreads();

    float cnt = 0.f, sel = 0.f;
    for (int i = tid; i < 2 * F_; i += 128) {
        float v = a[i];
        if (v >= 0.1f) { cnt += 1.f; sel += v; }
    }
    red[tid] = sel; redc[tid] = cnt; __syncthreads();
    for (int off = 64; off; off >>= 1) {
        if (tid < off) { red[tid] += red[tid + off]; redc[tid] += redc[tid + off]; }
        __syncthreads();
    }
    float selmean = red[0] / fmaxf(redc[0], 1.f);
    __syncthreads();

    for (int i = tid; i < 2 * F_; i += 128)
        if (a[i] >= 0.1f) a[i] = selmean;
    __syncthreads();

    for (int j = tid; j < F_; j += 128)
        alphab[b * F_ + j] = 0.5f * (a[j] + a[F_ + j]);
}

// fused: xw = x * alpha_b, padded to 128 cols, written as bf16 hi/lo split
__global__ void scale_split(const float* __restrict__ x, const float* __restrict__ ab,
                            __nv_bfloat16* __restrict__ hi, __nv_bfloat16* __restrict__ lo)
{
    int i = blockIdx.x * blockDim.x + threadIdx.x;   // over M*128
    if (i < T_ * B_ * 128) {
        int f = i & 127;
        int m = i >> 7;
        int b = m & (B_ - 1);
        float v = 0.f;
        if (f < F_) v = x[m * F_ + f] * ab[b * F_ + f];
        __nv_bfloat16 h = __float2bfloat16(v);
        hi[i] = h;
        lo[i] = __float2bfloat16(v - __bfloat162float(h));
    }
}

// ---------------- host driver ----------------
extern "C" void kernel_launch(void* const* d_in, const int* in_sizes, int n_in,
                              void* d_out, int out_size)
{
    const float* x     = (const float*)d_in[0];
    const float* h0    = (const float*)d_in[1];
    const float* c0    = (const float*)d_in[2];
    const float* saWih = (const float*)d_in[3];
    const float* saWhh = (const float*)d_in[4];
    const float* sabih = (const float*)d_in[5];
    const float* sabhh = (const float*)d_in[6];
    const float* m0Wih = (const float*)d_in[7];
    const float* m0Whh = (const float*)d_in[8];
    const float* m0bih = (const float*)d_in[9];
    const float* m0bhh = (const float*)d_in[10];
    const float* mLWih = (const float*)d_in[11];
    const float* mLWhh = (const float*)d_in[12];
    const float* mLbih = (const float*)d_in[13];
    const float* mLbhh = (const float*)d_in[14];
    const float* sf1W  = (const float*)d_in[15];
    const float* sf1b  = (const float*)d_in[16];
    const float* sf2W  = (const float*)d_in[17];
    const float* sf2b  = (const float*)d_in[18];
    const float* fc1W  = (const float*)d_in[19];
    const float* fc1b  = (const float*)d_in[20];
    float* out = (float*)d_out;

    float *xw, *hlast, *t1, *e, *ab;
    unsigned* bar;
    __nv_bfloat16 *wh, *wl, *ah, *al, *hbf;
    cudaGetSymbolAddress((void**)&xw,    g_xw);
    cudaGetSymbolAddress((void**)&hbf,   g_hbf);
    cudaGetSymbolAddress((void**)&hlast, g_hlast);
    cudaGetSymbolAddress((void**)&t1,    g_t1);
    cudaGetSymbolAddress((void**)&e,     g_e);
    cudaGetSymbolAddress((void**)&ab,    g_ab);
    cudaGetSymbolAddress((void**)&bar,   g_bar);
    cudaGetSymbolAddress((void**)&wh,    g_wh);
    cudaGetSymbolAddress((void**)&wl,    g_wl);
    cudaGetSymbolAddress((void**)&ah,    g_ah);
    cudaGetSymbolAddress((void**)&al,    g_al);

    const int SMEM_LSTM = 230416;
    cudaFuncSetAttribute(lstm_persist, cudaFuncAttributeMaxDynamicSharedMemorySize, SMEM_LSTM);
    const int SMEM_MMA = 2 * BUFB;
    cudaFuncSetAttribute(gemm_mma, cudaFuncAttributeMaxDynamicSharedMemorySize, SMEM_MMA);

    const int M = T_ * B_;   // 8192

    auto proj = [&](long long woff, const float* bih, const float* bhh, int Kpad) {
        gemm_mma<<<dim3(G4 / 128, M / 128, 2), 256, SMEM_MMA>>>(
            ah, al, wh + woff, wl + woff, (long long)G4 * Kpad,
            bih, G4, bhh, G4, xw, (long long)M * G4, Kpad, G4);
    };
    auto recur = [&](const float* Whh, const float* h0s, const float* c0s,
                     __nv_bfloat16* yhp, __nv_bfloat16* ylp, int stage) {
        lstm_persist<<<128, 256, SMEM_LSTM>>>(xw, Whh, h0s, c0s, hbf, hlast,
                                              yhp, ylp, bar + 2 * stage);
    };

    reset_bar<<<1, 32>>>(bar);

    // ---- stage 0: spatial-attention biLSTM ----
    conv_split<<<1024, 256>>>(saWih, 2 * G4, F_, 128, wh + OFF_SAW, wl + OFF_SAW);
    conv_split<<<1024, 256>>>(x, M, F_, 128, ah, al);
    proj(OFF_SAW, sabih, sabhh, 128);
    conv_split<<<1024, 256>>>(m0Wih, 2 * G4, F_, 128, wh + OFF_M0W, wl + OFF_M0W);
    recur(saWhh, h0, c0, nullptr, nullptr, 0);

    // ---- attention ----
    gemm_small<1, 32, 64, 2, 4><<<dim3(H_ / 64, (2 * B_ + 31) / 32), 256>>>(
        hlast, H_, sf1W, H_, sf1b, t1, H_, 2 * B_, H_, H_);
    gemm_small<2, 32, 64, 2, 4><<<dim3((F_ + 63) / 64, (2 * B_ + 31) / 32), 256>>>(
        t1, H_, sf2W, H_, sf2b, e, F_, 2 * B_, F_, H_);
    attn_alpha<<<B_, 128>>>(e, ab);
    scale_split<<<(M * 128 + 255) / 256, 256>>>(x, ab, ah, al);

    // ---- main layer 0 ----
    proj(OFF_M0W, m0bih, m0bhh, 128);
    conv_split<<<2048, 256>>>(mLWih, 2 * 2 * G4, H2, H2, wh + OFF_MLW, wl + OFF_MLW);
    recur(m0Whh, h0, c0, ah, al, 1);

    // ---- main layers 1,2 ----
    proj(OFF_MLW, mLbih, mLbhh, H2);
    recur(mLWhh, h0 + 2 * B_ * H_, c0 + 2 * B_ * H_, ah, al, 2);

    gemm_mma<<<dim3(G4 / 128, M / 128, 2), 256, SMEM_MMA>>>(
        ah, al, wh + OFF_MLW + 2ll * G4 * H2, wl + OFF_MLW + 2ll * G4 * H2,
        (long long)G4 * H2,
        mLbih + 2 * G4, G4, mLbhh + 2 * G4, G4, xw, (long long)M * G4, H2, G4);
    conv_split<<<1024, 256>>>(fc1W, H_, H2, H2, wh + OFF_FCW, wl + OFF_FCW);
    recur(mLWhh + 2ll * G4 * H_, h0 + 4 * B_ * H_, c0 + 4 * B_ * H_, ah, al, 3);

    // ---- final FC ----
    gemm_mma<<<dim3(H_ / 128, M / 128, 1), 256, SMEM_MMA>>>(
        ah, al, wh + OFF_FCW, wl + OFF_FCW, 0ll,
        fc1b, 0ll, nullptr, 0ll, out, 0ll, H2, H_);
}

// round 9
// speedup vs baseline: 2.8963x; 1.0532x over previous
#include <cuda_runtime.h>
#include <cuda_bf16.h>
#include <math.h>
#include <stdint.h>

#define T_  128
#define B_  64
#define F_  75
#define H_  512
#define G4  2048   // 4*H
#define H2  1024   // 2*H

// ---------------- static scratch ----------------
__device__ __align__(256) float g_xw   [2ll * T_ * B_ * G4];
// h between steps, grouped by k-quarter, already in the SMEM swizzled layout:
// elem off = ((buf*2+d)*4+q)*16384 + part*8192 + (b<<7) + (((u&15)^(b&7))<<3) + jj
__device__ __align__(256) __nv_bfloat16 g_hbf[2 * 2 * 2 * B_ * H_];
__device__ float g_hlast[2 * B_ * H_];
__device__ float g_t1   [2 * B_ * H_];
__device__ float g_e    [2 * B_ * F_];
__device__ float g_ab   [B_ * F_];
__device__ unsigned g_bar[1024];   // [stage][d][group][32-pad]

// bf16 split buffers (hi / lo)
#define WSZ 10485760ll
__device__ __align__(256) __nv_bfloat16 g_wh[WSZ];
__device__ __align__(256) __nv_bfloat16 g_wl[WSZ];
__device__ __align__(256) __nv_bfloat16 g_ah[8388608ll];
__device__ __align__(256) __nv_bfloat16 g_al[8388608ll];

#define OFF_SAW 0ll
#define OFF_M0W 524288ll
#define OFF_MLW 1048576ll
#define OFF_FCW 9437184ll

// ---------------- helpers ----------------
__device__ __forceinline__ void cp16(uint32_t dst, const void* src) {
    asm volatile("cp.async.cg.shared.global [%0], [%1], 16;" :: "r"(dst), "l"(src));
}
__device__ __forceinline__ uint32_t smem_u32(const void* p) {
    return (uint32_t)__cvta_generic_to_shared(p);
}
__device__ __forceinline__ void mma_bf16(float* d, const uint32_t* a, const uint32_t* b) {
    asm volatile(
        "mma.sync.aligned.m16n8k16.row.col.f32.bf16.bf16.f32 "
        "{%0,%1,%2,%3}, {%4,%5,%6,%7}, {%8,%9}, {%0,%1,%2,%3};"
        : "+f"(d[0]), "+f"(d[1]), "+f"(d[2]), "+f"(d[3])
        : "r"(a[0]), "r"(a[1]), "r"(a[2]), "r"(a[3]), "r"(b[0]), "r"(b[1]));
}
__device__ __forceinline__ uint32_t pkbf2(float a, float b) {
    __nv_bfloat16 ha = __float2bfloat16(a), hb = __float2bfloat16(b);
    uint16_t ua = *(uint16_t*)&ha, ub = *(uint16_t*)&hb;
    return (uint32_t)ua | ((uint32_t)ub << 16);
}
__device__ __forceinline__ float sigf(float x) {
    return __fdividef(1.f, 1.f + __expf(-x));
}
__device__ __forceinline__ float tanhfast(float x) {
    return __fmaf_rn(2.f, sigf(2.f * x), -1.f);
}

// ---------------- fp32 -> bf16 hi/lo split conversion ----------------
__global__ void conv_split(const float* __restrict__ src, int rows, int K, int Kpad,
                           __nv_bfloat16* __restrict__ hi, __nv_bfloat16* __restrict__ lo)
{
    long long n = (long long)rows * Kpad;
    for (long long i = blockIdx.x * (long long)blockDim.x + threadIdx.x; i < n;
         i += (long long)gridDim.x * blockDim.x) {
        int kc = (int)(i % Kpad);
        long long r = i / Kpad;
        float v = (kc < K) ? src[r * K + kc] : 0.f;
        __nv_bfloat16 h = __float2bfloat16(v);
        hi[i] = h;
        lo[i] = __float2bfloat16(v - __bfloat162float(h));
    }
}

// ================= bf16 split tensor-core GEMM (mma.sync / HMMA) ==================
#define TILEB 10240
#define BUFB  40960

__global__ void __launch_bounds__(256, 1)
gemm_mma(const __nv_bfloat16* __restrict__ Ah, const __nv_bfloat16* __restrict__ Al,
         const __nv_bfloat16* __restrict__ Wh, const __nv_bfloat16* __restrict__ Wl,
         long long sW,
         const float* __restrict__ b1, long long sB1,
         const float* __restrict__ b2, long long sB2,
         float* __restrict__ C, long long sC,
         int Kpad, int N)
{
    extern __shared__ char smem[];
    const uint32_t sb = smem_u32(smem);

    const int z = blockIdx.z;
    Wh += (long long)z * sW;
    Wl += (long long)z * sW;
    C  += (long long)z * sC;
    if (b1) b1 += (long long)z * sB1;
    if (b2) b2 += (long long)z * sB2;

    const int tid  = threadIdx.x;
    const int lane = tid & 31;
    const int warp = tid >> 5;
    const int wm   = warp >> 2;
    const int wn   = warp & 3;
    const int m0   = blockIdx.y * 128;
    const int n0   = blockIdx.x * 128;
    const int q2   = (lane & 3) * 2;
    const int lr   = lane >> 2;

    float acc[4][4][4];
    #pragma unroll
    for (int mf = 0; mf < 4; mf++)
        #pragma unroll
        for (int nf = 0; nf < 4; nf++)
            #pragma unroll
            for (int r = 0; r < 4; r++) acc[mf][nf][r] = 0.f;

    const int sr = tid >> 1;
    const int skc = (tid & 1) * 2;

    auto stage = [&](int buf, int ch) {
        long long col = (long long)ch * 32;
        #pragma unroll
        for (int i = 0; i < 2; i++) {
            int kc = skc + i;
            uint32_t so = (uint32_t)(buf * BUFB + sr * 80 + kc * 16);
            long long gc = col + kc * 8;
            cp16(sb + so,             Ah + (long long)(m0 + sr) * Kpad + gc);
            cp16(sb + so + TILEB,     Al + (long long)(m0 + sr) * Kpad + gc);
            cp16(sb + so + 2 * TILEB, Wh + (long long)(n0 + sr) * Kpad + gc);
            cp16(sb + so + 3 * TILEB, Wl + (long long)(n0 + sr) * Kpad + gc);
        }
        asm volatile("cp.async.commit_group;");
    };

    const int nch = Kpad >> 5;
    stage(0, 0);

    for (int ch = 0; ch < nch; ch++) {
        if (ch + 1 < nch) {
            stage((ch + 1) & 1, ch + 1);
            asm volatile("cp.async.wait_group 1;");
        } else {
            asm volatile("cp.async.wait_group 0;");
        }
        __syncthreads();

        const char* base = smem + (ch & 1) * BUFB;
        #pragma unroll
        for (int ks = 0; ks < 2; ks++) {
            const int k0 = ks * 16;
            uint32_t ah[4][4], al[4][4], bh[4][2], bl[4][2];
            #pragma unroll
            for (int mf = 0; mf < 4; mf++) {
                int row = wm * 64 + mf * 16 + lr;
                const char* p0 = base + row * 80 + (k0 + q2) * 2;
                const char* p1 = base + (row + 8) * 80 + (k0 + q2) * 2;
                ah[mf][0] = *(const uint32_t*)(p0);
                ah[mf][1] = *(const uint32_t*)(p1);
                ah[mf][2] = *(const uint32_t*)(p0 + 16);
                ah[mf][3] = *(const uint32_t*)(p1 + 16);
                al[mf][0] = *(const uint32_t*)(p0 + TILEB);
                al[mf][1] = *(const uint32_t*)(p1 + TILEB);
                al[mf][2] = *(const uint32_t*)(p0 + 16 + TILEB);
                al[mf][3] = *(const uint32_t*)(p1 + 16 + TILEB);
            }
            #pragma unroll
            for (int nf = 0; nf < 4; nf++) {
                int col = wn * 32 + nf * 8 + lr;
                const char* p = base + 2 * TILEB + col * 80 + (k0 + q2) * 2;
                bh[nf][0] = *(const uint32_t*)(p);
                bh[nf][1] = *(const uint32_t*)(p + 16);
                bl[nf][0] = *(const uint32_t*)(p + TILEB);
                bl[nf][1] = *(const uint32_t*)(p + 16 + TILEB);
            }
            #pragma unroll
            for (int mf = 0; mf < 4; mf++)
                #pragma unroll
                for (int nf = 0; nf < 4; nf++)
                    mma_bf16(acc[mf][nf], ah[mf], bh[nf]);
            #pragma unroll
            for (int mf = 0; mf < 4; mf++)
                #pragma unroll
                for (int nf = 0; nf < 4; nf++)
                    mma_bf16(acc[mf][nf], ah[mf], bl[nf]);
            #pragma unroll
            for (int mf = 0; mf < 4; mf++)
                #pragma unroll
                for (int nf = 0; nf < 4; nf++)
                    mma_bf16(acc[mf][nf], al[mf], bh[nf]);
        }
        __syncthreads();
    }

    #pragma unroll
    for (int nf = 0; nf < 4; nf++) {
        int gn = n0 + wn * 32 + nf * 8 + q2;
        float bb0 = 0.f, bb1 = 0.f;
        if (b1) { bb0 += b1[gn]; bb1 += b1[gn + 1]; }
        if (b2) { bb0 += b2[gn]; bb1 += b2[gn + 1]; }
        #pragma unroll
        for (int mf = 0; mf < 4; mf++) {
            long long gm = m0 + wm * 64 + mf * 16 + lr;
            float2 v0 = make_float2(acc[mf][nf][0] + bb0, acc[mf][nf][1] + bb1);
            float2 v1 = make_float2(acc[mf][nf][2] + bb0, acc[mf][nf][3] + bb1);
            *(float2*)(C + gm * N + gn)       = v0;
            *(float2*)(C + (gm + 8) * N + gn) = v1;
        }
    }
}

// ================= small generic GEMM (attention FCs) ==============================
template<int ACT, int BM, int BN, int TM, int TN>
__global__ void gemm_small(const float* __restrict__ A, int lda,
                           const float* __restrict__ W, int ldw,
                           const float* __restrict__ b1,
                           float* __restrict__ C, int ldc,
                           int M, int N, int K)
{
    const int BK = 16;
    __shared__ float As[BK][BM + 2];
    __shared__ float Ws[BK][BN + 2];

    int m0 = blockIdx.y * BM;
    int n0 = blockIdx.x * BN;
    int tid = threadIdx.x;
    int tcol = tid % (BN / TN);
    int trow = tid / (BN / TN);
    int tm = trow * TM, tn = tcol * TN;

    float acc[TM][TN];
    #pragma unroll
    for (int i = 0; i < TM; i++)
        #pragma unroll
        for (int j = 0; j < TN; j++) acc[i][j] = 0.f;

    for (int kk = 0; kk < K; kk += BK) {
        for (int idx = tid; idx < BM * BK; idx += 256) {
            int m = idx / BK, k = idx % BK;
            int gm = m0 + m, gk = kk + k;
            As[k][m] = (gm < M && gk < K) ? A[(long long)gm * lda + gk] : 0.f;
        }
        for (int idx = tid; idx < BN * BK; idx += 256) {
            int n = idx / BK, k = idx % BK;
            int gn = n0 + n, gk = kk + k;
            Ws[k][n] = (gn < N && gk < K) ? W[(long long)gn * ldw + gk] : 0.f;
        }
        __syncthreads();
        #pragma unroll
        for (int k = 0; k < BK; k++) {
            float a[TM], wv[TN];
            #pragma unroll
            for (int i = 0; i < TM; i++) a[i] = As[k][tm + i];
            #pragma unroll
            for (int j = 0; j < TN; j++) wv[j] = Ws[k][tn + j];
            #pragma unroll
            for (int i = 0; i < TM; i++)
                #pragma unroll
                for (int j = 0; j < TN; j++)
                    acc[i][j] += a[i] * wv[j];
        }
        __syncthreads();
    }

    #pragma unroll
    for (int i = 0; i < TM; i++) {
        int gm = m0 + tm + i;
        if (gm >= M) continue;
        #pragma unroll
        for (int j = 0; j < TN; j++) {
            int gn = n0 + tn + j;
            if (gn >= N) continue;
            float v = acc[i][j] + b1[gn];
            if (ACT == 1) v = tanhf(v);
            else if (ACT == 2) v = expf(v);
            C[(long long)gm * ldc + gn] = v;
        }
    }
}

// ---------------- persistent bidirectional LSTM recurrence (tensor-core v4) -------
// 128 blocks = 2 dirs * 64 slices of 8 h-cols. h grouped by k-quarter in global:
// 4 group barriers (16 arrivals each) + 4 independent 32KB bulk copies, each
// issued by a coordinator warp as soon as its group's producers arrive. Warp kq
// only waits on mbar[kq] -> group-level pipelining of barrier/transfer/MMA.
__global__ void __launch_bounds__(256, 1)
lstm_persist(const float* __restrict__ xw,    // [2][T][B][G4]
             const float* __restrict__ Whh,   // [2][G4][H]
             const float* __restrict__ h0s,   // [2][B][H]
             const float* __restrict__ c0s,   // [2][B][H]
             __nv_bfloat16* __restrict__ hbf, // grouped/swizzled (see decl)
             float* __restrict__ hlast,       // [2][B][H]
             __nv_bfloat16* __restrict__ yh,  // [T*B][2H] split hi or null
             __nv_bfloat16* __restrict__ yl,  // split lo or null
             unsigned* __restrict__ bar)      // [d][group][32-pad]
{
    extern __shared__ char smem[];
    char*  hsm = smem;                          // 4 x 32KB: [q][hi 16KB | lo 16KB]
    char*  wsh = smem + 131072;                 // 32KB W hi (swizzled)
    char*  wsl = smem + 163840;                 // 32KB W lo
    float* gs  = (float*)(smem + 196608);       // [4][64][33] partials
    const uint32_t mbase = smem_u32(smem + 230400);  // 4 mbarriers

    const int tid  = threadIdx.x;
    const int lane = tid & 31, w = tid >> 5;
    const int wm   = w & 1;                     // m-half
    const int kq   = w >> 1;                    // k-quarter
    const int r    = lane >> 2, qd = lane & 3;
    const int d    = blockIdx.x >> 6;
    const int s    = blockIdx.x & 63;
    const int j0   = s * 8;
    const int sq   = s >> 4;                    // this block's producer group
    const int su   = s & 15;                    // within-quarter chunk index

    const int pb = tid >> 2;
    const int jp = (tid & 3) << 1;

    unsigned* mybar = bar + d * 4 * 32;         // 4 group counters for this dir

    // ---- prologue: split Whh slice into SMEM; init h0 (grouped global) / c0 ----
    const float* wp = Whh + (size_t)d * G4 * H_;
    for (int i = tid; i < 32 * 64; i += 256) {
        int cl = i >> 6, u = i & 63;
        int gate = cl >> 3, jj = cl & 7;
        const float* src = wp + (size_t)(gate * H_ + j0 + jj) * H_ + u * 8;
        uint32_t hi4[4], lo4[4];
        #pragma unroll
        for (int p = 0; p < 4; p++) {
            float a = src[2 * p], b = src[2 * p + 1];
            __nv_bfloat16 ha = __float2bfloat16(a), hb = __float2bfloat16(b);
            hi4[p] = pkbf2(a, b);
            lo4[p] = pkbf2(a - __bfloat162float(ha), b - __bfloat162float(hb));
        }
        int off = cl * 1024 + ((u ^ (cl & 7)) << 4);
        *(uint4*)(wsh + off) = make_uint4(hi4[0], hi4[1], hi4[2], hi4[3]);
        *(uint4*)(wsl + off) = make_uint4(lo4[0], lo4[1], lo4[2], lo4[3]);
    }
    {
        float2 v = *(const float2*)(h0s + (size_t)d * B_ * H_ + pb * H_ + j0 + jp);
        __nv_bfloat16 h0a = __float2bfloat16(v.x), h0b = __float2bfloat16(v.y);
        uint32_t hip = pkbf2(v.x, v.y);
        uint32_t lop = pkbf2(v.x - __bfloat162float(h0a), v.y - __bfloat162float(h0b));
        // buf 0 (read at t=0)
        size_t base = ((size_t)(0 * 2 + d) * 4 + sq) * 16384
                    + (pb << 7) + (((su) ^ (pb & 7)) << 3) + jp;
        *(uint32_t*)(hbf + base)        = hip;
        *(uint32_t*)(hbf + base + 8192) = lop;
    }
    float2 creg = *(const float2*)(c0s + (size_t)d * B_ * H_ + pb * H_ + j0 + jp);

    if (tid < 4)
        asm volatile("mbarrier.init.shared.b64 [%0], 1;" :: "r"(mbase + 8 * tid) : "memory");
    __syncthreads();
    if (tid == 0)
        asm volatile("red.release.gpu.global.add.u32 [%0], 1;"
                     :: "l"(mybar + sq * 32) : "memory");

    const uint32_t hsmA = smem_u32(hsm);

    float acc[2][4][4];
    #pragma unroll
    for (int mf = 0; mf < 2; mf++)
        #pragma unroll
        for (int nf = 0; nf < 4; nf++)
            #pragma unroll
            for (int x = 0; x < 4; x++) acc[mf][nf][x] = 0.f;

    for (int t = 0; t < T_; t++) {
        const int td = d ? (T_ - 1 - t) : t;
        const int bufr = t & 1;

        // xw gate values -> registers (consumed only at pointwise)
        const float* xp = xw + ((size_t)(d * T_ + td) * B_ + pb) * G4 + j0 + jp;
        float2 xg0 = *(const float2*)(xp);
        float2 xg1 = *(const float2*)(xp + H_);
        float2 xg2 = *(const float2*)(xp + 2 * H_);
        float2 xg3 = *(const float2*)(xp + 3 * H_);

        // coordinators: warp g (g<4) lane 0 handles group g
        if (w < 4 && lane == 0) {
            const int g = w;
            unsigned tgt = 16u * (unsigned)(t + 1), v;
            do { asm volatile("ld.acquire.gpu.u32 %0, [%1];"
                              : "=r"(v) : "l"(mybar + g * 32)); }
            while (v < tgt);
            asm volatile("fence.proxy.async;" ::: "memory");
            asm volatile("mbarrier.arrive.expect_tx.shared.b64 _, [%0], %1;"
                         :: "r"(mbase + 8 * g), "r"(32768u) : "memory");
            const __nv_bfloat16* src = hbf + ((size_t)(bufr * 2 + d) * 4 + g) * 16384;
            asm volatile(
                "cp.async.bulk.shared::cluster.global.mbarrier::complete_tx::bytes "
                "[%0], [%1], %2, [%3];"
                :: "r"(hsmA + g * 32768), "l"(src), "r"(32768u), "r"(mbase + 8 * g)
                : "memory");
        }

        // wait only my quarter
        asm volatile(
            "{\n\t.reg .pred P;\n\t"
            "W%=:\n\t"
            "mbarrier.try_wait.parity.shared.b64 P, [%0], %1;\n\t"
            "@!P bra W%=;\n\t"
            "}" :: "r"(mbase + 8 * kq), "r"(t & 1) : "memory");

        // MMA: my k-quarter, 8 k16-steps, 3 split terms
        const char* hq = hsm + (kq << 15);
        #pragma unroll
        for (int ks2 = 0; ks2 < 8; ks2++) {
            const int u0  = ks2 << 1;
            const int uG  = (kq << 4) + u0;
            const int swH0 = ((u0 ^ r) << 4) + qd * 4;
            const int swH1 = (((u0 + 1) ^ r) << 4) + qd * 4;
            const int swW0 = ((uG ^ r) << 4) + qd * 4;
            const int swW1 = (((uG + 1) ^ r) << 4) + qd * 4;

            uint32_t ah[2][4], al2[2][4], bh[4][2], bl2[4][2];
            #pragma unroll
            for (int mf = 0; mf < 2; mf++) {
                int m0r = wm * 32 + mf * 16 + r;
                const char* p0 = hq + (m0r << 8);
                const char* p1 = hq + ((m0r + 8) << 8);
                ah[mf][0] = *(const uint32_t*)(p0 + swH0);
                ah[mf][1] = *(const uint32_t*)(p1 + swH0);
                ah[mf][2] = *(const uint32_t*)(p0 + swH1);
                ah[mf][3] = *(const uint32_t*)(p1 + swH1);
                al2[mf][0] = *(const uint32_t*)(p0 + 16384 + swH0);
                al2[mf][1] = *(const uint32_t*)(p1 + 16384 + swH0);
                al2[mf][2] = *(const uint32_t*)(p0 + 16384 + swH1);
                al2[mf][3] = *(const uint32_t*)(p1 + 16384 + swH1);
            }
            #pragma unroll
            for (int nf = 0; nf < 4; nf++) {
                int nr = nf * 8 + r;
                const char* pb2 = wsh + (nr << 10);
                const char* qb2 = wsl + (nr << 10);
                bh[nf][0]  = *(const uint32_t*)(pb2 + swW0);
                bh[nf][1]  = *(const uint32_t*)(pb2 + swW1);
                bl2[nf][0] = *(const uint32_t*)(qb2 + swW0);
                bl2[nf][1] = *(const uint32_t*)(qb2 + swW1);
            }
            #pragma unroll
            for (int mf = 0; mf < 2; mf++)
                #pragma unroll
                for (int nf = 0; nf < 4; nf++) {
                    mma_bf16(acc[mf][nf], ah[mf],  bh[nf]);
                    mma_bf16(acc[mf][nf], ah[mf],  bl2[nf]);
                    mma_bf16(acc[mf][nf], al2[mf], bh[nf]);
                }
        }

        // atomic-free partial store
        #pragma unroll
        for (int mf = 0; mf < 2; mf++) {
            int b = wm * 32 + mf * 16 + r;
            #pragma unroll
            for (int nf = 0; nf < 4; nf++) {
                int cl = nf * 8 + qd * 2;
                float* gp0 = gs + ((kq * 64 + b) * 33) + cl;
                float* gp1 = gs + ((kq * 64 + b + 8) * 33) + cl;
                gp0[0] = acc[mf][nf][0]; gp0[1] = acc[mf][nf][1];
                gp1[0] = acc[mf][nf][2]; gp1[1] = acc[mf][nf][3];
                acc[mf][nf][0] = acc[mf][nf][1] = acc[mf][nf][2] = acc[mf][nf][3] = 0.f;
            }
        }
        __syncthreads();

        // pointwise c/h update for the (pb, jp) pair
        float gi0 = xg0.x, gi1 = xg0.y;
        float gf0 = xg1.x, gf1 = xg1.y;
        float gg0 = xg2.x, gg1 = xg2.y;
        float go0 = xg3.x, go1 = xg3.y;
        #pragma unroll
        for (int kk2 = 0; kk2 < 4; kk2++) {
            const float* gp = gs + (kk2 * 64 + pb) * 33;
            gi0 += gp[jp];      gi1 += gp[jp + 1];
            gf0 += gp[8 + jp];  gf1 += gp[8 + jp + 1];
            gg0 += gp[16 + jp]; gg1 += gp[16 + jp + 1];
            go0 += gp[24 + jp]; go1 += gp[24 + jp + 1];
        }
        float cn0 = sigf(gf0) * creg.x + sigf(gi0) * tanhfast(gg0);
        float cn1 = sigf(gf1) * creg.y + sigf(gi1) * tanhfast(gg1);
        float hn0 = sigf(go0) * tanhfast(cn0);
        float hn1 = sigf(go1) * tanhfast(cn1);
        creg.x = cn0; creg.y = cn1;

        __nv_bfloat16 hb0 = __float2bfloat16(hn0), hb1 = __float2bfloat16(hn1);
        uint32_t hip = pkbf2(hn0, hn1);
        uint32_t lop = pkbf2(hn0 - __bfloat162float(hb0), hn1 - __bfloat162float(hb1));

        size_t wbase = ((size_t)(((t + 1) & 1) * 2 + d) * 4 + sq) * 16384
                     + (pb << 7) + ((su ^ (pb & 7)) << 3) + jp;
        *(uint32_t*)(hbf + wbase)        = hip;
        *(uint32_t*)(hbf + wbase + 8192) = lop;
        if (yh) {
            size_t yi = (size_t)(td * B_ + pb) * H2 + d * H_ + j0 + jp;
            *(uint32_t*)(yh + yi) = hip;
            *(uint32_t*)(yl + yi) = lop;
        }
        if (t == T_ - 1)
            *(float2*)(hlast + (size_t)d * B_ * H_ + pb * H_ + j0 + jp) =
                make_float2(hn0, hn1);

        __syncthreads();
        if (t < T_ - 1 && tid == 0)
            asm volatile("red.release.gpu.global.add.u32 [%0], 1;"
                         :: "l"(mybar + sq * 32) : "memory");
    }
}

// ---------------- small kernels ----------------
__global__ void reset_bar(unsigned* __restrict__ bar)
{
    for (int i = threadIdx.x; i < 1024; i += 256) bar[i] = 0;
}

__global__ void attn_alpha(const float* __restrict__ e, float* __restrict__ alphab)
{
    int b = blockIdx.x;
    __shared__ float a[2 * F_];
    __shared__ float red[128];
    __shared__ float redc[128];
    int tid = threadIdx.x;

    for (int i = tid; i < 2 * F_; i += 128) {
        int d = i / F_, j = i % F_;
        a[i] = e[(d * B_ + b) * F_ + j];
    }
    __syncthreads();

    float s = 0.f;
    for (int i = tid; i < 2 * F_; i += 128) s += a[i];
    red[tid] = s; __syncthreads();
    for (int off = 64; off; off >>= 1) { if (tid < off) red[tid] += red[tid + off]; __syncthreads(); }
    float denom = red[0];
    __syncthreads();

    for (int i = tid; i < 2 * F_; i += 128) a[i] /= denom;
    __syncthreads();

    float cnt = 0.f, sel = 0.f;
    for (int i = tid; i < 2 * F_; i += 128) {
        float v = a[i];
        if (v >= 0.1f) { cnt += 1.f; sel += v; }
    }
    red[tid] = sel; redc[tid] = cnt; __syncthreads();
    for (int off = 64; off; off >>= 1) {
        if (tid < off) { red[tid] += red[tid + off]; redc[tid] += redc[tid + off]; }
        __syncthreads();
    }
    float selmean = red[0] / fmaxf(redc[0], 1.f);
    __syncthreads();

    for (int i = tid; i < 2 * F_; i += 128)
        if (a[i] >= 0.1f) a[i] = selmean;
    __syncthreads();

    for (int j = tid; j < F_; j += 128)
        alphab[b * F_ + j] = 0.5f * (a[j] + a[F_ + j]);
}

// fused: xw = x * alpha_b, padded to 128 cols, written as bf16 hi/lo split
__global__ void scale_split(const float* __restrict__ x, const float* __restrict__ ab,
                            __nv_bfloat16* __restrict__ hi, __nv_bfloat16* __restrict__ lo)
{
    int i = blockIdx.x * blockDim.x + threadIdx.x;
    if (i < T_ * B_ * 128) {
        int f = i & 127;
        int m = i >> 7;
        int b = m & (B_ - 1);
        float v = 0.f;
        if (f < F_) v = x[m * F_ + f] * ab[b * F_ + f];
        __nv_bfloat16 h = __float2bfloat16(v);
        hi[i] = h;
        lo[i] = __float2bfloat16(v - __bfloat162float(h));
    }
}

// ---------------- host driver ----------------
extern "C" void kernel_launch(void* const* d_in, const int* in_sizes, int n_in,
                              void* d_out, int out_size)
{
    const float* x     = (const float*)d_in[0];
    const float* h0    = (const float*)d_in[1];
    const float* c0    = (const float*)d_in[2];
    const float* saWih = (const float*)d_in[3];
    const float* saWhh = (const float*)d_in[4];
    const float* sabih = (const float*)d_in[5];
    const float* sabhh = (const float*)d_in[6];
    const float* m0Wih = (const float*)d_in[7];
    const float* m0Whh = (const float*)d_in[8];
    const float* m0bih = (const float*)d_in[9];
    const float* m0bhh = (const float*)d_in[10];
    const float* mLWih = (const float*)d_in[11];
    const float* mLWhh = (const float*)d_in[12];
    const float* mLbih = (const float*)d_in[13];
    const float* mLbhh = (const float*)d_in[14];
    const float* sf1W  = (const float*)d_in[15];
    const float* sf1b  = (const float*)d_in[16];
    const float* sf2W  = (const float*)d_in[17];
    const float* sf2b  = (const float*)d_in[18];
    const float* fc1W  = (const float*)d_in[19];
    const float* fc1b  = (const float*)d_in[20];
    float* out = (float*)d_out;

    float *xw, *hlast, *t1, *e, *ab;
    unsigned* bar;
    __nv_bfloat16 *wh, *wl, *ah, *al, *hbf;
    cudaGetSymbolAddress((void**)&xw,    g_xw);
    cudaGetSymbolAddress((void**)&hbf,   g_hbf);
    cudaGetSymbolAddress((void**)&hlast, g_hlast);
    cudaGetSymbolAddress((void**)&t1,    g_t1);
    cudaGetSymbolAddress((void**)&e,     g_e);
    cudaGetSymbolAddress((void**)&ab,    g_ab);
    cudaGetSymbolAddress((void**)&bar,   g_bar);
    cudaGetSymbolAddress((void**)&wh,    g_wh);
    cudaGetSymbolAddress((void**)&wl,    g_wl);
    cudaGetSymbolAddress((void**)&ah,    g_ah);
    cudaGetSymbolAddress((void**)&al,    g_al);

    const int SMEM_LSTM = 230432;
    cudaFuncSetAttribute(lstm_persist, cudaFuncAttributeMaxDynamicSharedMemorySize, SMEM_LSTM);
    const int SMEM_MMA = 2 * BUFB;
    cudaFuncSetAttribute(gemm_mma, cudaFuncAttributeMaxDynamicSharedMemorySize, SMEM_MMA);

    const int M = T_ * B_;   // 8192

    auto proj = [&](long long woff, const float* bih, const float* bhh, int Kpad) {
        gemm_mma<<<dim3(G4 / 128, M / 128, 2), 256, SMEM_MMA>>>(
            ah, al, wh + woff, wl + woff, (long long)G4 * Kpad,
            bih, G4, bhh, G4, xw, (long long)M * G4, Kpad, G4);
    };
    auto recur = [&](const float* Whh, const float* h0s, const float* c0s,
                     __nv_bfloat16* yhp, __nv_bfloat16* ylp, int stage) {
        lstm_persist<<<128, 256, SMEM_LSTM>>>(xw, Whh, h0s, c0s, hbf, hlast,
                                              yhp, ylp, bar + stage * 256);
    };

    reset_bar<<<1, 256>>>(bar);

    // ---- stage 0: spatial-attention biLSTM ----
    conv_split<<<1024, 256>>>(saWih, 2 * G4, F_, 128, wh + OFF_SAW, wl + OFF_SAW);
    conv_split<<<1024, 256>>>(x, M, F_, 128, ah, al);
    proj(OFF_SAW, sabih, sabhh, 128);
    conv_split<<<1024, 256>>>(m0Wih, 2 * G4, F_, 128, wh + OFF_M0W, wl + OFF_M0W);
    recur(saWhh, h0, c0, nullptr, nullptr, 0);

    // ---- attention ----
    gemm_small<1, 32, 64, 2, 4><<<dim3(H_ / 64, (2 * B_ + 31) / 32), 256>>>(
        hlast, H_, sf1W, H_, sf1b, t1, H_, 2 * B_, H_, H_);
    gemm_small<2, 32, 64, 2, 4><<<dim3((F_ + 63) / 64, (2 * B_ + 31) / 32), 256>>>(
        t1, H_, sf2W, H_, sf2b, e, F_, 2 * B_, F_, H_);
    attn_alpha<<<B_, 128>>>(e, ab);
    scale_split<<<(M * 128 + 255) / 256, 256>>>(x, ab, ah, al);

    // ---- main layer 0 ----
    proj(OFF_M0W, m0bih, m0bhh, 128);
    conv_split<<<2048, 256>>>(mLWih, 2 * 2 * G4, H2, H2, wh + OFF_MLW, wl + OFF_MLW);
    recur(m0Whh, h0, c0, ah, al, 1);

    // ---- main layers 1,2 ----
    proj(OFF_MLW, mLbih, mLbhh, H2);
    recur(mLWhh, h0 + 2 * B_ * H_, c0 + 2 * B_ * H_, ah, al, 2);

    gemm_mma<<<dim3(G4 / 128, M / 128, 2), 256, SMEM_MMA>>>(
        ah, al, wh + OFF_MLW + 2ll * G4 * H2, wl + OFF_MLW + 2ll * G4 * H2,
        (long long)G4 * H2,
        mLbih + 2 * G4, G4, mLbhh + 2 * G4, G4, xw, (long long)M * G4, H2, G4);
    conv_split<<<1024, 256>>>(fc1W, H_, H2, H2, wh + OFF_FCW, wl + OFF_FCW);
    recur(mLWhh + 2ll * G4 * H_, h0 + 4 * B_ * H_, c0 + 4 * B_ * H_, ah, al, 3);

    // ---- final FC ----
    gemm_mma<<<dim3(H_ / 128, M / 128, 1), 256, SMEM_MMA>>>(
        ah, al, wh + OFF_FCW, wl + OFF_FCW, 0ll,
        fc1b, 0ll, nullptr, 0ll, out, 0ll, H2, H_);
}

// round 10
// speedup vs baseline: 3.2576x; 1.1247x over previous
#include <cuda_runtime.h>
#include <cuda_bf16.h>
#include <math.h>
#include <stdint.h>

#define T_  128
#define B_  64
#define F_  75
#define H_  512
#define G4  2048   // 4*H
#define H2  1024   // 2*H

// ---------------- static scratch ----------------
__device__ __align__(256) float g_xw   [2ll * T_ * B_ * G4];
// h between steps, stored directly in MMA *fragment* layout:
// region ((buf*2+d)*4+q) of 32KB: [hi 16KB | lo 16KB],
// slot byte = (((ks2*2+wm)*2+mf)*32 + lane)*16 + reg*4
__device__ __align__(256) __nv_bfloat16 g_hbf[2 * 2 * 2 * B_ * H_];
__device__ float g_hlast[2 * B_ * H_];
__device__ float g_t1   [2 * B_ * H_];
__device__ float g_e    [2 * B_ * F_];
__device__ float g_ab   [B_ * F_];
__device__ unsigned g_bar[1024];   // [stage][d][group][32-pad]

// bf16 split buffers (hi / lo)
#define WSZ 10485760ll
__device__ __align__(256) __nv_bfloat16 g_wh[WSZ];
__device__ __align__(256) __nv_bfloat16 g_wl[WSZ];
__device__ __align__(256) __nv_bfloat16 g_ah[8388608ll];
__device__ __align__(256) __nv_bfloat16 g_al[8388608ll];

#define OFF_SAW 0ll
#define OFF_M0W 524288ll
#define OFF_MLW 1048576ll
#define OFF_FCW 9437184ll

// ---------------- helpers ----------------
__device__ __forceinline__ void cp16(uint32_t dst, const void* src) {
    asm volatile("cp.async.cg.shared.global [%0], [%1], 16;" :: "r"(dst), "l"(src));
}
__device__ __forceinline__ uint32_t smem_u32(const void* p) {
    return (uint32_t)__cvta_generic_to_shared(p);
}
__device__ __forceinline__ void mma_bf16(float* d, const uint32_t* a, const uint32_t* b) {
    asm volatile(
        "mma.sync.aligned.m16n8k16.row.col.f32.bf16.bf16.f32 "
        "{%0,%1,%2,%3}, {%4,%5,%6,%7}, {%8,%9}, {%0,%1,%2,%3};"
        : "+f"(d[0]), "+f"(d[1]), "+f"(d[2]), "+f"(d[3])
        : "r"(a[0]), "r"(a[1]), "r"(a[2]), "r"(a[3]), "r"(b[0]), "r"(b[1]));
}
__device__ __forceinline__ uint32_t pkbf2(float a, float b) {
    __nv_bfloat16 ha = __float2bfloat16(a), hb = __float2bfloat16(b);
    uint16_t ua = *(uint16_t*)&ha, ub = *(uint16_t*)&hb;
    return (uint32_t)ua | ((uint32_t)ub << 16);
}
__device__ __forceinline__ float sigf(float x) {
    return __fdividef(1.f, 1.f + __expf(-x));
}
__device__ __forceinline__ float tanhfast(float x) {
    return __fmaf_rn(2.f, sigf(2.f * x), -1.f);
}
__device__ __forceinline__ uint4 ldcg128(const void* p) {
    uint4 v;
    asm volatile("ld.global.cg.v4.u32 {%0,%1,%2,%3}, [%4];"
                 : "=r"(v.x), "=r"(v.y), "=r"(v.z), "=r"(v.w) : "l"(p));
    return v;
}

// ---------------- fp32 -> bf16 hi/lo split conversion ----------------
__global__ void conv_split(const float* __restrict__ src, int rows, int K, int Kpad,
                           __nv_bfloat16* __restrict__ hi, __nv_bfloat16* __restrict__ lo)
{
    long long n = (long long)rows * Kpad;
    for (long long i = blockIdx.x * (long long)blockDim.x + threadIdx.x; i < n;
         i += (long long)gridDim.x * blockDim.x) {
        int kc = (int)(i % Kpad);
        long long r = i / Kpad;
        float v = (kc < K) ? src[r * K + kc] : 0.f;
        __nv_bfloat16 h = __float2bfloat16(v);
        hi[i] = h;
        lo[i] = __float2bfloat16(v - __bfloat162float(h));
    }
}

// ================= bf16 split tensor-core GEMM (mma.sync / HMMA) ==================
#define TILEB 10240
#define BUFB  40960

__global__ void __launch_bounds__(256, 1)
gemm_mma(const __nv_bfloat16* __restrict__ Ah, const __nv_bfloat16* __restrict__ Al,
         const __nv_bfloat16* __restrict__ Wh, const __nv_bfloat16* __restrict__ Wl,
         long long sW,
         const float* __restrict__ b1, long long sB1,
         const float* __restrict__ b2, long long sB2,
         float* __restrict__ C, long long sC,
         int Kpad, int N)
{
    extern __shared__ char smem[];
    const uint32_t sb = smem_u32(smem);

    const int z = blockIdx.z;
    Wh += (long long)z * sW;
    Wl += (long long)z * sW;
    C  += (long long)z * sC;
    if (b1) b1 += (long long)z * sB1;
    if (b2) b2 += (long long)z * sB2;

    const int tid  = threadIdx.x;
    const int lane = tid & 31;
    const int warp = tid >> 5;
    const int wm   = warp >> 2;
    const int wn   = warp & 3;
    const int m0   = blockIdx.y * 128;
    const int n0   = blockIdx.x * 128;
    const int q2   = (lane & 3) * 2;
    const int lr   = lane >> 2;

    float acc[4][4][4];
    #pragma unroll
    for (int mf = 0; mf < 4; mf++)
        #pragma unroll
        for (int nf = 0; nf < 4; nf++)
            #pragma unroll
            for (int r = 0; r < 4; r++) acc[mf][nf][r] = 0.f;

    const int sr = tid >> 1;
    const int skc = (tid & 1) * 2;

    auto stage = [&](int buf, int ch) {
        long long col = (long long)ch * 32;
        #pragma unroll
        for (int i = 0; i < 2; i++) {
            int kc = skc + i;
            uint32_t so = (uint32_t)(buf * BUFB + sr * 80 + kc * 16);
            long long gc = col + kc * 8;
            cp16(sb + so,             Ah + (long long)(m0 + sr) * Kpad + gc);
            cp16(sb + so + TILEB,     Al + (long long)(m0 + sr) * Kpad + gc);
            cp16(sb + so + 2 * TILEB, Wh + (long long)(n0 + sr) * Kpad + gc);
            cp16(sb + so + 3 * TILEB, Wl + (long long)(n0 + sr) * Kpad + gc);
        }
        asm volatile("cp.async.commit_group;");
    };

    const int nch = Kpad >> 5;
    stage(0, 0);

    for (int ch = 0; ch < nch; ch++) {
        if (ch + 1 < nch) {
            stage((ch + 1) & 1, ch + 1);
            asm volatile("cp.async.wait_group 1;");
        } else {
            asm volatile("cp.async.wait_group 0;");
        }
        __syncthreads();

        const char* base = smem + (ch & 1) * BUFB;
        #pragma unroll
        for (int ks = 0; ks < 2; ks++) {
            const int k0 = ks * 16;
            uint32_t ah[4][4], al[4][4], bh[4][2], bl[4][2];
            #pragma unroll
            for (int mf = 0; mf < 4; mf++) {
                int row = wm * 64 + mf * 16 + lr;
                const char* p0 = base + row * 80 + (k0 + q2) * 2;
                const char* p1 = base + (row + 8) * 80 + (k0 + q2) * 2;
                ah[mf][0] = *(const uint32_t*)(p0);
                ah[mf][1] = *(const uint32_t*)(p1);
                ah[mf][2] = *(const uint32_t*)(p0 + 16);
                ah[mf][3] = *(const uint32_t*)(p1 + 16);
                al[mf][0] = *(const uint32_t*)(p0 + TILEB);
                al[mf][1] = *(const uint32_t*)(p1 + TILEB);
                al[mf][2] = *(const uint32_t*)(p0 + 16 + TILEB);
                al[mf][3] = *(const uint32_t*)(p1 + 16 + TILEB);
            }
            #pragma unroll
            for (int nf = 0; nf < 4; nf++) {
                int col = wn * 32 + nf * 8 + lr;
                const char* p = base + 2 * TILEB + col * 80 + (k0 + q2) * 2;
                bh[nf][0] = *(const uint32_t*)(p);
                bh[nf][1] = *(const uint32_t*)(p + 16);
                bl[nf][0] = *(const uint32_t*)(p + TILEB);
                bl[nf][1] = *(const uint32_t*)(p + 16 + TILEB);
            }
            #pragma unroll
            for (int mf = 0; mf < 4; mf++)
                #pragma unroll
                for (int nf = 0; nf < 4; nf++)
                    mma_bf16(acc[mf][nf], ah[mf], bh[nf]);
            #pragma unroll
            for (int mf = 0; mf < 4; mf++)
                #pragma unroll
                for (int nf = 0; nf < 4; nf++)
                    mma_bf16(acc[mf][nf], ah[mf], bl[nf]);
            #pragma unroll
            for (int mf = 0; mf < 4; mf++)
                #pragma unroll
                for (int nf = 0; nf < 4; nf++)
                    mma_bf16(acc[mf][nf], al[mf], bh[nf]);
        }
        __syncthreads();
    }

    #pragma unroll
    for (int nf = 0; nf < 4; nf++) {
        int gn = n0 + wn * 32 + nf * 8 + q2;
        float bb0 = 0.f, bb1 = 0.f;
        if (b1) { bb0 += b1[gn]; bb1 += b1[gn + 1]; }
        if (b2) { bb0 += b2[gn]; bb1 += b2[gn + 1]; }
        #pragma unroll
        for (int mf = 0; mf < 4; mf++) {
            long long gm = m0 + wm * 64 + mf * 16 + lr;
            float2 v0 = make_float2(acc[mf][nf][0] + bb0, acc[mf][nf][1] + bb1);
            float2 v1 = make_float2(acc[mf][nf][2] + bb0, acc[mf][nf][3] + bb1);
            *(float2*)(C + gm * N + gn)       = v0;
            *(float2*)(C + (gm + 8) * N + gn) = v1;
        }
    }
}

// ================= small generic GEMM (attention FCs) ==============================
template<int ACT, int BM, int BN, int TM, int TN>
__global__ void gemm_small(const float* __restrict__ A, int lda,
                           const float* __restrict__ W, int ldw,
                           const float* __restrict__ b1,
                           float* __restrict__ C, int ldc,
                           int M, int N, int K)
{
    const int BK = 16;
    __shared__ float As[BK][BM + 2];
    __shared__ float Ws[BK][BN + 2];

    int m0 = blockIdx.y * BM;
    int n0 = blockIdx.x * BN;
    int tid = threadIdx.x;
    int tcol = tid % (BN / TN);
    int trow = tid / (BN / TN);
    int tm = trow * TM, tn = tcol * TN;

    float acc[TM][TN];
    #pragma unroll
    for (int i = 0; i < TM; i++)
        #pragma unroll
        for (int j = 0; j < TN; j++) acc[i][j] = 0.f;

    for (int kk = 0; kk < K; kk += BK) {
        for (int idx = tid; idx < BM * BK; idx += 256) {
            int m = idx / BK, k = idx % BK;
            int gm = m0 + m, gk = kk + k;
            As[k][m] = (gm < M && gk < K) ? A[(long long)gm * lda + gk] : 0.f;
        }
        for (int idx = tid; idx < BN * BK; idx += 256) {
            int n = idx / BK, k = idx % BK;
            int gn = n0 + n, gk = kk + k;
            Ws[k][n] = (gn < N && gk < K) ? W[(long long)gn * ldw + gk] : 0.f;
        }
        __syncthreads();
        #pragma unroll
        for (int k = 0; k < BK; k++) {
            float a[TM], wv[TN];
            #pragma unroll
            for (int i = 0; i < TM; i++) a[i] = As[k][tm + i];
            #pragma unroll
            for (int j = 0; j < TN; j++) wv[j] = Ws[k][tn + j];
            #pragma unroll
            for (int i = 0; i < TM; i++)
                #pragma unroll
                for (int j = 0; j < TN; j++)
                    acc[i][j] += a[i] * wv[j];
        }
        __syncthreads();
    }

    #pragma unroll
    for (int i = 0; i < TM; i++) {
        int gm = m0 + tm + i;
        if (gm >= M) continue;
        #pragma unroll
        for (int j = 0; j < TN; j++) {
            int gn = n0 + tn + j;
            if (gn >= N) continue;
            float v = acc[i][j] + b1[gn];
            if (ACT == 1) v = tanhf(v);
            else if (ACT == 2) v = expf(v);
            C[(long long)gm * ldc + gn] = v;
        }
    }
}

// ---------------- persistent bidirectional LSTM recurrence (tensor-core v5) -------
// Fragment-direct h exchange: producers scatter h straight into the consumers'
// MMA fragment layout in global; consumers acquire-poll their group counter and
// pull fragments with coalesced LDG.128 (.cg). No SMEM h staging, no bulk copy,
// no mbarriers, no coordinator warps.
__global__ void __launch_bounds__(256, 1)
lstm_persist(const float* __restrict__ xw,    // [2][T][B][G4]
             const float* __restrict__ Whh,   // [2][G4][H]
             const float* __restrict__ h0s,   // [2][B][H]
             const float* __restrict__ c0s,   // [2][B][H]
             __nv_bfloat16* __restrict__ hbf, // fragment regions (see decl)
             float* __restrict__ hlast,       // [2][B][H]
             __nv_bfloat16* __restrict__ yh,  // [T*B][2H] split hi or null
             __nv_bfloat16* __restrict__ yl,  // split lo or null
             unsigned* __restrict__ bar)      // [d][group][32-pad]
{
    extern __shared__ char smem[];
    char*  wsh = smem;                          // 32KB W hi (swizzled)
    char*  wsl = smem + 32768;                  // 32KB W lo
    float* gs  = (float*)(smem + 65536);        // [4][64][33] partials

    const int tid  = threadIdx.x;
    const int lane = tid & 31, w = tid >> 5;
    const int wm   = w & 1;                     // m-half
    const int kq   = w >> 1;                    // k-quarter
    const int r    = lane >> 2, qd = lane & 3;
    const int d    = blockIdx.x >> 6;
    const int s    = blockIdx.x & 63;
    const int j0   = s * 8;
    const int sq   = s >> 4;                    // producer group of this block

    const int pb = tid >> 2;
    const int jp = (tid & 3) << 1;

    unsigned* mybar = bar + d * 4 * 32;

    // ---- prologue: split Whh slice into SMEM ----
    const float* wp = Whh + (size_t)d * G4 * H_;
    for (int i = tid; i < 32 * 64; i += 256) {
        int cl = i >> 6, u = i & 63;
        int gate = cl >> 3, jj = cl & 7;
        const float* src = wp + (size_t)(gate * H_ + j0 + jj) * H_ + u * 8;
        uint32_t hi4[4], lo4[4];
        #pragma unroll
        for (int p = 0; p < 4; p++) {
            float a = src[2 * p], b = src[2 * p + 1];
            __nv_bfloat16 ha = __float2bfloat16(a), hb = __float2bfloat16(b);
            hi4[p] = pkbf2(a, b);
            lo4[p] = pkbf2(a - __bfloat162float(ha), b - __bfloat162float(hb));
        }
        int off = cl * 1024 + ((u ^ (cl & 7)) << 4);
        *(uint4*)(wsh + off) = make_uint4(hi4[0], hi4[1], hi4[2], hi4[3]);
        *(uint4*)(wsl + off) = make_uint4(lo4[0], lo4[1], lo4[2], lo4[3]);
    }

    // ---- fragment slot for this thread's h pair (bijection (b,k2) -> slot) ----
    // k2l within quarter, consumer coords (ks2, wm, mf, lane, reg)
    const int k2l   = (s & 15) * 4 + (jp >> 1);
    const int ks2p  = k2l >> 3;
    const int cc    = k2l & 7;
    const int klo   = cc & 3;
    const int khalf = cc >> 2;
    const int wmp   = pb >> 5;
    const int mfp   = (pb >> 4) & 1;
    const int apos  = (pb >> 3) & 1;
    const int rp    = pb & 7;
    const int slot  = ((((ks2p * 2 + wmp) * 2 + mfp) * 32) + (rp * 4 + klo)) * 16
                    + (apos + 2 * khalf) * 4;
    char* wfrag0 = (char*)hbf + (size_t)(d * 4 + sq) * 32768 + slot;         // buf 0
    char* wfrag1 = (char*)hbf + (size_t)((2 + d) * 4 + sq) * 32768 + slot;   // buf 1

    // h0 -> buf 0
    {
        float2 v = *(const float2*)(h0s + (size_t)d * B_ * H_ + pb * H_ + j0 + jp);
        __nv_bfloat16 h0a = __float2bfloat16(v.x), h0b = __float2bfloat16(v.y);
        *(uint32_t*)(wfrag0)         = pkbf2(v.x, v.y);
        *(uint32_t*)(wfrag0 + 16384) = pkbf2(v.x - __bfloat162float(h0a),
                                             v.y - __bfloat162float(h0b));
    }
    float2 creg = *(const float2*)(c0s + (size_t)d * B_ * H_ + pb * H_ + j0 + jp);

    __syncthreads();
    if (tid == 0)
        asm volatile("red.release.gpu.global.add.u32 [%0], 1;"
                     :: "l"(mybar + sq * 32) : "memory");

    // consumer read bases for my quarter
    const char* rq0 = (const char*)hbf + (size_t)(d * 4 + kq) * 32768;
    const char* rq1 = (const char*)hbf + (size_t)((2 + d) * 4 + kq) * 32768;
    unsigned* pollp = mybar + kq * 32;

    float acc[2][4][4];
    #pragma unroll
    for (int mf = 0; mf < 2; mf++)
        #pragma unroll
        for (int nf = 0; nf < 4; nf++)
            #pragma unroll
            for (int x = 0; x < 4; x++) acc[mf][nf][x] = 0.f;

    for (int t = 0; t < T_; t++) {
        const int td = d ? (T_ - 1 - t) : t;

        // xw gate values -> registers
        const float* xp = xw + ((size_t)(d * T_ + td) * B_ + pb) * G4 + j0 + jp;
        float2 xg0 = *(const float2*)(xp);
        float2 xg1 = *(const float2*)(xp + H_);
        float2 xg2 = *(const float2*)(xp + 2 * H_);
        float2 xg3 = *(const float2*)(xp + 3 * H_);

        // acquire-poll my quarter's producer counter (all lanes, one L2 req/warp)
        {
            unsigned tgt = 16u * (unsigned)(t + 1), v;
            do { asm volatile("ld.acquire.gpu.u32 %0, [%1];"
                              : "=r"(v) : "l"(pollp)); }
            while (v < tgt);
        }

        const char* aq = (t & 1) ? rq1 : rq0;

        // prefetch ks2=0 fragments
        uint4 AH[2], AL[2], AHn[2], ALn[2];
        #pragma unroll
        for (int mf = 0; mf < 2; mf++) {
            const char* p = aq + (size_t)((((0 * 2 + wm) * 2 + mf) * 32 + lane) * 16);
            AH[mf] = ldcg128(p);
            AL[mf] = ldcg128(p + 16384);
        }

        #pragma unroll
        for (int ks2 = 0; ks2 < 8; ks2++) {
            if (ks2 < 7) {
                #pragma unroll
                for (int mf = 0; mf < 2; mf++) {
                    const char* p = aq +
                        (size_t)(((((ks2 + 1) * 2 + wm) * 2 + mf) * 32 + lane) * 16);
                    AHn[mf] = ldcg128(p);
                    ALn[mf] = ldcg128(p + 16384);
                }
            }

            const int u0 = ks2 << 1;
            const int uG = (kq << 4) + u0;
            const int swW0 = ((uG ^ r) << 4) + qd * 4;
            const int swW1 = (((uG + 1) ^ r) << 4) + qd * 4;

            uint32_t bh[4][2], bl2[4][2];
            #pragma unroll
            for (int nf = 0; nf < 4; nf++) {
                int nr = nf * 8 + r;
                const char* pb2 = wsh + (nr << 10);
                const char* qb2 = wsl + (nr << 10);
                bh[nf][0]  = *(const uint32_t*)(pb2 + swW0);
                bh[nf][1]  = *(const uint32_t*)(pb2 + swW1);
                bl2[nf][0] = *(const uint32_t*)(qb2 + swW0);
                bl2[nf][1] = *(const uint32_t*)(qb2 + swW1);
            }
            #pragma unroll
            for (int mf = 0; mf < 2; mf++)
                #pragma unroll
                for (int nf = 0; nf < 4; nf++) {
                    mma_bf16(acc[mf][nf], (const uint32_t*)&AH[mf], bh[nf]);
                    mma_bf16(acc[mf][nf], (const uint32_t*)&AH[mf], bl2[nf]);
                    mma_bf16(acc[mf][nf], (const uint32_t*)&AL[mf], bh[nf]);
                }
            #pragma unroll
            for (int mf = 0; mf < 2; mf++) { AH[mf] = AHn[mf]; AL[mf] = ALn[mf]; }
        }

        // atomic-free partial store
        #pragma unroll
        for (int mf = 0; mf < 2; mf++) {
            int b = wm * 32 + mf * 16 + r;
            #pragma unroll
            for (int nf = 0; nf < 4; nf++) {
                int cl = nf * 8 + qd * 2;
                float* gp0 = gs + ((kq * 64 + b) * 33) + cl;
                float* gp1 = gs + ((kq * 64 + b + 8) * 33) + cl;
                gp0[0] = acc[mf][nf][0]; gp0[1] = acc[mf][nf][1];
                gp1[0] = acc[mf][nf][2]; gp1[1] = acc[mf][nf][3];
                acc[mf][nf][0] = acc[mf][nf][1] = acc[mf][nf][2] = acc[mf][nf][3] = 0.f;
            }
        }
        __syncthreads();

        // pointwise c/h update for the (pb, jp) pair
        float gi0 = xg0.x, gi1 = xg0.y;
        float gf0 = xg1.x, gf1 = xg1.y;
        float gg0 = xg2.x, gg1 = xg2.y;
        float go0 = xg3.x, go1 = xg3.y;
        #pragma unroll
        for (int kk2 = 0; kk2 < 4; kk2++) {
            const float* gp = gs + (kk2 * 64 + pb) * 33;
            gi0 += gp[jp];      gi1 += gp[jp + 1];
            gf0 += gp[8 + jp];  gf1 += gp[8 + jp + 1];
            gg0 += gp[16 + jp]; gg1 += gp[16 + jp + 1];
            go0 += gp[24 + jp]; go1 += gp[24 + jp + 1];
        }
        float cn0 = sigf(gf0) * creg.x + sigf(gi0) * tanhfast(gg0);
        float cn1 = sigf(gf1) * creg.y + sigf(gi1) * tanhfast(gg1);
        float hn0 = sigf(go0) * tanhfast(cn0);
        float hn1 = sigf(go1) * tanhfast(cn1);
        creg.x = cn0; creg.y = cn1;

        __nv_bfloat16 hb0 = __float2bfloat16(hn0), hb1 = __float2bfloat16(hn1);
        uint32_t hip = pkbf2(hn0, hn1);
        uint32_t lop = pkbf2(hn0 - __bfloat162float(hb0), hn1 - __bfloat162float(hb1));

        // write next-buffer fragments (t even -> buf1, t odd -> buf0)
        char* wf = (t & 1) ? wfrag0 : wfrag1;
        *(uint32_t*)(wf)         = hip;
        *(uint32_t*)(wf + 16384) = lop;
        if (yh) {
            size_t yi = (size_t)(td * B_ + pb) * H2 + d * H_ + j0 + jp;
            *(uint32_t*)(yh + yi) = hip;
            *(uint32_t*)(yl + yi) = lop;
        }
        if (t == T_ - 1)
            *(float2*)(hlast + (size_t)d * B_ * H_ + pb * H_ + j0 + jp) =
                make_float2(hn0, hn1);

        __syncthreads();
        if (t < T_ - 1 && tid == 0)
            asm volatile("red.release.gpu.global.add.u32 [%0], 1;"
                         :: "l"(mybar + sq * 32) : "memory");
    }
}

// ---------------- small kernels ----------------
__global__ void reset_bar(unsigned* __restrict__ bar)
{
    for (int i = threadIdx.x; i < 1024; i += 256) bar[i] = 0;
}

__global__ void attn_alpha(const float* __restrict__ e, float* __restrict__ alphab)
{
    int b = blockIdx.x;
    __shared__ float a[2 * F_];
    __shared__ float red[128];
    __shared__ float redc[128];
    int tid = threadIdx.x;

    for (int i = tid; i < 2 * F_; i += 128) {
        int d = i / F_, j = i % F_;
        a[i] = e[(d * B_ + b) * F_ + j];
    }
    __syncthreads();

    float s = 0.f;
    for (int i = tid; i < 2 * F_; i += 128) s += a[i];
    red[tid] = s; __syncthreads();
    for (int off = 64; off; off >>= 1) { if (tid < off) red[tid] += red[tid + off]; __syncthreads(); }
    float denom = red[0];
    __syncthreads();

    for (int i = tid; i < 2 * F_; i += 128) a[i] /= denom;
    __syncthreads();

    float cnt = 0.f, sel = 0.f;
    for (int i = tid; i < 2 * F_; i += 128) {
        float v = a[i];
        if (v >= 0.1f) { cnt += 1.f; sel += v; }
    }
    red[tid] = sel; redc[tid] = cnt; __syncthreads();
    for (int off = 64; off; off >>= 1) {
        if (tid < off) { red[tid] += red[tid + off]; redc[tid] += redc[tid + off]; }
        __syncthreads();
    }
    float selmean = red[0] / fmaxf(redc[0], 1.f);
    __syncthreads();

    for (int i = tid; i < 2 * F_; i += 128)
        if (a[i] >= 0.1f) a[i] = selmean;
    __syncthreads();

    for (int j = tid; j < F_; j += 128)
        alphab[b * F_ + j] = 0.5f * (a[j] + a[F_ + j]);
}

// fused: xw = x * alpha_b, padded to 128 cols, written as bf16 hi/lo split
__global__ void scale_split(const float* __restrict__ x, const float* __restrict__ ab,
                            __nv_bfloat16* __restrict__ hi, __nv_bfloat16* __restrict__ lo)
{
    int i = blockIdx.x * blockDim.x + threadIdx.x;
    if (i < T_ * B_ * 128) {
        int f = i & 127;
        int m = i >> 7;
        int b = m & (B_ - 1);
        float v = 0.f;
        if (f < F_) v = x[m * F_ + f] * ab[b * F_ + f];
        __nv_bfloat16 h = __float2bfloat16(v);
        hi[i] = h;
        lo[i] = __float2bfloat16(v - __bfloat162float(h));
    }
}

// ---------------- host driver ----------------
extern "C" void kernel_launch(void* const* d_in, const int* in_sizes, int n_in,
                              void* d_out, int out_size)
{
    const float* x     = (const float*)d_in[0];
    const float* h0    = (const float*)d_in[1];
    const float* c0    = (const float*)d_in[2];
    const float* saWih = (const float*)d_in[3];
    const float* saWhh = (const float*)d_in[4];
    const float* sabih = (const float*)d_in[5];
    const float* sabhh = (const float*)d_in[6];
    const float* m0Wih = (const float*)d_in[7];
    const float* m0Whh = (const float*)d_in[8];
    const float* m0bih = (const float*)d_in[9];
    const float* m0bhh = (const float*)d_in[10];
    const float* mLWih = (const float*)d_in[11];
    const float* mLWhh = (const float*)d_in[12];
    const float* mLbih = (const float*)d_in[13];
    const float* mLbhh = (const float*)d_in[14];
    const float* sf1W  = (const float*)d_in[15];
    const float* sf1b  = (const float*)d_in[16];
    const float* sf2W  = (const float*)d_in[17];
    const float* sf2b  = (const float*)d_in[18];
    const float* fc1W  = (const float*)d_in[19];
    const float* fc1b  = (const float*)d_in[20];
    float* out = (float*)d_out;

    float *xw, *hlast, *t1, *e, *ab;
    unsigned* bar;
    __nv_bfloat16 *wh, *wl, *ah, *al, *hbf;
    cudaGetSymbolAddress((void**)&xw,    g_xw);
    cudaGetSymbolAddress((void**)&hbf,   g_hbf);
    cudaGetSymbolAddress((void**)&hlast, g_hlast);
    cudaGetSymbolAddress((void**)&t1,    g_t1);
    cudaGetSymbolAddress((void**)&e,     g_e);
    cudaGetSymbolAddress((void**)&ab,    g_ab);
    cudaGetSymbolAddress((void**)&bar,   g_bar);
    cudaGetSymbolAddress((void**)&wh,    g_wh);
    cudaGetSymbolAddress((void**)&wl,    g_wl);
    cudaGetSymbolAddress((void**)&ah,    g_ah);
    cudaGetSymbolAddress((void**)&al,    g_al);

    const int SMEM_LSTM = 65536 + 4 * 64 * 33 * 4;   // 99328
    cudaFuncSetAttribute(lstm_persist, cudaFuncAttributeMaxDynamicSharedMemorySize, SMEM_LSTM);
    const int SMEM_MMA = 2 * BUFB;
    cudaFuncSetAttribute(gemm_mma, cudaFuncAttributeMaxDynamicSharedMemorySize, SMEM_MMA);

    const int M = T_ * B_;   // 8192

    auto proj = [&](long long woff, const float* bih, const float* bhh, int Kpad) {
        gemm_mma<<<dim3(G4 / 128, M / 128, 2), 256, SMEM_MMA>>>(
            ah, al, wh + woff, wl + woff, (long long)G4 * Kpad,
            bih, G4, bhh, G4, xw, (long long)M * G4, Kpad, G4);
    };
    auto recur = [&](const float* Whh, const float* h0s, const float* c0s,
                     __nv_bfloat16* yhp, __nv_bfloat16* ylp, int stage) {
        lstm_persist<<<128, 256, SMEM_LSTM>>>(xw, Whh, h0s, c0s, hbf, hlast,
                                              yhp, ylp, bar + stage * 256);
    };

    reset_bar<<<1, 256>>>(bar);

    // ---- stage 0: spatial-attention biLSTM ----
    conv_split<<<1024, 256>>>(saWih, 2 * G4, F_, 128, wh + OFF_SAW, wl + OFF_SAW);
    conv_split<<<1024, 256>>>(x, M, F_, 128, ah, al);
    proj(OFF_SAW, sabih, sabhh, 128);
    conv_split<<<1024, 256>>>(m0Wih, 2 * G4, F_, 128, wh + OFF_M0W, wl + OFF_M0W);
    recur(saWhh, h0, c0, nullptr, nullptr, 0);

    // ---- attention ----
    gemm_small<1, 32, 64, 2, 4><<<dim3(H_ / 64, (2 * B_ + 31) / 32), 256>>>(
        hlast, H_, sf1W, H_, sf1b, t1, H_, 2 * B_, H_, H_);
    gemm_small<2, 32, 64, 2, 4><<<dim3((F_ + 63) / 64, (2 * B_ + 31) / 32), 256>>>(
        t1, H_, sf2W, H_, sf2b, e, F_, 2 * B_, F_, H_);
    attn_alpha<<<B_, 128>>>(e, ab);
    scale_split<<<(M * 128 + 255) / 256, 256>>>(x, ab, ah, al);

    // ---- main layer 0 ----
    proj(OFF_M0W, m0bih, m0bhh, 128);
    conv_split<<<2048, 256>>>(mLWih, 2 * 2 * G4, H2, H2, wh + OFF_MLW, wl + OFF_MLW);
    recur(m0Whh, h0, c0, ah, al, 1);

    // ---- main layers 1,2 ----
    proj(OFF_MLW, mLbih, mLbhh, H2);
    recur(mLWhh, h0 + 2 * B_ * H_, c0 + 2 * B_ * H_, ah, al, 2);

    gemm_mma<<<dim3(G4 / 128, M / 128, 2), 256, SMEM_MMA>>>(
        ah, al, wh + OFF_MLW + 2ll * G4 * H2, wl + OFF_MLW + 2ll * G4 * H2,
        (long long)G4 * H2,
        mLbih + 2 * G4, G4, mLbhh + 2 * G4, G4, xw, (long long)M * G4, H2, G4);
    conv_split<<<1024, 256>>>(fc1W, H_, H2, H2, wh + OFF_FCW, wl + OFF_FCW);
    recur(mLWhh + 2ll * G4 * H_, h0 + 4 * B_ * H_, c0 + 4 * B_ * H_, ah, al, 3);

    // ---- final FC ----
    gemm_mma<<<dim3(H_ / 128, M / 128, 1), 256, SMEM_MMA>>>(
        ah, al, wh + OFF_FCW, wl + OFF_FCW, 0ll,
        fc1b, 0ll, nullptr, 0ll, out, 0ll, H2, H_);
}